// round 12
// baseline (speedup 1.0000x reference)
#include <cuda_runtime.h>
#include <cuda_bf16.h>
#include <math.h>

// Problem constants
#define Bz    128
#define Tt    1024
#define Dd    512
#define Hh    512
#define Oo    256
#define G4H   2048
#define FEAT  4608
#define NBLK  128
#define PTHR  512       // persist/producer block threads (16 warps)
#define PITCH 48        // tf32 xw0 fallback smem pitch (floats)

// persist smem layout (bytes)
#define WP_G0 520
#define WP_G1 1032
#define WP_K  584
#define SM_WG0 0
#define SM_WG1 33280
#define SM_WK  99328
#define SM_AST 175104
#define SM_STRIDE 18560       // 3 staging buffers (gates 17408B, KAN 18432B)
#define SM_KT  230784         // kt[12] + invd[30] floats
#define SMEM_TOTAL 232448
// producer smem layout (aliased)
#define PX_A  0
#define PX_W  133120
#define PX_MT 232000

// ---------------- device scratch ----------------
__device__ float g_xw0[(size_t)Tt * Bz * G4H];
__device__ __nv_bfloat16 g_wihb[(size_t)G4H * Dd];
__device__ float g_bg0[G4H];
__device__ float g_bg1[G4H];
__device__ __nv_bfloat16 g_hcat[Bz * 1024];
__device__ float g_sig[2][Bz * G4H];
__device__ __nv_bfloat16 g_feat[2][(size_t)Bz * FEAT];
__device__ float g_part[2][8][Bz * Hh];
__device__ float g_kt[12];
__device__ float g_invd[30];
__device__ unsigned g_bar;
__device__ unsigned g_gcnt[16];
__device__ unsigned g_pcnt[8];
__device__ unsigned g_xwflag[Tt];
__device__ unsigned g_mtnext;

// ---------------- grid barrier (128 persist blocks only) ----------------
__device__ __forceinline__ void gsync(unsigned target) {
    __syncthreads();
    if (threadIdx.x == 0) {
        asm volatile("red.release.gpu.global.add.u32 [%0], 1;" :: "l"(&g_bar) : "memory");
        unsigned v;
        do {
            asm volatile("ld.acquire.gpu.global.u32 %0, [%1];" : "=r"(v) : "l"(&g_bar) : "memory");
        } while (v < target);
    }
    __syncthreads();
}

// ---------------- bf16 mma primitives ----------------
__device__ __forceinline__ void ldm_x4(unsigned &r0, unsigned &r1, unsigned &r2, unsigned &r3, unsigned addr) {
    asm volatile("ldmatrix.sync.aligned.m8n8.x4.shared.b16 {%0,%1,%2,%3}, [%4];"
                 : "=r"(r0), "=r"(r1), "=r"(r2), "=r"(r3) : "r"(addr));
}
__device__ __forceinline__ void ldm_x2(unsigned &r0, unsigned &r1, unsigned addr) {
    asm volatile("ldmatrix.sync.aligned.m8n8.x2.shared.b16 {%0,%1}, [%2];"
                 : "=r"(r0), "=r"(r1) : "r"(addr));
}
__device__ __forceinline__ void mma16816(float c[4], unsigned a0, unsigned a1, unsigned a2, unsigned a3,
                                         unsigned b0, unsigned b1) {
    asm volatile("mma.sync.aligned.m16n8k16.row.col.f32.bf16.bf16.f32 "
                 "{%0,%1,%2,%3},{%4,%5,%6,%7},{%8,%9},{%0,%1,%2,%3};"
                 : "+f"(c[0]), "+f"(c[1]), "+f"(c[2]), "+f"(c[3])
                 : "r"(a0), "r"(a1), "r"(a2), "r"(a3), "r"(b0), "r"(b1));
}

// ---------------- merged gates mma: 16 warps 4m x 4n, KCH=128 ----------------
__device__ __forceinline__ void mma_gates(
    const __nv_bfloat16* __restrict__ Ag, int arow0,
    const __nv_bfloat16* sWg0, const __nv_bfloat16* sWg1,
    __nv_bfloat16* sA, float (&acc0)[4], float (&acc1)[4])
{
    constexpr int KCH = 128, AP = 136, NCH = 8;
    int tid = threadIdx.x, lane = tid & 31, warp = tid >> 5;
    int wm = (warp & 3) * 16, wn = (warp >> 2) * 8;
    unsigned sW0a = (unsigned)__cvta_generic_to_shared(sWg0);
    unsigned sW1a = (unsigned)__cvta_generic_to_shared(sWg1);
    unsigned sAa  = (unsigned)__cvta_generic_to_shared(sA);

    auto issue = [&](int cc) {
        const __nv_bfloat16* gb = Ag + (size_t)arow0 * 1024 + cc * KCH;
        unsigned sb = sAa + (unsigned)(cc % 3) * SM_STRIDE;
#pragma unroll
        for (int o = 0; o < 2; o++) {
            int idx = o * PTHR + tid;
            int r = idx >> 4, c = (idx & 15) * 8;
            unsigned sa = sb + (unsigned)(r * AP + c) * 2u;
            const void* ga = gb + (size_t)r * 1024 + c;
            asm volatile("cp.async.cg.shared.global [%0], [%1], 16;" :: "r"(sa), "l"(ga) : "memory");
        }
        asm volatile("cp.async.commit_group;" ::: "memory");
    };
    issue(0); issue(1);

    int a_r = (lane & 7) + ((lane >> 3) & 1) * 8;
    int a_k = ((lane >> 4) & 1) * 8;
    int l16 = lane & 15;
    int b_r = l16 & 7;
    int b_k = ((l16 >> 3) & 1) * 8;
    unsigned b0base = sW0a + (unsigned)((wn + b_r) * WP_G0 + b_k) * 2u;
    unsigned b1base = sW1a + (unsigned)((wn + b_r) * WP_G1 + b_k) * 2u;

    for (int cc = 0; cc < NCH; cc++) {
        asm volatile("cp.async.wait_group 1;" ::: "memory");
        __syncthreads();
        if (cc + 2 < NCH) issue(cc + 2);
        unsigned ab = sAa + (unsigned)(cc % 3) * SM_STRIDE + (unsigned)((wm + a_r) * AP + a_k) * 2u;
#pragma unroll
        for (int ks = 0; ks < 8; ks++) {
            unsigned a0r, a1r, a2r, a3r;
            ldm_x4(a0r, a1r, a2r, a3r, ab + ks * 32);
            unsigned b0, b1;
            ldm_x2(b0, b1, b1base + (unsigned)(cc * KCH + ks * 16) * 2u);
            mma16816(acc1, a0r, a1r, a2r, a3r, b0, b1);
            if (cc < 4) {
                unsigned c0, c1;
                ldm_x2(c0, c1, b0base + (unsigned)(cc * KCH + ks * 16) * 2u);
                mma16816(acc0, a0r, a1r, a2r, a3r, c0, c1);
            }
        }
    }
}

// ---------------- KAN mma: 16 warps 4m x 4n (warp 32m x 16n), KCH=64 ----------
__device__ __forceinline__ void mma_kan(
    const __nv_bfloat16* __restrict__ Ag, int kbeg,
    const __nv_bfloat16* sW, __nv_bfloat16* sA, float cacc[2][2][4])
{
    constexpr int KCH = 64, AP = 72, NCHN = 9;
    int tid = threadIdx.x, lane = tid & 31, warp = tid >> 5;
    int wm = (warp & 3) * 32, wn = (warp >> 2) * 16;
    unsigned sWa = (unsigned)__cvta_generic_to_shared(sW);
    unsigned sAa = (unsigned)__cvta_generic_to_shared(sA);

    auto issue = [&](int cc) {
        const __nv_bfloat16* gb = Ag + kbeg + cc * KCH;
        unsigned sb = sAa + (unsigned)(cc % 3) * SM_STRIDE;
#pragma unroll
        for (int o = 0; o < 2; o++) {
            int idx = o * PTHR + tid;
            int r = idx >> 3, c = (idx & 7) * 8;
            unsigned sa = sb + (unsigned)(r * AP + c) * 2u;
            const void* ga = gb + (size_t)r * FEAT + c;
            asm volatile("cp.async.cg.shared.global [%0], [%1], 16;" :: "r"(sa), "l"(ga) : "memory");
        }
        asm volatile("cp.async.commit_group;" ::: "memory");
    };
    issue(0); issue(1);

    int a_r = (lane & 7) + ((lane >> 3) & 1) * 8;
    int a_k = ((lane >> 4) & 1) * 8;
    int b_r = (lane & 7) + ((lane >> 4) & 1) * 8;
    int b_k = ((lane >> 3) & 1) * 8;
    unsigned bbase = sWa + (unsigned)((wn + b_r) * WP_K + b_k) * 2u;

    for (int cc = 0; cc < NCHN; cc++) {
        asm volatile("cp.async.wait_group 1;" ::: "memory");
        __syncthreads();
        if (cc + 2 < NCHN) issue(cc + 2);

        unsigned sb = sAa + (unsigned)(cc % 3) * SM_STRIDE;
        unsigned ab0 = sb + (unsigned)((wm + a_r) * AP + a_k) * 2u;
        unsigned ab1 = sb + (unsigned)((wm + 16 + a_r) * AP + a_k) * 2u;
#pragma unroll
        for (int ks = 0; ks < 4; ks++) {
            unsigned p0, p1, p2, p3, q0, q1, q2, q3;
            ldm_x4(p0, p1, p2, p3, ab0 + ks * 32);
            ldm_x4(q0, q1, q2, q3, ab1 + ks * 32);
            unsigned b0, b1, b2, b3;
            ldm_x4(b0, b1, b2, b3, bbase + (unsigned)(cc * KCH + ks * 16) * 2u);
            mma16816(cacc[0][0], p0, p1, p2, p3, b0, b1);
            mma16816(cacc[0][1], p0, p1, p2, p3, b2, b3);
            mma16816(cacc[1][0], q0, q1, q2, q3, b0, b1);
            mma16816(cacc[1][1], q0, q1, q2, q3, b2, b3);
        }
    }
}

// ---------------- init ----------------
__global__ void init_kernel(const float* __restrict__ wih,
                            const float* __restrict__ bih, const float* __restrict__ bhh,
                            const float* __restrict__ grid, int preset_flags)
{
    size_t stride = (size_t)gridDim.x * blockDim.x;
    size_t t0 = (size_t)blockIdx.x * blockDim.x + threadIdx.x;
    for (size_t i = t0; i < (size_t)G4H * Dd; i += stride)
        g_wihb[i] = __float2bfloat16(wih[i]);
    for (size_t i = t0; i < G4H; i += stride) {
        g_bg0[i] = bih[i] + bhh[i];
        g_bg1[i] = bih[G4H + i] + bhh[G4H + i];
    }
    for (size_t i = t0; i < (size_t)Bz * 1024; i += stride) g_hcat[i] = __float2bfloat16(0.f);
    for (size_t i = t0; i < 12; i += stride) g_kt[i] = grid[i];
    for (size_t i = t0; i < 30; i += stride) {
        int j = (int)i; int k, jj;
        if (j < 11)      { k = 1; jj = j; }
        else if (j < 21) { k = 2; jj = j - 11; }
        else             { k = 3; jj = j - 21; }
        g_invd[i] = 1.0f / (grid[jj + k] - grid[jj]);
    }
    for (size_t i = t0; i < Tt; i += stride) g_xwflag[i] = (unsigned)preset_flags;
    if (t0 < 16) g_gcnt[t0] = 0u;
    if (t0 < 8) g_pcnt[t0] = 0u;
    if (t0 == 0) { g_bar = 0u; g_mtnext = 0u; }
}

// ---------------- tf32 xw0 fallback (256 threads; used only if few SMs) -------
__device__ __forceinline__ unsigned f2tf(float x) {
    unsigned u; asm("cvt.rna.tf32.f32 %0, %1;" : "=r"(u) : "f"(x)); return u;
}
__device__ __forceinline__ void mma8(float c[4], unsigned a0, unsigned a1, unsigned a2, unsigned a3,
                                     unsigned b0, unsigned b1) {
    asm volatile("mma.sync.aligned.m16n8k8.row.col.f32.tf32.tf32.f32 "
                 "{%0,%1,%2,%3},{%4,%5,%6,%7},{%8,%9},{%0,%1,%2,%3};"
                 : "+f"(c[0]), "+f"(c[1]), "+f"(c[2]), "+f"(c[3])
                 : "r"(a0), "r"(a1), "r"(a2), "r"(a3), "r"(b0), "r"(b1));
}
__global__ void __launch_bounds__(256) xw0_mma(const float* __restrict__ x,
                                               const float* __restrict__ wih,
                                               const float* __restrict__ bih,
                                               const float* __restrict__ bhh)
{
    __shared__ __align__(16) float sA[128 * PITCH];
    __shared__ __align__(16) float sB[64 * PITCH];
    int nt = blockIdx.x, mt = blockIdx.y;
    int tid = threadIdx.x, lane = tid & 31, warp = tid >> 5;
    int wm = (warp & 3) * 32, wn = (warp >> 2) * 32;
    int qr = lane >> 2, qc = lane & 3;
    float cacc[2][4][4] = {};
    const float* A = x + (size_t)mt * Dd;
    const float* W = wih + (size_t)nt * 64 * Dd;
    float4 ra[4], rb[2];
    {
#pragma unroll
        for (int j = 0; j < 4; j++) { int idx = j * 256 + tid;
            ra[j] = *(const float4*)(A + (size_t)(idx >> 3) * ((size_t)Tt * Dd) + ((idx & 7) << 2)); }
#pragma unroll
        for (int j = 0; j < 2; j++) { int idx = j * 256 + tid;
            rb[j] = *(const float4*)(W + (size_t)(idx >> 3) * Dd + ((idx & 7) << 2)); }
    }
    for (int cc = 0; cc < Dd / 32; cc++) {
        __syncthreads();
#pragma unroll
        for (int j = 0; j < 4; j++) {
            int idx = j * 256 + tid; int row = idx >> 3; int c0 = (idx & 7) << 2;
            int base = row * PITCH + ((c0 >> 4) << 4) + ((c0 & 15) >> 2);
            sA[base + 0]  = __uint_as_float(f2tf(ra[j].x));
            sA[base + 4]  = __uint_as_float(f2tf(ra[j].y));
            sA[base + 8]  = __uint_as_float(f2tf(ra[j].z));
            sA[base + 12] = __uint_as_float(f2tf(ra[j].w));
        }
#pragma unroll
        for (int j = 0; j < 2; j++) {
            int idx = j * 256 + tid; int row = idx >> 3; int c0 = (idx & 7) << 2;
            int base = row * PITCH + ((c0 >> 4) << 4) + ((c0 & 15) >> 2);
            sB[base + 0]  = __uint_as_float(f2tf(rb[j].x));
            sB[base + 4]  = __uint_as_float(f2tf(rb[j].y));
            sB[base + 8]  = __uint_as_float(f2tf(rb[j].z));
            sB[base + 12] = __uint_as_float(f2tf(rb[j].w));
        }
        __syncthreads();
        if (cc + 1 < Dd / 32) {
            int kb = (cc + 1) * 32;
#pragma unroll
            for (int j = 0; j < 4; j++) { int idx = j * 256 + tid;
                ra[j] = *(const float4*)(A + (size_t)(idx >> 3) * ((size_t)Tt * Dd) + kb + ((idx & 7) << 2)); }
#pragma unroll
            for (int j = 0; j < 2; j++) { int idx = j * 256 + tid;
                rb[j] = *(const float4*)(W + (size_t)(idx >> 3) * Dd + kb + ((idx & 7) << 2)); }
        }
#pragma unroll
        for (int h = 0; h < 2; h++) {
            unsigned bf[4][4];
#pragma unroll
            for (int f = 0; f < 4; f++) {
                float4 v = *(const float4*)(sB + (wn + f * 8 + qr) * PITCH + h * 16 + qc * 4);
                bf[f][0] = __float_as_uint(v.x); bf[f][1] = __float_as_uint(v.y);
                bf[f][2] = __float_as_uint(v.z); bf[f][3] = __float_as_uint(v.w);
            }
#pragma unroll
            for (int mi = 0; mi < 2; mi++) {
                float4 lo = *(const float4*)(sA + (wm + mi * 16 + qr) * PITCH + h * 16 + qc * 4);
                float4 hi = *(const float4*)(sA + (wm + mi * 16 + 8 + qr) * PITCH + h * 16 + qc * 4);
#pragma unroll
                for (int f = 0; f < 4; f++) {
                    mma8(cacc[mi][f], __float_as_uint(lo.x), __float_as_uint(hi.x),
                         __float_as_uint(lo.y), __float_as_uint(hi.y), bf[f][0], bf[f][1]);
                    mma8(cacc[mi][f], __float_as_uint(lo.z), __float_as_uint(hi.z),
                         __float_as_uint(lo.w), __float_as_uint(hi.w), bf[f][2], bf[f][3]);
                }
            }
        }
    }
    size_t rowbase = (size_t)mt * 128;
#pragma unroll
    for (int mi = 0; mi < 2; mi++)
#pragma unroll
        for (int f = 0; f < 4; f++) {
            int r0 = wm + mi * 16 + qr;
            int cb = nt * 64 + wn + f * 8 + qc * 2;
            float b0 = __ldg(&bih[cb]) + __ldg(&bhh[cb]);
            float b1 = __ldg(&bih[cb + 1]) + __ldg(&bhh[cb + 1]);
            *(float2*)(g_xw0 + (rowbase + r0) * G4H + cb) =
                make_float2(cacc[mi][f][0] + b0, cacc[mi][f][1] + b1);
            *(float2*)(g_xw0 + (rowbase + r0 + 8) * G4H + cb) =
                make_float2(cacc[mi][f][2] + b0, cacc[mi][f][3] + b1);
        }
}

// ---------------- mega kernel: 128 persist blocks + producer blocks ----------------
__global__ void __launch_bounds__(PTHR, 1) persist_kernel(
    const float* __restrict__ x,
    const float* __restrict__ wih, const float* __restrict__ whh,
    const float* __restrict__ kbase, const float* __restrict__ kspl,
    const float* __restrict__ kscl, const float* __restrict__ fc_w,
    const float* __restrict__ fc_b, float* __restrict__ out)
{
    extern __shared__ __align__(16) char smem_raw[];
    int bid = blockIdx.x, tid = threadIdx.x;
    int lane = tid & 31, warp = tid >> 5;
    int qr = lane >> 2, qc = lane & 3;

    // =================== xw0 producer blocks (bid >= 128) ===================
    if (bid >= NBLK) {
        __nv_bfloat16* sA = (__nv_bfloat16*)(smem_raw + PX_A);
        unsigned sAa = (unsigned)__cvta_generic_to_shared(smem_raw + PX_A);
        unsigned sWa = (unsigned)__cvta_generic_to_shared(smem_raw + PX_W);
        unsigned* s_mt = (unsigned*)(smem_raw + PX_MT);
        int a_r = (lane & 7) + ((lane >> 3) & 1) * 8;
        int a_k = ((lane >> 4) & 1) * 8;
        int b_r = (lane & 7) + ((lane >> 4) & 1) * 8;
        int b_k = ((lane >> 3) & 1) * 8;
        int wm = (warp & 3) * 32, wn = ((warp >> 2) & 1) * 16;   // warps 0-7 tile

        auto stageW = [&](int sub, int buf) {
            const __nv_bfloat16* gb = g_wihb + (size_t)sub * 32 * 512;
            unsigned dstb = sWa + (unsigned)buf * 33280u;
#pragma unroll
            for (int o = 0; o < 4; o++) {
                int idx = o * PTHR + tid;
                int r = idx >> 6, c = (idx & 63) * 8;
                asm volatile("cp.async.cg.shared.global [%0], [%1], 16;"
                             :: "r"(dstb + (unsigned)(r * 520 + c) * 2u),
                                "l"(gb + r * 512 + c) : "memory");
            }
            asm volatile("cp.async.commit_group;" ::: "memory");
        };

        for (;;) {
            __syncthreads();
            if (tid == 0) *s_mt = atomicAdd(&g_mtnext, 1u);
            __syncthreads();
            unsigned mt = *s_mt;
            if (mt >= Tt) break;
            for (int i = tid; i < 128 * 128; i += PTHR) {
                int r = i >> 7, c4 = (i & 127) << 2;
                float4 v = *(const float4*)(x + ((size_t)r * Tt + mt) * Dd + c4);
                __nv_bfloat162 p0 = __float22bfloat162_rn(make_float2(v.x, v.y));
                __nv_bfloat162 p1 = __float22bfloat162_rn(make_float2(v.z, v.w));
                *(__nv_bfloat162*)&sA[r * 520 + c4] = p0;
                *(__nv_bfloat162*)&sA[r * 520 + c4 + 2] = p1;
            }
            __syncthreads();
            stageW(0, 0);
            for (int sub = 0; sub < 64; sub++) {
                if (sub + 1 < 64) stageW(sub + 1, (sub + 1) & 1);
                else asm volatile("cp.async.commit_group;" ::: "memory");
                asm volatile("cp.async.wait_group 1;" ::: "memory");
                __syncthreads();
                if (warp < 8) {
                    unsigned bb = sWa + (unsigned)((sub & 1) * 33280) +
                                  (unsigned)((wn + b_r) * 520 + b_k) * 2u;
                    float cacc[2][2][4] = {};
#pragma unroll
                    for (int ks = 0; ks < 32; ks++) {
                        unsigned b0, b1, b2, b3;
                        ldm_x4(b0, b1, b2, b3, bb + ks * 32);
#pragma unroll
                        for (int mi = 0; mi < 2; mi++) {
                            unsigned a0, a1, a2, a3;
                            ldm_x4(a0, a1, a2, a3,
                                   sAa + (unsigned)((wm + mi * 16 + a_r) * 520 + ks * 16 + a_k) * 2u);
                            mma16816(cacc[mi][0], a0, a1, a2, a3, b0, b1);
                            mma16816(cacc[mi][1], a0, a1, a2, a3, b2, b3);
                        }
                    }
                    int n0 = sub * 32;
#pragma unroll
                    for (int mi = 0; mi < 2; mi++)
#pragma unroll
                        for (int nf = 0; nf < 2; nf++) {
                            int row = wm + mi * 16 + qr;
                            int col = n0 + wn + nf * 8 + qc * 2;
                            float2 bv = *(const float2*)&g_bg0[col];
                            *(float2*)&g_xw0[((size_t)mt * Bz + row) * G4H + col] =
                                make_float2(cacc[mi][nf][0] + bv.x, cacc[mi][nf][1] + bv.y);
                            *(float2*)&g_xw0[((size_t)mt * Bz + row + 8) * G4H + col] =
                                make_float2(cacc[mi][nf][2] + bv.x, cacc[mi][nf][3] + bv.y);
                        }
                }
                __syncthreads();
            }
            if (tid == 0)
                asm volatile("st.release.gpu.global.u32 [%0], %1;"
                             :: "l"(&g_xwflag[mt]), "r"(1u) : "memory");
        }
        return;
    }

    // =================== persist blocks (bid < 128) ===================
    __nv_bfloat16* sWg0 = (__nv_bfloat16*)(smem_raw + SM_WG0);
    __nv_bfloat16* sWg1 = (__nv_bfloat16*)(smem_raw + SM_WG1);
    __nv_bfloat16* sWk  = (__nv_bfloat16*)(smem_raw + SM_WK);
    __nv_bfloat16* sAst = (__nv_bfloat16*)(smem_raw + SM_AST);
    float* skt   = (float*)(smem_raw + SM_KT);
    float* sinvd = (float*)(smem_raw + SM_KT + 48);

    int g_nt = bid >> 1, g_mh = bid & 1;
    int lyr  = bid >> 6;
    int kb2  = bid & 63;
    int k_nt = kb2 >> 3, k_ks = kb2 & 7;

    for (int i = tid; i < 32 * 512; i += PTHR) {
        int r = i >> 9, c = i & 511;
        int ng = (r >> 3) * 512 + g_nt * 8 + (r & 7);
        sWg0[r * WP_G0 + c] = __float2bfloat16(whh[(size_t)ng * 512 + c]);
    }
    for (int i = tid; i < 32 * 1024; i += PTHR) {
        int r = i >> 10, c = i & 1023;
        int ng = (r >> 3) * 512 + g_nt * 8 + (r & 7);
        float v = (c < 512) ? wih[(size_t)G4H * Dd + (size_t)ng * 512 + c]
                            : whh[(size_t)G4H * Hh + (size_t)ng * 512 + (c - 512)];
        sWg1[r * WP_G1 + c] = __float2bfloat16(v);
    }
    for (int i = tid; i < 64 * 576; i += PTHR) {
        int r = i / 576, kk0 = i % 576;
        int row = lyr * 512 + k_nt * 64 + r;
        float v;
        if (kk0 < 64) {
            int ii2 = k_ks * 64 + kk0;
            v = kbase[(size_t)row * 512 + ii2];
        } else {
            int q = kk0 - 64;
            int ii2 = k_ks * 64 + (q >> 3);
            v = kspl[((size_t)row * 512 + ii2) * 8 + (q & 7)] * kscl[(size_t)row * 512 + ii2];
        }
        sWk[r * WP_K + kk0] = __float2bfloat16(v);
    }
    if (tid < 12) skt[tid] = g_kt[tid];
    if (tid < 30) sinvd[tid] = g_invd[tid];
    __syncthreads();

    // gates epilogue coordinates: each warp owns one class (warp>>2)
    int eb0 = g_mh * 64 + (warp & 3) * 16 + qr;
    int cls = warp >> 2;
    int encl = cls * 512 + g_nt * 8 + qc * 2;
    bool isg = (cls == 2);
    float2 pb = *(const float2*)&g_bg1[encl];

    int upd_row = k_ks * 16 + (tid >> 5);
    int upd_col = k_nt * 64 + ((tid & 31) << 1);
    float2 creg[2] = {make_float2(0.f, 0.f), make_float2(0.f, 0.f)};
    int gidx = lyr * 8 + k_nt;
    int my_pcnt = g_nt >> 3;

    auto gate_epilogue = [&](int l, const float2 (&pre)[2], const float (&cc4)[4]) {
#pragma unroll
        for (int r = 0; r < 2; r++) {
            int b = eb0 + r * 8;
            float v0 = cc4[r * 2 + 0] + pre[r].x;
            float v1 = cc4[r * 2 + 1] + pre[r].y;
            if (!isg) {
                *(float2*)&g_sig[l][b * G4H + encl] = make_float2(
                    1.f / (1.f + __expf(-v0)), 1.f / (1.f + __expf(-v1)));
            } else {
#pragma unroll
                for (int e = 0; e < 2; e++) {
                    float v = e ? v1 : v0;
                    int ii = encl + e - 1024;
                    int ch = ii >> 6, w = ii & 63;
                    size_t fbase = (size_t)b * FEAT + ch * 576;
                    g_feat[l][fbase + w] = __float2bfloat16(v / (1.f + __expf(-v)));
                    float bas[11];
#pragma unroll
                    for (int q = 0; q < 11; q++)
                        bas[q] = (v >= skt[q] && v < skt[q + 1]) ? 1.f : 0.f;
#pragma unroll
                    for (int k = 1; k <= 3; k++) {
                        int off = (k == 1) ? 0 : ((k == 2) ? 11 : 21);
#pragma unroll
                        for (int q = 0; q + k < 11; q++) {
                            float lf = (v - skt[q]) * sinvd[off + q];
                            float rf = (skt[q + k + 1] - v) * sinvd[off + q + 1];
                            bas[q] = lf * bas[q] + rf * bas[q + 1];
                        }
                    }
                    __nv_bfloat162 p0 = __float22bfloat162_rn(make_float2(bas[0], bas[1]));
                    __nv_bfloat162 p1 = __float22bfloat162_rn(make_float2(bas[2], bas[3]));
                    __nv_bfloat162 p2 = __float22bfloat162_rn(make_float2(bas[4], bas[5]));
                    __nv_bfloat162 p3 = __float22bfloat162_rn(make_float2(bas[6], bas[7]));
                    uint4 u;
                    u.x = *(unsigned*)&p0; u.y = *(unsigned*)&p1;
                    u.z = *(unsigned*)&p2; u.w = *(unsigned*)&p3;
                    *(uint4*)&g_feat[l][fbase + 64 + w * 8] = u;
                }
            }
        }
    };

    unsigned gs = 0, ainst = 0;

    auto produce = [&]() {
        __syncthreads();
        if (tid == 0)
            asm volatile("red.release.gpu.global.add.u32 [%0], 1;"
                         :: "l"(&g_pcnt[my_pcnt]) : "memory");
        ainst++;
    };

    auto kan_step = [&](void) {
        if (tid == 0) {
            unsigned tgt = 16u * ainst, v;
            do {
                asm volatile("ld.acquire.gpu.global.u32 %0, [%1];"
                             : "=r"(v) : "l"(&g_pcnt[k_ks]) : "memory");
            } while (v < tgt);
            do {
                asm volatile("ld.acquire.gpu.global.u32 %0, [%1];"
                             : "=r"(v) : "l"(&g_pcnt[k_nt]) : "memory");
            } while (v < tgt);
        }
        __syncthreads();

        float cacc[2][2][4] = {};
        mma_kan(g_feat[lyr], k_ks * 576, sWk, sAst, cacc);
        int wm = (warp & 3) * 32, wn = (warp >> 2) * 16;
#pragma unroll
        for (int mi = 0; mi < 2; mi++)
#pragma unroll
            for (int f = 0; f < 2; f++) {
                int r0 = wm + mi * 16 + qr;
                int cb = k_nt * 64 + wn + f * 8 + qc * 2;
                *(float2*)&g_part[lyr][k_ks][r0 * Hh + cb] =
                    make_float2(cacc[mi][f][0], cacc[mi][f][1]);
                *(float2*)&g_part[lyr][k_ks][(r0 + 8) * Hh + cb] =
                    make_float2(cacc[mi][f][2], cacc[mi][f][3]);
            }

        float2 ig, fg, og;
        {
            int b = upd_row, o = upd_col;
            ig = __ldcg((const float2*)&g_sig[lyr][b * G4H + o]);
            fg = __ldcg((const float2*)&g_sig[lyr][b * G4H + 512 + o]);
            og = __ldcg((const float2*)&g_sig[lyr][b * G4H + 1536 + o]);
        }

        ++gs;
        __syncthreads();
        if (tid == 0) {
            asm volatile("red.release.gpu.global.add.u32 [%0], 1;"
                         :: "l"(&g_gcnt[gidx]) : "memory");
            unsigned v, tgt = gs * 8;
            do {
                asm volatile("ld.acquire.gpu.global.u32 %0, [%1];"
                             : "=r"(v) : "l"(&g_gcnt[gidx]) : "memory");
            } while (v < tgt);
        }
        __syncthreads();

        {
            int b = upd_row, o = upd_col;
            float2 v = make_float2(0.f, 0.f);
#pragma unroll
            for (int s = 0; s < 8; s++) {
                float2 p = __ldcg((const float2*)&g_part[lyr][s][b * Hh + o]);
                v.x += p.x; v.y += p.y;
            }
            float c0 = fg.x * creg[0].x + ig.x * v.x;
            float c1 = fg.y * creg[0].y + ig.y * v.y;
            creg[0] = make_float2(c0, c1);
            __nv_bfloat162 h2 = __float22bfloat162_rn(
                make_float2(og.x * tanhf(c0), og.y * tanhf(c1)));
            *(unsigned*)&g_hcat[b * 1024 + lyr * 512 + o] = *(unsigned*)&h2;
        }
    };

    auto ld_pre0 = [&](int t, float2 (&pre)[2]) {
        unsigned fv;
        do {
            asm volatile("ld.acquire.gpu.global.u32 %0, [%1];"
                         : "=r"(fv) : "l"(&g_xwflag[t]) : "memory");
        } while (!fv);
#pragma unroll
        for (int r = 0; r < 2; r++)
            pre[r] = __ldcs((const float2*)&g_xw0[
                ((size_t)t * Bz + eb0 + r * 8) * G4H + encl]);
    };

    unsigned nb = 0;

    // ---- prologue: L0 step 0 (h = 0 -> gates = xw0[0], no mma) ----
    {
        float2 pre[2];
        ld_pre0(0, pre);
        float zero4[4] = {};
        gate_epilogue(0, pre, zero4);
    }
    produce();
    if (lyr == 0) kan_step();
    gsync(++nb * NBLK);

    // ---- main loop ----
    for (int i = 0; i < Tt; i++) {
        bool doL0 = (i < Tt - 1);
        {
            float2 pre0[2];
            if (doL0) ld_pre0(i + 1, pre0);
            float a0[4] = {}, a1[4] = {};
            mma_gates(g_hcat, g_mh * 64, sWg0, sWg1, sAst, a0, a1);
            if (doL0) gate_epilogue(0, pre0, a0);
            float2 pre1[2] = {pb, pb};
            gate_epilogue(1, pre1, a1);
        }
        produce();

        if (lyr == 1 || doL0) kan_step();
        gsync(++nb * NBLK);
    }

    // ---- final FC: out = h1 @ fc_w^T + fc_b ----
    {
        int idx = bid * PTHR + tid;
        if (idx < Bz * Oo) {
            int o = idx >> 7, b = idx & 127;
            float s = fc_b[o];
            const __nv_bfloat16* hp = &g_hcat[b * 1024 + 512];
            const float* wp = &fc_w[(size_t)o * Hh];
#pragma unroll 8
            for (int k = 0; k < Hh; k++) s += __bfloat162float(__ldcg(&hp[k])) * wp[k];
            out[b * Oo + o] = s;
        }
    }
}

// ---------------- launch ----------------
extern "C" void kernel_launch(void* const* d_in, const int* in_sizes, int n_in,
                              void* d_out, int out_size)
{
    const float* x     = (const float*)d_in[0];
    const float* wih   = (const float*)d_in[1];
    const float* whh   = (const float*)d_in[2];
    const float* bih   = (const float*)d_in[3];
    const float* bhh   = (const float*)d_in[4];
    const float* kbase = (const float*)d_in[5];
    const float* kspl  = (const float*)d_in[6];
    const float* kscl  = (const float*)d_in[7];
    const float* grid  = (const float*)d_in[8];
    const float* fc_w  = (const float*)d_in[9];
    const float* fc_b  = (const float*)d_in[10];
    float* out = (float*)d_out;

    cudaFuncSetAttribute(persist_kernel, cudaFuncAttributeMaxDynamicSharedMemorySize, SMEM_TOTAL);

    int dev = 0, smCount = 0;
    cudaGetDevice(&dev);
    cudaDeviceGetAttribute(&smCount, cudaDevAttrMultiProcessorCount, dev);
    int nprod = smCount - NBLK;
    bool overlap = (nprod >= 16);
    if (!overlap) nprod = 0;

    init_kernel<<<512, 256>>>(wih, bih, bhh, grid, overlap ? 0 : 1);
    if (!overlap) {
        dim3 gg(G4H / 64, Tt);
        xw0_mma<<<gg, 256>>>(x, wih, bih, bhh);
    }
    persist_kernel<<<NBLK + nprod, PTHR, SMEM_TOTAL>>>(
        x, wih, whh, kbase, kspl, kscl, fc_w, fc_b, out);
}

// round 13
// speedup vs baseline: 1.0137x; 1.0137x over previous
#include <cuda_runtime.h>
#include <cuda_bf16.h>
#include <math.h>

// Problem constants
#define Bz    128
#define Tt    1024
#define Dd    512
#define Hh    512
#define Oo    256
#define G4H   2048
#define FEAT  4608
#define NBLK  128
#define NTHR  256
#define PITCH 48        // tf32 xw0 fallback smem pitch (floats)

// persist smem layout (bytes)
#define WP_G0 520
#define WP_G1 1032
#define WP_K  584
#define SM_WG0 0
#define SM_WG1 33280
#define SM_WK  99328
#define SM_AST 175104
#define SM_STRIDE 18560       // 3 staging buffers
#define SM_KT  230784         // kt[12] + invd[30]
#define SMEM_TOTAL 232448
// producer smem layout (aliased)
#define PX_A  0
#define PX_W  133120
#define PX_MT 232000

// ---------------- device scratch ----------------
__device__ float g_xw0[(size_t)Tt * Bz * G4H];
__device__ __nv_bfloat16 g_wihb[(size_t)G4H * Dd];
__device__ float g_bg0[G4H];
__device__ float g_bg1[G4H];
__device__ __nv_bfloat16 g_hcat[Bz * 1024];
__device__ float g_sig[2][Bz * G4H];
__device__ __nv_bfloat16 g_feat[2][(size_t)Bz * FEAT];
__device__ float g_part[2][8][Bz * Hh];
__device__ float g_kt[12];
__device__ float g_invd[30];
__device__ unsigned g_bar;
__device__ unsigned g_gcnt[16];
__device__ unsigned g_pcnt[8];
__device__ unsigned g_xwflag[Tt];
__device__ unsigned g_mtnext;

// ---------------- grid barrier (128 persist blocks only) ----------------
__device__ __forceinline__ void gsync(unsigned target) {
    __syncthreads();
    if (threadIdx.x == 0) {
        asm volatile("red.release.gpu.global.add.u32 [%0], 1;" :: "l"(&g_bar) : "memory");
        unsigned v;
        do {
            asm volatile("ld.acquire.gpu.global.u32 %0, [%1];" : "=r"(v) : "l"(&g_bar) : "memory");
        } while (v < target);
    }
    __syncthreads();
}

// ---------------- bf16 mma primitives ----------------
__device__ __forceinline__ void ldm_x4(unsigned &r0, unsigned &r1, unsigned &r2, unsigned &r3, unsigned addr) {
    asm volatile("ldmatrix.sync.aligned.m8n8.x4.shared.b16 {%0,%1,%2,%3}, [%4];"
                 : "=r"(r0), "=r"(r1), "=r"(r2), "=r"(r3) : "r"(addr));
}
__device__ __forceinline__ void mma16816(float c[4], unsigned a0, unsigned a1, unsigned a2, unsigned a3,
                                         unsigned b0, unsigned b1) {
    asm volatile("mma.sync.aligned.m16n8k16.row.col.f32.bf16.bf16.f32 "
                 "{%0,%1,%2,%3},{%4,%5,%6,%7},{%8,%9},{%0,%1,%2,%3};"
                 : "+f"(c[0]), "+f"(c[1]), "+f"(c[2]), "+f"(c[3])
                 : "r"(a0), "r"(a1), "r"(a2), "r"(a3), "r"(b0), "r"(b1));
}

// ---------------- merged gates mma: 2m x 2n x 2k warps, warp tile m32 x n16 ----
// k-split by ks within each chunk (km=0: ks 0-3, km=1: ks 4-7); cross-k reduce via smem.
__device__ __forceinline__ void mma_gates(
    const __nv_bfloat16* __restrict__ Ag, int arow0,
    const __nv_bfloat16* sWg0, const __nv_bfloat16* sWg1,
    __nv_bfloat16* sA, float* sred,
    float (&acc0)[2][4], float (&acc1)[2][4])
{
    constexpr int KCH = 128, AP = 136, NCH = 8;
    int tid = threadIdx.x, lane = tid & 31, warp = tid >> 5;
    int km = warp & 1;
    int wm = ((warp >> 1) & 1) * 32;
    int wn = (warp >> 2) * 16;
    unsigned sW0a = (unsigned)__cvta_generic_to_shared(sWg0);
    unsigned sW1a = (unsigned)__cvta_generic_to_shared(sWg1);
    unsigned sAa  = (unsigned)__cvta_generic_to_shared(sA);
    float a0l[2][2][4] = {}, a1l[2][2][4] = {};   // [mi][nf][e]

    auto issue = [&](int cc) {
        const __nv_bfloat16* gb = Ag + (size_t)arow0 * 1024 + cc * KCH;
        unsigned sb = sAa + (unsigned)(cc % 3) * SM_STRIDE;
#pragma unroll
        for (int o = 0; o < 4; o++) {
            int idx = o * NTHR + tid;
            int r = idx >> 4, c = (idx & 15) * 8;
            unsigned sa = sb + (unsigned)(r * AP + c) * 2u;
            const void* ga = gb + (size_t)r * 1024 + c;
            asm volatile("cp.async.cg.shared.global [%0], [%1], 16;" :: "r"(sa), "l"(ga) : "memory");
        }
        asm volatile("cp.async.commit_group;" ::: "memory");
    };
    issue(0); issue(1);

    int a_r = (lane & 7) + ((lane >> 3) & 1) * 8;
    int a_k = ((lane >> 4) & 1) * 8;
    int b_r = (lane & 7) + ((lane >> 4) & 1) * 8;
    int b_k = ((lane >> 3) & 1) * 8;
    unsigned b0base = sW0a + (unsigned)((wn + b_r) * WP_G0 + b_k) * 2u;
    unsigned b1base = sW1a + (unsigned)((wn + b_r) * WP_G1 + b_k) * 2u;

    for (int cc = 0; cc < NCH; cc++) {
        asm volatile("cp.async.wait_group 1;" ::: "memory");
        __syncthreads();
        if (cc + 2 < NCH) issue(cc + 2);
        else asm volatile("cp.async.commit_group;" ::: "memory");
        unsigned sb = sAa + (unsigned)(cc % 3) * SM_STRIDE;
        unsigned ab0 = sb + (unsigned)((wm + a_r) * AP + a_k) * 2u;
        unsigned ab1 = sb + (unsigned)((wm + 16 + a_r) * AP + a_k) * 2u;
#pragma unroll
        for (int ks = 0; ks < 4; ks++) {
            int kk = km * 4 + ks;
            unsigned p0, p1, p2, p3, q0, q1, q2, q3;
            ldm_x4(p0, p1, p2, p3, ab0 + kk * 32);
            ldm_x4(q0, q1, q2, q3, ab1 + kk * 32);
            unsigned b0, b1, b2, b3;
            ldm_x4(b0, b1, b2, b3, b1base + (unsigned)(cc * KCH + kk * 16) * 2u);
            mma16816(a1l[0][0], p0, p1, p2, p3, b0, b1);
            mma16816(a1l[0][1], p0, p1, p2, p3, b2, b3);
            mma16816(a1l[1][0], q0, q1, q2, q3, b0, b1);
            mma16816(a1l[1][1], q0, q1, q2, q3, b2, b3);
            if (cc < 4) {
                unsigned d0, d1, d2, d3;
                ldm_x4(d0, d1, d2, d3, b0base + (unsigned)(cc * KCH + kk * 16) * 2u);
                mma16816(a0l[0][0], p0, p1, p2, p3, d0, d1);
                mma16816(a0l[0][1], p0, p1, p2, p3, d2, d3);
                mma16816(a0l[1][0], q0, q1, q2, q3, d0, d1);
                mma16816(a0l[1][1], q0, q1, q2, q3, d2, d3);
            }
        }
    }

    // cross-k reduction: partner warp^1 holds the other k-half of both m16 blocks.
    // Each warp stores its NON-owned m16 (mi = 1-km), reads partner's contribution
    // for its owned m16 (mi = km), and outputs owned m16 x n16 per layer.
    __syncthreads();
    int oth = 1 - km;
    float4* slot = (float4*)(sred + warp * 512);
    slot[0 * 32 + lane] = make_float4(a1l[oth][0][0], a1l[oth][0][1], a1l[oth][0][2], a1l[oth][0][3]);
    slot[1 * 32 + lane] = make_float4(a1l[oth][1][0], a1l[oth][1][1], a1l[oth][1][2], a1l[oth][1][3]);
    slot[2 * 32 + lane] = make_float4(a0l[oth][0][0], a0l[oth][0][1], a0l[oth][0][2], a0l[oth][0][3]);
    slot[3 * 32 + lane] = make_float4(a0l[oth][1][0], a0l[oth][1][1], a0l[oth][1][2], a0l[oth][1][3]);
    __syncthreads();
    float4* ps = (float4*)(sred + (warp ^ 1) * 512);
#pragma unroll
    for (int nf = 0; nf < 2; nf++) {
        float4 v1 = ps[nf * 32 + lane];
        float4 v0 = ps[(2 + nf) * 32 + lane];
        acc1[nf][0] = a1l[km][nf][0] + v1.x; acc1[nf][1] = a1l[km][nf][1] + v1.y;
        acc1[nf][2] = a1l[km][nf][2] + v1.z; acc1[nf][3] = a1l[km][nf][3] + v1.w;
        acc0[nf][0] = a0l[km][nf][0] + v0.x; acc0[nf][1] = a0l[km][nf][1] + v0.y;
        acc0[nf][2] = a0l[km][nf][2] + v0.z; acc0[nf][3] = a0l[km][nf][3] + v0.w;
    }
}

// ---------------- KAN mma phase (R11-proven core + tail-commit fix) ----------
template<int MI, int NW, int KCH>
__device__ __forceinline__ void mma_phase(
    const __nv_bfloat16* __restrict__ Ag, int lda, int arow0, int kbeg, int nch,
    const __nv_bfloat16* sW, int wp, __nv_bfloat16* sA, float cacc[MI][NW * 2][4])
{
    constexpr int AP  = KCH + 8;
    constexpr int OPR = KCH / 8;
    constexpr int NOPS = (MI * 64) * KCH / 8 / NTHR;
    int tid = threadIdx.x, lane = tid & 31, warp = tid >> 5;
    int wm = (warp & 3) * (MI * 16), wn = (warp >> 2) * (NW * 16);
    unsigned sWa = (unsigned)__cvta_generic_to_shared(sW);
    unsigned sAa = (unsigned)__cvta_generic_to_shared(sA);

    auto issue = [&](int cc) {
        const __nv_bfloat16* gb = Ag + (size_t)arow0 * lda + kbeg + cc * KCH;
        unsigned sb = sAa + (unsigned)(cc % 3) * SM_STRIDE;
#pragma unroll
        for (int o = 0; o < NOPS; o++) {
            int idx = o * NTHR + tid;
            int r = idx / OPR, c = (idx % OPR) * 8;
            unsigned sa = sb + (unsigned)(r * AP + c) * 2u;
            const void* ga = gb + (size_t)r * lda + c;
            asm volatile("cp.async.cg.shared.global [%0], [%1], 16;" :: "r"(sa), "l"(ga) : "memory");
        }
        asm volatile("cp.async.commit_group;" ::: "memory");
    };
    issue(0);
    if (nch > 1) issue(1);

    int a_r = (lane & 7) + ((lane >> 3) & 1) * 8;
    int a_k = ((lane >> 4) & 1) * 8;
    int b_r = (lane & 7) + ((lane >> 4) & 1) * 8;
    int b_k = ((lane >> 3) & 1) * 8;
    unsigned bbase[NW];
#pragma unroll
    for (int nw = 0; nw < NW; nw++)
        bbase[nw] = sWa + (unsigned)((wn + nw * 16 + b_r) * wp + b_k) * 2u;

    for (int cc = 0; cc < nch; cc++) {
        asm volatile("cp.async.wait_group 1;" ::: "memory");
        __syncthreads();
        if (cc + 2 < nch) issue(cc + 2);
        else asm volatile("cp.async.commit_group;" ::: "memory");

        unsigned sb = sAa + (unsigned)(cc % 3) * SM_STRIDE;
        unsigned ab[MI];
#pragma unroll
        for (int mi = 0; mi < MI; mi++)
            ab[mi] = sb + (unsigned)((wm + mi * 16 + a_r) * AP + a_k) * 2u;
#pragma unroll
        for (int ks = 0; ks < KCH / 16; ks++) {
            unsigned a0[MI], a1[MI], a2[MI], a3[MI];
#pragma unroll
            for (int mi = 0; mi < MI; mi++)
                ldm_x4(a0[mi], a1[mi], a2[mi], a3[mi], ab[mi] + ks * 32);
#pragma unroll
            for (int nw = 0; nw < NW; nw++) {
                unsigned b0, b1, b2, b3;
                ldm_x4(b0, b1, b2, b3, bbase[nw] + (unsigned)(cc * KCH + ks * 16) * 2u);
#pragma unroll
                for (int mi = 0; mi < MI; mi++) {
                    mma16816(cacc[mi][nw * 2 + 0], a0[mi], a1[mi], a2[mi], a3[mi], b0, b1);
                    mma16816(cacc[mi][nw * 2 + 1], a0[mi], a1[mi], a2[mi], a3[mi], b2, b3);
                }
            }
        }
    }
}

// ---------------- init ----------------
__global__ void init_kernel(const float* __restrict__ wih,
                            const float* __restrict__ bih, const float* __restrict__ bhh,
                            const float* __restrict__ grid, int preset_flags)
{
    size_t stride = (size_t)gridDim.x * blockDim.x;
    size_t t0 = (size_t)blockIdx.x * blockDim.x + threadIdx.x;
    for (size_t i = t0; i < (size_t)G4H * Dd; i += stride)
        g_wihb[i] = __float2bfloat16(wih[i]);
    for (size_t i = t0; i < G4H; i += stride) {
        g_bg0[i] = bih[i] + bhh[i];
        g_bg1[i] = bih[G4H + i] + bhh[G4H + i];
    }
    for (size_t i = t0; i < (size_t)Bz * 1024; i += stride) g_hcat[i] = __float2bfloat16(0.f);
    for (size_t i = t0; i < 12; i += stride) g_kt[i] = grid[i];
    for (size_t i = t0; i < 30; i += stride) {
        int j = (int)i; int k, jj;
        if (j < 11)      { k = 1; jj = j; }
        else if (j < 21) { k = 2; jj = j - 11; }
        else             { k = 3; jj = j - 21; }
        g_invd[i] = 1.0f / (grid[jj + k] - grid[jj]);
    }
    for (size_t i = t0; i < Tt; i += stride) g_xwflag[i] = (unsigned)preset_flags;
    if (t0 < 16) g_gcnt[t0] = 0u;
    if (t0 < 8) g_pcnt[t0] = 0u;
    if (t0 == 0) { g_bar = 0u; g_mtnext = 0u; }
}

// ---------------- tf32 xw0 fallback (used only if few SMs) ----------------
__device__ __forceinline__ unsigned f2tf(float x) {
    unsigned u; asm("cvt.rna.tf32.f32 %0, %1;" : "=r"(u) : "f"(x)); return u;
}
__device__ __forceinline__ void mma8(float c[4], unsigned a0, unsigned a1, unsigned a2, unsigned a3,
                                     unsigned b0, unsigned b1) {
    asm volatile("mma.sync.aligned.m16n8k8.row.col.f32.tf32.tf32.f32 "
                 "{%0,%1,%2,%3},{%4,%5,%6,%7},{%8,%9},{%0,%1,%2,%3};"
                 : "+f"(c[0]), "+f"(c[1]), "+f"(c[2]), "+f"(c[3])
                 : "r"(a0), "r"(a1), "r"(a2), "r"(a3), "r"(b0), "r"(b1));
}
__global__ void __launch_bounds__(NTHR) xw0_mma(const float* __restrict__ x,
                                                const float* __restrict__ wih,
                                                const float* __restrict__ bih,
                                                const float* __restrict__ bhh)
{
    __shared__ __align__(16) float sA[128 * PITCH];
    __shared__ __align__(16) float sB[64 * PITCH];
    int nt = blockIdx.x, mt = blockIdx.y;
    int tid = threadIdx.x, lane = tid & 31, warp = tid >> 5;
    int wm = (warp & 3) * 32, wn = (warp >> 2) * 32;
    int qr = lane >> 2, qc = lane & 3;
    float cacc[2][4][4] = {};
    const float* A = x + (size_t)mt * Dd;
    const float* W = wih + (size_t)nt * 64 * Dd;
    float4 ra[4], rb[2];
    {
#pragma unroll
        for (int j = 0; j < 4; j++) { int idx = j * 256 + tid;
            ra[j] = *(const float4*)(A + (size_t)(idx >> 3) * ((size_t)Tt * Dd) + ((idx & 7) << 2)); }
#pragma unroll
        for (int j = 0; j < 2; j++) { int idx = j * 256 + tid;
            rb[j] = *(const float4*)(W + (size_t)(idx >> 3) * Dd + ((idx & 7) << 2)); }
    }
    for (int cc = 0; cc < Dd / 32; cc++) {
        __syncthreads();
#pragma unroll
        for (int j = 0; j < 4; j++) {
            int idx = j * 256 + tid; int row = idx >> 3; int c0 = (idx & 7) << 2;
            int base = row * PITCH + ((c0 >> 4) << 4) + ((c0 & 15) >> 2);
            sA[base + 0]  = __uint_as_float(f2tf(ra[j].x));
            sA[base + 4]  = __uint_as_float(f2tf(ra[j].y));
            sA[base + 8]  = __uint_as_float(f2tf(ra[j].z));
            sA[base + 12] = __uint_as_float(f2tf(ra[j].w));
        }
#pragma unroll
        for (int j = 0; j < 2; j++) {
            int idx = j * 256 + tid; int row = idx >> 3; int c0 = (idx & 7) << 2;
            int base = row * PITCH + ((c0 >> 4) << 4) + ((c0 & 15) >> 2);
            sB[base + 0]  = __uint_as_float(f2tf(rb[j].x));
            sB[base + 4]  = __uint_as_float(f2tf(rb[j].y));
            sB[base + 8]  = __uint_as_float(f2tf(rb[j].z));
            sB[base + 12] = __uint_as_float(f2tf(rb[j].w));
        }
        __syncthreads();
        if (cc + 1 < Dd / 32) {
            int kb = (cc + 1) * 32;
#pragma unroll
            for (int j = 0; j < 4; j++) { int idx = j * 256 + tid;
                ra[j] = *(const float4*)(A + (size_t)(idx >> 3) * ((size_t)Tt * Dd) + kb + ((idx & 7) << 2)); }
#pragma unroll
            for (int j = 0; j < 2; j++) { int idx = j * 256 + tid;
                rb[j] = *(const float4*)(W + (size_t)(idx >> 3) * Dd + kb + ((idx & 7) << 2)); }
        }
#pragma unroll
        for (int h = 0; h < 2; h++) {
            unsigned bf[4][4];
#pragma unroll
            for (int f = 0; f < 4; f++) {
                float4 v = *(const float4*)(sB + (wn + f * 8 + qr) * PITCH + h * 16 + qc * 4);
                bf[f][0] = __float_as_uint(v.x); bf[f][1] = __float_as_uint(v.y);
                bf[f][2] = __float_as_uint(v.z); bf[f][3] = __float_as_uint(v.w);
            }
#pragma unroll
            for (int mi = 0; mi < 2; mi++) {
                float4 lo = *(const float4*)(sA + (wm + mi * 16 + qr) * PITCH + h * 16 + qc * 4);
                float4 hi = *(const float4*)(sA + (wm + mi * 16 + 8 + qr) * PITCH + h * 16 + qc * 4);
#pragma unroll
                for (int f = 0; f < 4; f++) {
                    mma8(cacc[mi][f], __float_as_uint(lo.x), __float_as_uint(hi.x),
                         __float_as_uint(lo.y), __float_as_uint(hi.y), bf[f][0], bf[f][1]);
                    mma8(cacc[mi][f], __float_as_uint(lo.z), __float_as_uint(hi.z),
                         __float_as_uint(lo.w), __float_as_uint(hi.w), bf[f][2], bf[f][3]);
                }
            }
        }
    }
    size_t rowbase = (size_t)mt * 128;
#pragma unroll
    for (int mi = 0; mi < 2; mi++)
#pragma unroll
        for (int f = 0; f < 4; f++) {
            int r0 = wm + mi * 16 + qr;
            int cb = nt * 64 + wn + f * 8 + qc * 2;
            float b0 = __ldg(&bih[cb]) + __ldg(&bhh[cb]);
            float b1 = __ldg(&bih[cb + 1]) + __ldg(&bhh[cb + 1]);
            *(float2*)(g_xw0 + (rowbase + r0) * G4H + cb) =
                make_float2(cacc[mi][f][0] + b0, cacc[mi][f][1] + b1);
            *(float2*)(g_xw0 + (rowbase + r0 + 8) * G4H + cb) =
                make_float2(cacc[mi][f][2] + b0, cacc[mi][f][3] + b1);
        }
}

// ---------------- mega kernel: 128 persist blocks + producer blocks ----------------
__global__ void __launch_bounds__(NTHR, 1) persist_kernel(
    const float* __restrict__ x,
    const float* __restrict__ wih, const float* __restrict__ whh,
    const float* __restrict__ kbase, const float* __restrict__ kspl,
    const float* __restrict__ kscl, const float* __restrict__ fc_w,
    const float* __restrict__ fc_b, float* __restrict__ out)
{
    extern __shared__ __align__(16) char smem_raw[];
    int bid = blockIdx.x, tid = threadIdx.x;
    int lane = tid & 31, warp = tid >> 5;
    int qr = lane >> 2, qc = lane & 3;

    // =================== xw0 producer blocks (bid >= 128) ===================
    if (bid >= NBLK) {
        __nv_bfloat16* sA = (__nv_bfloat16*)(smem_raw + PX_A);
        unsigned sAa = (unsigned)__cvta_generic_to_shared(smem_raw + PX_A);
        unsigned sWa = (unsigned)__cvta_generic_to_shared(smem_raw + PX_W);
        unsigned* s_mt = (unsigned*)(smem_raw + PX_MT);
        int a_r = (lane & 7) + ((lane >> 3) & 1) * 8;
        int a_k = ((lane >> 4) & 1) * 8;
        int b_r = (lane & 7) + ((lane >> 4) & 1) * 8;
        int b_k = ((lane >> 3) & 1) * 8;
        int wm = (warp & 3) * 32, wn = (warp >> 2) * 16;

        auto stageW = [&](int sub, int buf) {
            const __nv_bfloat16* gb = g_wihb + (size_t)sub * 32 * 512;
            unsigned dstb = sWa + (unsigned)buf * 33280u;
#pragma unroll
            for (int o = 0; o < 8; o++) {
                int idx = o * NTHR + tid;
                int r = idx >> 6, c = (idx & 63) * 8;
                asm volatile("cp.async.cg.shared.global [%0], [%1], 16;"
                             :: "r"(dstb + (unsigned)(r * 520 + c) * 2u),
                                "l"(gb + r * 512 + c) : "memory");
            }
            asm volatile("cp.async.commit_group;" ::: "memory");
        };

        for (;;) {
            __syncthreads();
            if (tid == 0) *s_mt = atomicAdd(&g_mtnext, 1u);
            __syncthreads();
            unsigned mt = *s_mt;
            if (mt >= Tt) break;
            for (int i = tid; i < 128 * 128; i += NTHR) {
                int r = i >> 7, c4 = (i & 127) << 2;
                float4 v = *(const float4*)(x + ((size_t)r * Tt + mt) * Dd + c4);
                __nv_bfloat162 p0 = __float22bfloat162_rn(make_float2(v.x, v.y));
                __nv_bfloat162 p1 = __float22bfloat162_rn(make_float2(v.z, v.w));
                *(__nv_bfloat162*)&sA[r * 520 + c4] = p0;
                *(__nv_bfloat162*)&sA[r * 520 + c4 + 2] = p1;
            }
            __syncthreads();
            stageW(0, 0);
            for (int sub = 0; sub < 64; sub++) {
                if (sub + 1 < 64) stageW(sub + 1, (sub + 1) & 1);
                else asm volatile("cp.async.commit_group;" ::: "memory");
                asm volatile("cp.async.wait_group 1;" ::: "memory");
                __syncthreads();
                unsigned bb = sWa + (unsigned)((sub & 1) * 33280) +
                              (unsigned)((wn + b_r) * 520 + b_k) * 2u;
                float cacc[2][2][4] = {};
#pragma unroll
                for (int ks = 0; ks < 32; ks++) {
                    unsigned b0, b1, b2, b3;
                    ldm_x4(b0, b1, b2, b3, bb + ks * 32);
#pragma unroll
                    for (int mi = 0; mi < 2; mi++) {
                        unsigned a0, a1, a2, a3;
                        ldm_x4(a0, a1, a2, a3,
                               sAa + (unsigned)((wm + mi * 16 + a_r) * 520 + ks * 16 + a_k) * 2u);
                        mma16816(cacc[mi][0], a0, a1, a2, a3, b0, b1);
                        mma16816(cacc[mi][1], a0, a1, a2, a3, b2, b3);
                    }
                }
                int n0 = sub * 32;
#pragma unroll
                for (int mi = 0; mi < 2; mi++)
#pragma unroll
                    for (int nf = 0; nf < 2; nf++) {
                        int row = wm + mi * 16 + qr;
                        int col = n0 + wn + nf * 8 + qc * 2;
                        float2 bv = *(const float2*)&g_bg0[col];
                        *(float2*)&g_xw0[((size_t)mt * Bz + row) * G4H + col] =
                            make_float2(cacc[mi][nf][0] + bv.x, cacc[mi][nf][1] + bv.y);
                        *(float2*)&g_xw0[((size_t)mt * Bz + row + 8) * G4H + col] =
                            make_float2(cacc[mi][nf][2] + bv.x, cacc[mi][nf][3] + bv.y);
                    }
                __syncthreads();
            }
            if (tid == 0)
                asm volatile("st.release.gpu.global.u32 [%0], %1;"
                             :: "l"(&g_xwflag[mt]), "r"(1u) : "memory");
        }
        return;
    }

    // =================== persist blocks (bid < 128) ===================
    __nv_bfloat16* sWg0 = (__nv_bfloat16*)(smem_raw + SM_WG0);
    __nv_bfloat16* sWg1 = (__nv_bfloat16*)(smem_raw + SM_WG1);
    __nv_bfloat16* sWk  = (__nv_bfloat16*)(smem_raw + SM_WK);
    __nv_bfloat16* sAst = (__nv_bfloat16*)(smem_raw + SM_AST);
    float* sred  = (float*)(smem_raw + SM_AST);   // 16KB, reused after gates pipeline
    float* skt   = (float*)(smem_raw + SM_KT);
    float* sinvd = (float*)(smem_raw + SM_KT + 48);

    int g_nt = bid >> 1, g_mh = bid & 1;
    int lyr  = bid >> 6;
    int kb2  = bid & 63;
    int k_nt = kb2 >> 3, k_ks = kb2 & 7;

    for (int i = tid; i < 32 * 512; i += NTHR) {
        int r = i >> 9, c = i & 511;
        int ng = (r >> 3) * 512 + g_nt * 8 + (r & 7);
        sWg0[r * WP_G0 + c] = __float2bfloat16(whh[(size_t)ng * 512 + c]);
    }
    for (int i = tid; i < 32 * 1024; i += NTHR) {
        int r = i >> 10, c = i & 1023;
        int ng = (r >> 3) * 512 + g_nt * 8 + (r & 7);
        float v = (c < 512) ? wih[(size_t)G4H * Dd + (size_t)ng * 512 + c]
                            : whh[(size_t)G4H * Hh + (size_t)ng * 512 + (c - 512)];
        sWg1[r * WP_G1 + c] = __float2bfloat16(v);
    }
    for (int i = tid; i < 64 * 576; i += NTHR) {
        int r = i / 576, kk0 = i % 576;
        int row = lyr * 512 + k_nt * 64 + r;
        float v;
        if (kk0 < 64) {
            int ii2 = k_ks * 64 + kk0;
            v = kbase[(size_t)row * 512 + ii2];
        } else {
            int q = kk0 - 64;
            int ii2 = k_ks * 64 + (q >> 3);
            v = kspl[((size_t)row * 512 + ii2) * 8 + (q & 7)] * kscl[(size_t)row * 512 + ii2];
        }
        sWk[r * WP_K + kk0] = __float2bfloat16(v);
    }
    if (tid < 12) skt[tid] = g_kt[tid];
    if (tid < 30) sinvd[tid] = g_invd[tid];
    __syncthreads();

    int wng = (warp >> 2) * 16;
    int eb0 = g_mh * 64 + (warp & 3) * 16 + qr;    // == g_mh*64 + wy*32 + km*16 + qr
    int encls[2]; bool isg[2];
#pragma unroll
    for (int nf = 0; nf < 2; nf++) {
        int cls = (wng + nf * 8) >> 3;
        encls[nf] = cls * 512 + g_nt * 8 + qc * 2;
        isg[nf] = (cls == 2);
    }
    float2 pb[2];
#pragma unroll
    for (int nf = 0; nf < 2; nf++) pb[nf] = *(const float2*)&g_bg1[encls[nf]];

    int upd_row0 = k_ks * 16 + (tid >> 5);
    int upd_col  = k_nt * 64 + ((tid & 31) << 1);
    float2 creg2[2] = {make_float2(0.f, 0.f), make_float2(0.f, 0.f)};
    int gidx = lyr * 8 + k_nt;
    int my_pcnt = g_nt >> 3;

    auto gate_epilogue = [&](int l, const float2 (&pre)[2][2], const float (&cc4)[2][4]) {
#pragma unroll
        for (int nf = 0; nf < 2; nf++)
#pragma unroll
            for (int r = 0; r < 2; r++) {
                int b = eb0 + r * 8;
                float v0 = cc4[nf][r * 2 + 0] + pre[nf][r].x;
                float v1 = cc4[nf][r * 2 + 1] + pre[nf][r].y;
                if (!isg[nf]) {
                    *(float2*)&g_sig[l][b * G4H + encls[nf]] = make_float2(
                        1.f / (1.f + __expf(-v0)), 1.f / (1.f + __expf(-v1)));
                } else {
#pragma unroll
                    for (int e = 0; e < 2; e++) {
                        float v = e ? v1 : v0;
                        int ii = encls[nf] + e - 1024;
                        int ch = ii >> 6, w = ii & 63;
                        size_t fbase = (size_t)b * FEAT + ch * 576;
                        g_feat[l][fbase + w] = __float2bfloat16(v / (1.f + __expf(-v)));
                        float bas[11];
#pragma unroll
                        for (int q = 0; q < 11; q++)
                            bas[q] = (v >= skt[q] && v < skt[q + 1]) ? 1.f : 0.f;
#pragma unroll
                        for (int k = 1; k <= 3; k++) {
                            int off = (k == 1) ? 0 : ((k == 2) ? 11 : 21);
#pragma unroll
                            for (int q = 0; q + k < 11; q++) {
                                float lf = (v - skt[q]) * sinvd[off + q];
                                float rf = (skt[q + k + 1] - v) * sinvd[off + q + 1];
                                bas[q] = lf * bas[q] + rf * bas[q + 1];
                            }
                        }
                        __nv_bfloat162 p0 = __float22bfloat162_rn(make_float2(bas[0], bas[1]));
                        __nv_bfloat162 p1 = __float22bfloat162_rn(make_float2(bas[2], bas[3]));
                        __nv_bfloat162 p2 = __float22bfloat162_rn(make_float2(bas[4], bas[5]));
                        __nv_bfloat162 p3 = __float22bfloat162_rn(make_float2(bas[6], bas[7]));
                        uint4 u;
                        u.x = *(unsigned*)&p0; u.y = *(unsigned*)&p1;
                        u.z = *(unsigned*)&p2; u.w = *(unsigned*)&p3;
                        *(uint4*)&g_feat[l][fbase + 64 + w * 8] = u;
                    }
                }
            }
    };

    unsigned gs = 0, ainst = 0;

    auto produce = [&]() {
        __syncthreads();
        if (tid == 0)
            asm volatile("red.release.gpu.global.add.u32 [%0], 1;"
                         :: "l"(&g_pcnt[my_pcnt]) : "memory");
        ainst++;
    };

    auto kan_step = [&](void) {
        if (tid == 0) {
            unsigned tgt = 16u * ainst, v;
            do {
                asm volatile("ld.acquire.gpu.global.u32 %0, [%1];"
                             : "=r"(v) : "l"(&g_pcnt[k_ks]) : "memory");
            } while (v < tgt);
            do {
                asm volatile("ld.acquire.gpu.global.u32 %0, [%1];"
                             : "=r"(v) : "l"(&g_pcnt[k_nt]) : "memory");
            } while (v < tgt);
        }
        __syncthreads();

        float cacc[2][4][4] = {};
        mma_phase<2, 2, 64>(g_feat[lyr], FEAT, 0, k_ks * 576, 9, sWk, WP_K, sAst, cacc);
        int wm = (warp & 3) * 32, wn = (warp >> 2) * 32;
#pragma unroll
        for (int mi = 0; mi < 2; mi++)
#pragma unroll
            for (int f = 0; f < 4; f++) {
                int r0 = wm + mi * 16 + qr;
                int cb = k_nt * 64 + wn + (f >> 1) * 16 + (f & 1) * 8 + qc * 2;
                *(float2*)&g_part[lyr][k_ks][r0 * Hh + cb] =
                    make_float2(cacc[mi][f][0], cacc[mi][f][1]);
                *(float2*)&g_part[lyr][k_ks][(r0 + 8) * Hh + cb] =
                    make_float2(cacc[mi][f][2], cacc[mi][f][3]);
            }

        float2 ig[2], fg[2], og[2];
#pragma unroll
        for (int r = 0; r < 2; r++) {
            int b = upd_row0 + r * 8, o = upd_col;
            ig[r] = __ldcg((const float2*)&g_sig[lyr][b * G4H + o]);
            fg[r] = __ldcg((const float2*)&g_sig[lyr][b * G4H + 512 + o]);
            og[r] = __ldcg((const float2*)&g_sig[lyr][b * G4H + 1536 + o]);
        }

        ++gs;
        __syncthreads();
        if (tid == 0) {
            asm volatile("red.release.gpu.global.add.u32 [%0], 1;"
                         :: "l"(&g_gcnt[gidx]) : "memory");
            unsigned v, tgt = gs * 8;
            do {
                asm volatile("ld.acquire.gpu.global.u32 %0, [%1];"
                             : "=r"(v) : "l"(&g_gcnt[gidx]) : "memory");
            } while (v < tgt);
        }
        __syncthreads();

#pragma unroll
        for (int r = 0; r < 2; r++) {
            int b = upd_row0 + r * 8, o = upd_col;
            float2 v = make_float2(0.f, 0.f);
#pragma unroll
            for (int s = 0; s < 8; s++) {
                float2 p = __ldcg((const float2*)&g_part[lyr][s][b * Hh + o]);
                v.x += p.x; v.y += p.y;
            }
            float c0 = fg[r].x * creg2[r].x + ig[r].x * v.x;
            float c1 = fg[r].y * creg2[r].y + ig[r].y * v.y;
            creg2[r] = make_float2(c0, c1);
            __nv_bfloat162 h2 = __float22bfloat162_rn(
                make_float2(og[r].x * tanhf(c0), og[r].y * tanhf(c1)));
            *(unsigned*)&g_hcat[b * 1024 + lyr * 512 + o] = *(unsigned*)&h2;
        }
    };

    auto ld_pre0 = [&](int t, float2 (&pre)[2][2]) {
        unsigned fv;
        do {
            asm volatile("ld.acquire.gpu.global.u32 %0, [%1];"
                         : "=r"(fv) : "l"(&g_xwflag[t]) : "memory");
        } while (!fv);
#pragma unroll
        for (int nf = 0; nf < 2; nf++)
#pragma unroll
            for (int r = 0; r < 2; r++)
                pre[nf][r] = __ldcs((const float2*)&g_xw0[
                    ((size_t)t * Bz + eb0 + r * 8) * G4H + encls[nf]]);
    };

    unsigned nb = 0;

    // ---- prologue: L0 step 0 (h = 0 -> gates = xw0[0], no mma) ----
    {
        float2 pre[2][2];
        ld_pre0(0, pre);
        float zero4[2][4] = {};
        gate_epilogue(0, pre, zero4);
    }
    produce();
    if (lyr == 0) kan_step();
    gsync(++nb * NBLK);

    // ---- main loop ----
    for (int i = 0; i < Tt; i++) {
        bool doL0 = (i < Tt - 1);
        {
            float2 pre0[2][2];
            if (doL0) ld_pre0(i + 1, pre0);
            float a0[2][4], a1[2][4];
            mma_gates(g_hcat, g_mh * 64, sWg0, sWg1, sAst, sred, a0, a1);
            if (doL0) gate_epilogue(0, pre0, a0);
            float2 pre1[2][2];
#pragma unroll
            for (int nf = 0; nf < 2; nf++) { pre1[nf][0] = pb[nf]; pre1[nf][1] = pb[nf]; }
            gate_epilogue(1, pre1, a1);
        }
        produce();

        if (lyr == 1 || doL0) kan_step();
        gsync(++nb * NBLK);
    }

    // ---- final FC: out = h1 @ fc_w^T + fc_b ----
    {
        int idx = bid * NTHR + tid;
        int o = idx >> 7, b = idx & 127;
        float s = fc_b[o];
        const __nv_bfloat16* hp = &g_hcat[b * 1024 + 512];
        const float* wp = &fc_w[(size_t)o * Hh];
#pragma unroll 8
        for (int k = 0; k < Hh; k++) s += __bfloat162float(__ldcg(&hp[k])) * wp[k];
        out[b * Oo + o] = s;
    }
}

// ---------------- launch ----------------
extern "C" void kernel_launch(void* const* d_in, const int* in_sizes, int n_in,
                              void* d_out, int out_size)
{
    const float* x     = (const float*)d_in[0];
    const float* wih   = (const float*)d_in[1];
    const float* whh   = (const float*)d_in[2];
    const float* bih   = (const float*)d_in[3];
    const float* bhh   = (const float*)d_in[4];
    const float* kbase = (const float*)d_in[5];
    const float* kspl  = (const float*)d_in[6];
    const float* kscl  = (const float*)d_in[7];
    const float* grid  = (const float*)d_in[8];
    const float* fc_w  = (const float*)d_in[9];
    const float* fc_b  = (const float*)d_in[10];
    float* out = (float*)d_out;

    cudaFuncSetAttribute(persist_kernel, cudaFuncAttributeMaxDynamicSharedMemorySize, SMEM_TOTAL);

    int dev = 0, smCount = 0;
    cudaGetDevice(&dev);
    cudaDeviceGetAttribute(&smCount, cudaDevAttrMultiProcessorCount, dev);
    int nprod = smCount - NBLK;
    bool overlap = (nprod >= 16);
    if (!overlap) nprod = 0;

    init_kernel<<<512, NTHR>>>(wih, bih, bhh, grid, overlap ? 0 : 1);
    if (!overlap) {
        dim3 gg(G4H / 64, Tt);
        xw0_mma<<<gg, NTHR>>>(x, wih, bih, bhh);
    }
    persist_kernel<<<NBLK + nprod, NTHR, SMEM_TOTAL>>>(
        x, wih, whh, kbase, kspl, kscl, fc_w, fc_b, out);
}

// round 14
// speedup vs baseline: 1.0559x; 1.0416x over previous
#include <cuda_runtime.h>
#include <cuda_bf16.h>
#include <math.h>

// Problem constants
#define Bz    128
#define Tt    1024
#define Dd    512
#define Hh    512
#define Oo    256
#define G4H   2048
#define FEAT  4608
#define NBLK  128
#define NTHR  256
#define PITCH 48        // tf32 xw0 fallback smem pitch (floats)

// persist smem layout (bytes)
#define WP_G0 520
#define WP_G1 1032
#define WP_K  584
#define SM_WG0 0
#define SM_WG1 33280
#define SM_WK  99328
#define SM_AST 175104
#define SM_STRIDE 18560       // 3 staging buffers (gates 17408B, KAN 18432B)
#define SM_KT  230784         // kt[12] + invd[30]
#define SMEM_TOTAL 232448
// producer smem layout (aliased)
#define PX_A  0
#define PX_W  133120
#define PX_MT 232000

// ---------------- device scratch ----------------
__device__ float g_xw0[(size_t)Tt * Bz * G4H];
__device__ __nv_bfloat16 g_wihb[(size_t)G4H * Dd];
__device__ float g_bg0[G4H];
__device__ float g_bg1[G4H];
__device__ __nv_bfloat16 g_hcat[Bz * 1024];
__device__ float g_sig[2][Bz * G4H];
__device__ __nv_bfloat16 g_feat[2][(size_t)Bz * FEAT];
__device__ float g_part[2][8][Bz * Hh];
__device__ float g_kt[12];
__device__ float g_invd[30];
__device__ unsigned g_bar;
__device__ unsigned g_gcnt[16];
__device__ unsigned g_pcnt[8];
__device__ unsigned g_xwflag[Tt];
__device__ unsigned g_mtnext;

// ---------------- grid barrier (128 persist blocks only) ----------------
__device__ __forceinline__ void gsync(unsigned target) {
    __syncthreads();
    if (threadIdx.x == 0) {
        asm volatile("red.release.gpu.global.add.u32 [%0], 1;" :: "l"(&g_bar) : "memory");
        unsigned v;
        do {
            asm volatile("ld.acquire.gpu.global.u32 %0, [%1];" : "=r"(v) : "l"(&g_bar) : "memory");
        } while (v < target);
    }
    __syncthreads();
}

// ---------------- bf16 mma primitives ----------------
__device__ __forceinline__ void ldm_x4(unsigned &r0, unsigned &r1, unsigned &r2, unsigned &r3, unsigned addr) {
    asm volatile("ldmatrix.sync.aligned.m8n8.x4.shared.b16 {%0,%1,%2,%3}, [%4];"
                 : "=r"(r0), "=r"(r1), "=r"(r2), "=r"(r3) : "r"(addr));
}
__device__ __forceinline__ void mma16816(float c[4], unsigned a0, unsigned a1, unsigned a2, unsigned a3,
                                         unsigned b0, unsigned b1) {
    asm volatile("mma.sync.aligned.m16n8k16.row.col.f32.bf16.bf16.f32 "
                 "{%0,%1,%2,%3},{%4,%5,%6,%7},{%8,%9},{%0,%1,%2,%3};"
                 : "+f"(c[0]), "+f"(c[1]), "+f"(c[2]), "+f"(c[3])
                 : "r"(a0), "r"(a1), "r"(a2), "r"(a3), "r"(b0), "r"(b1));
}

// ---------------- merged gates mma: R11 config (4m x 2n), KCH=128, tail-commit fix ----
__device__ __forceinline__ void mma_gates(
    const __nv_bfloat16* __restrict__ Ag, int arow0,
    const __nv_bfloat16* sWg0, const __nv_bfloat16* sWg1,
    __nv_bfloat16* sA, float (&acc0)[2][4], float (&acc1)[2][4])
{
    constexpr int KCH = 128, AP = 136, NCH = 8;
    int tid = threadIdx.x, lane = tid & 31, warp = tid >> 5;
    int wm = (warp & 3) * 16, wn = (warp >> 2) * 16;
    unsigned sW0a = (unsigned)__cvta_generic_to_shared(sWg0);
    unsigned sW1a = (unsigned)__cvta_generic_to_shared(sWg1);
    unsigned sAa  = (unsigned)__cvta_generic_to_shared(sA);

    auto issue = [&](int cc) {
        const __nv_bfloat16* gb = Ag + (size_t)arow0 * 1024 + cc * KCH;
        unsigned sb = sAa + (unsigned)(cc % 3) * SM_STRIDE;
#pragma unroll
        for (int o = 0; o < 4; o++) {
            int idx = o * NTHR + tid;
            int r = idx >> 4, c = (idx & 15) * 8;
            unsigned sa = sb + (unsigned)(r * AP + c) * 2u;
            const void* ga = gb + (size_t)r * 1024 + c;
            asm volatile("cp.async.cg.shared.global [%0], [%1], 16;" :: "r"(sa), "l"(ga) : "memory");
        }
        asm volatile("cp.async.commit_group;" ::: "memory");
    };
    issue(0); issue(1);

    int a_r = (lane & 7) + ((lane >> 3) & 1) * 8;
    int a_k = ((lane >> 4) & 1) * 8;
    int b_r = (lane & 7) + ((lane >> 4) & 1) * 8;
    int b_k = ((lane >> 3) & 1) * 8;
    unsigned b0base = sW0a + (unsigned)((wn + b_r) * WP_G0 + b_k) * 2u;
    unsigned b1base = sW1a + (unsigned)((wn + b_r) * WP_G1 + b_k) * 2u;

    for (int cc = 0; cc < NCH; cc++) {
        asm volatile("cp.async.wait_group 1;" ::: "memory");
        __syncthreads();
        if (cc + 2 < NCH) issue(cc + 2);
        else asm volatile("cp.async.commit_group;" ::: "memory");
        unsigned ab = sAa + (unsigned)(cc % 3) * SM_STRIDE + (unsigned)((wm + a_r) * AP + a_k) * 2u;
#pragma unroll
        for (int ks = 0; ks < 8; ks++) {
            unsigned a0r, a1r, a2r, a3r;
            ldm_x4(a0r, a1r, a2r, a3r, ab + ks * 32);
            unsigned b0, b1, b2, b3;
            ldm_x4(b0, b1, b2, b3, b1base + (unsigned)(cc * KCH + ks * 16) * 2u);
            mma16816(acc1[0], a0r, a1r, a2r, a3r, b0, b1);
            mma16816(acc1[1], a0r, a1r, a2r, a3r, b2, b3);
            if (cc < 4) {
                unsigned c0, c1, c2, c3;
                ldm_x4(c0, c1, c2, c3, b0base + (unsigned)(cc * KCH + ks * 16) * 2u);
                mma16816(acc0[0], a0r, a1r, a2r, a3r, c0, c1);
                mma16816(acc0[1], a0r, a1r, a2r, a3r, c2, c3);
            }
        }
    }
}

// ---------------- KAN mma: R11 config (4m x 2n, MI=2 NW=2), KCH=64, tail-commit fix ----
template<int MI, int NW, int KCH>
__device__ __forceinline__ void mma_phase(
    const __nv_bfloat16* __restrict__ Ag, int lda, int arow0, int kbeg, int nch,
    const __nv_bfloat16* sW, int wp, __nv_bfloat16* sA, float cacc[MI][NW * 2][4])
{
    constexpr int AP  = KCH + 8;
    constexpr int OPR = KCH / 8;
    constexpr int NOPS = (MI * 64) * KCH / 8 / NTHR;
    int tid = threadIdx.x, lane = tid & 31, warp = tid >> 5;
    int wm = (warp & 3) * (MI * 16), wn = (warp >> 2) * (NW * 16);
    unsigned sWa = (unsigned)__cvta_generic_to_shared(sW);
    unsigned sAa = (unsigned)__cvta_generic_to_shared(sA);

    auto issue = [&](int cc) {
        const __nv_bfloat16* gb = Ag + (size_t)arow0 * lda + kbeg + cc * KCH;
        unsigned sb = sAa + (unsigned)(cc % 3) * SM_STRIDE;
#pragma unroll
        for (int o = 0; o < NOPS; o++) {
            int idx = o * NTHR + tid;
            int r = idx / OPR, c = (idx % OPR) * 8;
            unsigned sa = sb + (unsigned)(r * AP + c) * 2u;
            const void* ga = gb + (size_t)r * lda + c;
            asm volatile("cp.async.cg.shared.global [%0], [%1], 16;" :: "r"(sa), "l"(ga) : "memory");
        }
        asm volatile("cp.async.commit_group;" ::: "memory");
    };
    issue(0);
    if (nch > 1) issue(1);

    int a_r = (lane & 7) + ((lane >> 3) & 1) * 8;
    int a_k = ((lane >> 4) & 1) * 8;
    int b_r = (lane & 7) + ((lane >> 4) & 1) * 8;
    int b_k = ((lane >> 3) & 1) * 8;
    unsigned bbase[NW];
#pragma unroll
    for (int nw = 0; nw < NW; nw++)
        bbase[nw] = sWa + (unsigned)((wn + nw * 16 + b_r) * wp + b_k) * 2u;

    for (int cc = 0; cc < nch; cc++) {
        asm volatile("cp.async.wait_group 1;" ::: "memory");
        __syncthreads();
        if (cc + 2 < nch) issue(cc + 2);
        else asm volatile("cp.async.commit_group;" ::: "memory");

        unsigned sb = sAa + (unsigned)(cc % 3) * SM_STRIDE;
        unsigned ab[MI];
#pragma unroll
        for (int mi = 0; mi < MI; mi++)
            ab[mi] = sb + (unsigned)((wm + mi * 16 + a_r) * AP + a_k) * 2u;
#pragma unroll
        for (int ks = 0; ks < KCH / 16; ks++) {
            unsigned a0[MI], a1[MI], a2[MI], a3[MI];
#pragma unroll
            for (int mi = 0; mi < MI; mi++)
                ldm_x4(a0[mi], a1[mi], a2[mi], a3[mi], ab[mi] + ks * 32);
#pragma unroll
            for (int nw = 0; nw < NW; nw++) {
                unsigned b0, b1, b2, b3;
                ldm_x4(b0, b1, b2, b3, bbase[nw] + (unsigned)(cc * KCH + ks * 16) * 2u);
#pragma unroll
                for (int mi = 0; mi < MI; mi++) {
                    mma16816(cacc[mi][nw * 2 + 0], a0[mi], a1[mi], a2[mi], a3[mi], b0, b1);
                    mma16816(cacc[mi][nw * 2 + 1], a0[mi], a1[mi], a2[mi], a3[mi], b2, b3);
                }
            }
        }
    }
}

// ---------------- init ----------------
__global__ void init_kernel(const float* __restrict__ wih,
                            const float* __restrict__ bih, const float* __restrict__ bhh,
                            const float* __restrict__ grid, int preset_flags)
{
    size_t stride = (size_t)gridDim.x * blockDim.x;
    size_t t0 = (size_t)blockIdx.x * blockDim.x + threadIdx.x;
    for (size_t i = t0; i < (size_t)G4H * Dd; i += stride)
        g_wihb[i] = __float2bfloat16(wih[i]);
    for (size_t i = t0; i < G4H; i += stride) {
        g_bg0[i] = bih[i] + bhh[i];
        g_bg1[i] = bih[G4H + i] + bhh[G4H + i];
    }
    for (size_t i = t0; i < (size_t)Bz * 1024; i += stride) g_hcat[i] = __float2bfloat16(0.f);
    for (size_t i = t0; i < 12; i += stride) g_kt[i] = grid[i];
    for (size_t i = t0; i < 30; i += stride) {
        int j = (int)i; int k, jj;
        if (j < 11)      { k = 1; jj = j; }
        else if (j < 21) { k = 2; jj = j - 11; }
        else             { k = 3; jj = j - 21; }
        g_invd[i] = 1.0f / (grid[jj + k] - grid[jj]);
    }
    for (size_t i = t0; i < Tt; i += stride) g_xwflag[i] = (unsigned)preset_flags;
    if (t0 < 16) g_gcnt[t0] = 0u;
    if (t0 < 8) g_pcnt[t0] = 0u;
    if (t0 == 0) { g_bar = 0u; g_mtnext = 0u; }
}

// ---------------- tf32 xw0 fallback (used only if few SMs) ----------------
__device__ __forceinline__ unsigned f2tf(float x) {
    unsigned u; asm("cvt.rna.tf32.f32 %0, %1;" : "=r"(u) : "f"(x)); return u;
}
__device__ __forceinline__ void mma8(float c[4], unsigned a0, unsigned a1, unsigned a2, unsigned a3,
                                     unsigned b0, unsigned b1) {
    asm volatile("mma.sync.aligned.m16n8k8.row.col.f32.tf32.tf32.f32 "
                 "{%0,%1,%2,%3},{%4,%5,%6,%7},{%8,%9},{%0,%1,%2,%3};"
                 : "+f"(c[0]), "+f"(c[1]), "+f"(c[2]), "+f"(c[3])
                 : "r"(a0), "r"(a1), "r"(a2), "r"(a3), "r"(b0), "r"(b1));
}
__global__ void __launch_bounds__(NTHR) xw0_mma(const float* __restrict__ x,
                                                const float* __restrict__ wih,
                                                const float* __restrict__ bih,
                                                const float* __restrict__ bhh)
{
    __shared__ __align__(16) float sA[128 * PITCH];
    __shared__ __align__(16) float sB[64 * PITCH];
    int nt = blockIdx.x, mt = blockIdx.y;
    int tid = threadIdx.x, lane = tid & 31, warp = tid >> 5;
    int wm = (warp & 3) * 32, wn = (warp >> 2) * 32;
    int qr = lane >> 2, qc = lane & 3;
    float cacc[2][4][4] = {};
    const float* A = x + (size_t)mt * Dd;
    const float* W = wih + (size_t)nt * 64 * Dd;
    float4 ra[4], rb[2];
    {
#pragma unroll
        for (int j = 0; j < 4; j++) { int idx = j * 256 + tid;
            ra[j] = *(const float4*)(A + (size_t)(idx >> 3) * ((size_t)Tt * Dd) + ((idx & 7) << 2)); }
#pragma unroll
        for (int j = 0; j < 2; j++) { int idx = j * 256 + tid;
            rb[j] = *(const float4*)(W + (size_t)(idx >> 3) * Dd + ((idx & 7) << 2)); }
    }
    for (int cc = 0; cc < Dd / 32; cc++) {
        __syncthreads();
#pragma unroll
        for (int j = 0; j < 4; j++) {
            int idx = j * 256 + tid; int row = idx >> 3; int c0 = (idx & 7) << 2;
            int base = row * PITCH + ((c0 >> 4) << 4) + ((c0 & 15) >> 2);
            sA[base + 0]  = __uint_as_float(f2tf(ra[j].x));
            sA[base + 4]  = __uint_as_float(f2tf(ra[j].y));
            sA[base + 8]  = __uint_as_float(f2tf(ra[j].z));
            sA[base + 12] = __uint_as_float(f2tf(ra[j].w));
        }
#pragma unroll
        for (int j = 0; j < 2; j++) {
            int idx = j * 256 + tid; int row = idx >> 3; int c0 = (idx & 7) << 2;
            int base = row * PITCH + ((c0 >> 4) << 4) + ((c0 & 15) >> 2);
            sB[base + 0]  = __uint_as_float(f2tf(rb[j].x));
            sB[base + 4]  = __uint_as_float(f2tf(rb[j].y));
            sB[base + 8]  = __uint_as_float(f2tf(rb[j].z));
            sB[base + 12] = __uint_as_float(f2tf(rb[j].w));
        }
        __syncthreads();
        if (cc + 1 < Dd / 32) {
            int kb = (cc + 1) * 32;
#pragma unroll
            for (int j = 0; j < 4; j++) { int idx = j * 256 + tid;
                ra[j] = *(const float4*)(A + (size_t)(idx >> 3) * ((size_t)Tt * Dd) + kb + ((idx & 7) << 2)); }
#pragma unroll
            for (int j = 0; j < 2; j++) { int idx = j * 256 + tid;
                rb[j] = *(const float4*)(W + (size_t)(idx >> 3) * Dd + kb + ((idx & 7) << 2)); }
        }
#pragma unroll
        for (int h = 0; h < 2; h++) {
            unsigned bf[4][4];
#pragma unroll
            for (int f = 0; f < 4; f++) {
                float4 v = *(const float4*)(sB + (wn + f * 8 + qr) * PITCH + h * 16 + qc * 4);
                bf[f][0] = __float_as_uint(v.x); bf[f][1] = __float_as_uint(v.y);
                bf[f][2] = __float_as_uint(v.z); bf[f][3] = __float_as_uint(v.w);
            }
#pragma unroll
            for (int mi = 0; mi < 2; mi++) {
                float4 lo = *(const float4*)(sA + (wm + mi * 16 + qr) * PITCH + h * 16 + qc * 4);
                float4 hi = *(const float4*)(sA + (wm + mi * 16 + 8 + qr) * PITCH + h * 16 + qc * 4);
#pragma unroll
                for (int f = 0; f < 4; f++) {
                    mma8(cacc[mi][f], __float_as_uint(lo.x), __float_as_uint(hi.x),
                         __float_as_uint(lo.y), __float_as_uint(hi.y), bf[f][0], bf[f][1]);
                    mma8(cacc[mi][f], __float_as_uint(lo.z), __float_as_uint(hi.z),
                         __float_as_uint(lo.w), __float_as_uint(hi.w), bf[f][2], bf[f][3]);
                }
            }
        }
    }
    size_t rowbase = (size_t)mt * 128;
#pragma unroll
    for (int mi = 0; mi < 2; mi++)
#pragma unroll
        for (int f = 0; f < 4; f++) {
            int r0 = wm + mi * 16 + qr;
            int cb = nt * 64 + wn + f * 8 + qc * 2;
            float b0 = __ldg(&bih[cb]) + __ldg(&bhh[cb]);
            float b1 = __ldg(&bih[cb + 1]) + __ldg(&bhh[cb + 1]);
            *(float2*)(g_xw0 + (rowbase + r0) * G4H + cb) =
                make_float2(cacc[mi][f][0] + b0, cacc[mi][f][1] + b1);
            *(float2*)(g_xw0 + (rowbase + r0 + 8) * G4H + cb) =
                make_float2(cacc[mi][f][2] + b0, cacc[mi][f][3] + b1);
        }
}

// ---------------- mega kernel: 128 persist blocks + producer blocks ----------------
__global__ void __launch_bounds__(NTHR, 1) persist_kernel(
    const float* __restrict__ x,
    const float* __restrict__ wih, const float* __restrict__ whh,
    const float* __restrict__ kbase, const float* __restrict__ kspl,
    const float* __restrict__ kscl, const float* __restrict__ fc_w,
    const float* __restrict__ fc_b, float* __restrict__ out)
{
    extern __shared__ __align__(16) char smem_raw[];
    int bid = blockIdx.x, tid = threadIdx.x;
    int lane = tid & 31, warp = tid >> 5;
    int qr = lane >> 2, qc = lane & 3;

    // =================== xw0 producer blocks (bid >= 128) ===================
    if (bid >= NBLK) {
        __nv_bfloat16* sA = (__nv_bfloat16*)(smem_raw + PX_A);
        unsigned sAa = (unsigned)__cvta_generic_to_shared(smem_raw + PX_A);
        unsigned sWa = (unsigned)__cvta_generic_to_shared(smem_raw + PX_W);
        unsigned* s_mt = (unsigned*)(smem_raw + PX_MT);
        int a_r = (lane & 7) + ((lane >> 3) & 1) * 8;
        int a_k = ((lane >> 4) & 1) * 8;
        int b_r = (lane & 7) + ((lane >> 4) & 1) * 8;
        int b_k = ((lane >> 3) & 1) * 8;
        int wm = (warp & 3) * 32, wn = (warp >> 2) * 16;

        auto stageW = [&](int sub, int buf) {
            const __nv_bfloat16* gb = g_wihb + (size_t)sub * 32 * 512;
            unsigned dstb = sWa + (unsigned)buf * 33280u;
#pragma unroll
            for (int o = 0; o < 8; o++) {
                int idx = o * NTHR + tid;
                int r = idx >> 6, c = (idx & 63) * 8;
                asm volatile("cp.async.cg.shared.global [%0], [%1], 16;"
                             :: "r"(dstb + (unsigned)(r * 520 + c) * 2u),
                                "l"(gb + r * 512 + c) : "memory");
            }
            asm volatile("cp.async.commit_group;" ::: "memory");
        };

        for (;;) {
            __syncthreads();
            if (tid == 0) *s_mt = atomicAdd(&g_mtnext, 1u);
            __syncthreads();
            unsigned mt = *s_mt;
            if (mt >= Tt) break;
            for (int i = tid; i < 128 * 128; i += NTHR) {
                int r = i >> 7, c4 = (i & 127) << 2;
                float4 v = *(const float4*)(x + ((size_t)r * Tt + mt) * Dd + c4);
                __nv_bfloat162 p0 = __float22bfloat162_rn(make_float2(v.x, v.y));
                __nv_bfloat162 p1 = __float22bfloat162_rn(make_float2(v.z, v.w));
                *(__nv_bfloat162*)&sA[r * 520 + c4] = p0;
                *(__nv_bfloat162*)&sA[r * 520 + c4 + 2] = p1;
            }
            __syncthreads();
            stageW(0, 0);
            for (int sub = 0; sub < 64; sub++) {
                if (sub + 1 < 64) stageW(sub + 1, (sub + 1) & 1);
                else asm volatile("cp.async.commit_group;" ::: "memory");
                asm volatile("cp.async.wait_group 1;" ::: "memory");
                __syncthreads();
                unsigned bb = sWa + (unsigned)((sub & 1) * 33280) +
                              (unsigned)((wn + b_r) * 520 + b_k) * 2u;
                float cacc[2][2][4] = {};
#pragma unroll
                for (int ks = 0; ks < 32; ks++) {
                    unsigned b0, b1, b2, b3;
                    ldm_x4(b0, b1, b2, b3, bb + ks * 32);
#pragma unroll
                    for (int mi = 0; mi < 2; mi++) {
                        unsigned a0, a1, a2, a3;
                        ldm_x4(a0, a1, a2, a3,
                               sAa + (unsigned)((wm + mi * 16 + a_r) * 520 + ks * 16 + a_k) * 2u);
                        mma16816(cacc[mi][0], a0, a1, a2, a3, b0, b1);
                        mma16816(cacc[mi][1], a0, a1, a2, a3, b2, b3);
                    }
                }
                int n0 = sub * 32;
#pragma unroll
                for (int mi = 0; mi < 2; mi++)
#pragma unroll
                    for (int nf = 0; nf < 2; nf++) {
                        int row = wm + mi * 16 + qr;
                        int col = n0 + wn + nf * 8 + qc * 2;
                        float2 bv = *(const float2*)&g_bg0[col];
                        *(float2*)&g_xw0[((size_t)mt * Bz + row) * G4H + col] =
                            make_float2(cacc[mi][nf][0] + bv.x, cacc[mi][nf][1] + bv.y);
                        *(float2*)&g_xw0[((size_t)mt * Bz + row + 8) * G4H + col] =
                            make_float2(cacc[mi][nf][2] + bv.x, cacc[mi][nf][3] + bv.y);
                    }
                __syncthreads();
            }
            if (tid == 0)
                asm volatile("st.release.gpu.global.u32 [%0], %1;"
                             :: "l"(&g_xwflag[mt]), "r"(1u) : "memory");
        }
        return;
    }

    // =================== persist blocks (bid < 128) ===================
    __nv_bfloat16* sWg0 = (__nv_bfloat16*)(smem_raw + SM_WG0);
    __nv_bfloat16* sWg1 = (__nv_bfloat16*)(smem_raw + SM_WG1);
    __nv_bfloat16* sWk  = (__nv_bfloat16*)(smem_raw + SM_WK);
    __nv_bfloat16* sAst = (__nv_bfloat16*)(smem_raw + SM_AST);
    float* skt   = (float*)(smem_raw + SM_KT);
    float* sinvd = (float*)(smem_raw + SM_KT + 48);

    int g_nt = bid >> 1, g_mh = bid & 1;
    int lyr  = bid >> 6;
    int kb2  = bid & 63;
    int k_nt = kb2 >> 3, k_ks = kb2 & 7;

    for (int i = tid; i < 32 * 512; i += NTHR) {
        int r = i >> 9, c = i & 511;
        int ng = (r >> 3) * 512 + g_nt * 8 + (r & 7);
        sWg0[r * WP_G0 + c] = __float2bfloat16(whh[(size_t)ng * 512 + c]);
    }
    for (int i = tid; i < 32 * 1024; i += NTHR) {
        int r = i >> 10, c = i & 1023;
        int ng = (r >> 3) * 512 + g_nt * 8 + (r & 7);
        float v = (c < 512) ? wih[(size_t)G4H * Dd + (size_t)ng * 512 + c]
                            : whh[(size_t)G4H * Hh + (size_t)ng * 512 + (c - 512)];
        sWg1[r * WP_G1 + c] = __float2bfloat16(v);
    }
    for (int i = tid; i < 64 * 576; i += NTHR) {
        int r = i / 576, kk0 = i % 576;
        int row = lyr * 512 + k_nt * 64 + r;
        float v;
        if (kk0 < 64) {
            int ii2 = k_ks * 64 + kk0;
            v = kbase[(size_t)row * 512 + ii2];
        } else {
            int q = kk0 - 64;
            int ii2 = k_ks * 64 + (q >> 3);
            v = kspl[((size_t)row * 512 + ii2) * 8 + (q & 7)] * kscl[(size_t)row * 512 + ii2];
        }
        sWk[r * WP_K + kk0] = __float2bfloat16(v);
    }
    if (tid < 12) skt[tid] = g_kt[tid];
    if (tid < 30) sinvd[tid] = g_invd[tid];
    __syncthreads();

    int wng = (warp >> 2) * 16;
    int eb0 = g_mh * 64 + (warp & 3) * 16 + qr;
    int encls[2]; bool isg[2];
#pragma unroll
    for (int nf = 0; nf < 2; nf++) {
        int cls = (wng + nf * 8) >> 3;
        encls[nf] = cls * 512 + g_nt * 8 + qc * 2;
        isg[nf] = (cls == 2);
    }
    float2 pb[2];
#pragma unroll
    for (int nf = 0; nf < 2; nf++) pb[nf] = *(const float2*)&g_bg1[encls[nf]];

    int upd_row0 = k_ks * 16 + (tid >> 5);
    int upd_col  = k_nt * 64 + ((tid & 31) << 1);
    float2 creg2[2] = {make_float2(0.f, 0.f), make_float2(0.f, 0.f)};
    int gidx = lyr * 8 + k_nt;
    int my_pcnt = g_nt >> 3;

    auto gate_epilogue = [&](int l, const float2 (&pre)[2][2], const float (&cc4)[2][4]) {
#pragma unroll
        for (int nf = 0; nf < 2; nf++)
#pragma unroll
            for (int r = 0; r < 2; r++) {
                int b = eb0 + r * 8;
                float v0 = cc4[nf][r * 2 + 0] + pre[nf][r].x;
                float v1 = cc4[nf][r * 2 + 1] + pre[nf][r].y;
                if (!isg[nf]) {
                    *(float2*)&g_sig[l][b * G4H + encls[nf]] = make_float2(
                        1.f / (1.f + __expf(-v0)), 1.f / (1.f + __expf(-v1)));
                } else {
#pragma unroll
                    for (int e = 0; e < 2; e++) {
                        float v = e ? v1 : v0;
                        int ii = encls[nf] + e - 1024;
                        int ch = ii >> 6, w = ii & 63;
                        size_t fbase = (size_t)b * FEAT + ch * 576;
                        g_feat[l][fbase + w] = __float2bfloat16(v / (1.f + __expf(-v)));
                        float bas[11];
#pragma unroll
                        for (int q = 0; q < 11; q++)
                            bas[q] = (v >= skt[q] && v < skt[q + 1]) ? 1.f : 0.f;
#pragma unroll
                        for (int k = 1; k <= 3; k++) {
                            int off = (k == 1) ? 0 : ((k == 2) ? 11 : 21);
#pragma unroll
                            for (int q = 0; q + k < 11; q++) {
                                float lf = (v - skt[q]) * sinvd[off + q];
                                float rf = (skt[q + k + 1] - v) * sinvd[off + q + 1];
                                bas[q] = lf * bas[q] + rf * bas[q + 1];
                            }
                        }
                        __nv_bfloat162 p0 = __float22bfloat162_rn(make_float2(bas[0], bas[1]));
                        __nv_bfloat162 p1 = __float22bfloat162_rn(make_float2(bas[2], bas[3]));
                        __nv_bfloat162 p2 = __float22bfloat162_rn(make_float2(bas[4], bas[5]));
                        __nv_bfloat162 p3 = __float22bfloat162_rn(make_float2(bas[6], bas[7]));
                        uint4 u;
                        u.x = *(unsigned*)&p0; u.y = *(unsigned*)&p1;
                        u.z = *(unsigned*)&p2; u.w = *(unsigned*)&p3;
                        *(uint4*)&g_feat[l][fbase + 64 + w * 8] = u;
                    }
                }
            }
    };

    unsigned gs = 0, ainst = 0;

    auto produce = [&]() {
        __syncthreads();
        if (tid == 0)
            asm volatile("red.release.gpu.global.add.u32 [%0], 1;"
                         :: "l"(&g_pcnt[my_pcnt]) : "memory");
        ainst++;
    };

    auto kan_step = [&](void) {
        if (tid == 0) {
            unsigned tgt = 16u * ainst, v;
            do {
                asm volatile("ld.acquire.gpu.global.u32 %0, [%1];"
                             : "=r"(v) : "l"(&g_pcnt[k_ks]) : "memory");
            } while (v < tgt);
            do {
                asm volatile("ld.acquire.gpu.global.u32 %0, [%1];"
                             : "=r"(v) : "l"(&g_pcnt[k_nt]) : "memory");
            } while (v < tgt);
        }
        __syncthreads();

        // hoist sigmoid operand loads: L2 latency hides behind the KAN mma
        float2 ig[2], fg[2], og[2];
#pragma unroll
        for (int r = 0; r < 2; r++) {
            int b = upd_row0 + r * 8, o = upd_col;
            ig[r] = __ldcg((const float2*)&g_sig[lyr][b * G4H + o]);
            fg[r] = __ldcg((const float2*)&g_sig[lyr][b * G4H + 512 + o]);
            og[r] = __ldcg((const float2*)&g_sig[lyr][b * G4H + 1536 + o]);
        }

        float cacc[2][4][4] = {};
        mma_phase<2, 2, 64>(g_feat[lyr], FEAT, 0, k_ks * 576, 9, sWk, WP_K, sAst, cacc);
        int wm = (warp & 3) * 32, wn = (warp >> 2) * 32;
#pragma unroll
        for (int mi = 0; mi < 2; mi++)
#pragma unroll
            for (int f = 0; f < 4; f++) {
                int r0 = wm + mi * 16 + qr;
                int cb = k_nt * 64 + wn + (f >> 1) * 16 + (f & 1) * 8 + qc * 2;
                *(float2*)&g_part[lyr][k_ks][r0 * Hh + cb] =
                    make_float2(cacc[mi][f][0], cacc[mi][f][1]);
                *(float2*)&g_part[lyr][k_ks][(r0 + 8) * Hh + cb] =
                    make_float2(cacc[mi][f][2], cacc[mi][f][3]);
            }

        ++gs;
        __syncthreads();
        if (tid == 0) {
            asm volatile("red.release.gpu.global.add.u32 [%0], 1;"
                         :: "l"(&g_gcnt[gidx]) : "memory");
            unsigned v, tgt = gs * 8;
            do {
                asm volatile("ld.acquire.gpu.global.u32 %0, [%1];"
                             : "=r"(v) : "l"(&g_gcnt[gidx]) : "memory");
            } while (v < tgt);
        }
        __syncthreads();

#pragma unroll
        for (int r = 0; r < 2; r++) {
            int b = upd_row0 + r * 8, o = upd_col;
            float2 v = make_float2(0.f, 0.f);
#pragma unroll
            for (int s = 0; s < 8; s++) {
                float2 p = __ldcg((const float2*)&g_part[lyr][s][b * Hh + o]);
                v.x += p.x; v.y += p.y;
            }
            float c0 = fg[r].x * creg2[r].x + ig[r].x * v.x;
            float c1 = fg[r].y * creg2[r].y + ig[r].y * v.y;
            creg2[r] = make_float2(c0, c1);
            __nv_bfloat162 h2 = __float22bfloat162_rn(
                make_float2(og[r].x * tanhf(c0), og[r].y * tanhf(c1)));
            *(unsigned*)&g_hcat[b * 1024 + lyr * 512 + o] = *(unsigned*)&h2;
        }
    };

    auto ld_pre0 = [&](int t, float2 (&pre)[2][2]) {
        unsigned fv;
        do {
            asm volatile("ld.acquire.gpu.global.u32 %0, [%1];"
                         : "=r"(fv) : "l"(&g_xwflag[t]) : "memory");
        } while (!fv);
#pragma unroll
        for (int nf = 0; nf < 2; nf++)
#pragma unroll
            for (int r = 0; r < 2; r++)
                pre[nf][r] = __ldcs((const float2*)&g_xw0[
                    ((size_t)t * Bz + eb0 + r * 8) * G4H + encls[nf]]);
    };

    unsigned nb = 0;

    // ---- prologue: L0 step 0 (h = 0 -> gates = xw0[0], no mma) ----
    {
        float2 pre[2][2];
        ld_pre0(0, pre);
        float zero4[2][4] = {};
        gate_epilogue(0, pre, zero4);
    }
    produce();
    if (lyr == 0) kan_step();
    gsync(++nb * NBLK);

    // ---- main loop ----
    for (int i = 0; i < Tt; i++) {
        bool doL0 = (i < Tt - 1);
        {
            float2 pre0[2][2];
            if (doL0) ld_pre0(i + 1, pre0);
            float a0[2][4] = {}, a1[2][4] = {};
            mma_gates(g_hcat, g_mh * 64, sWg0, sWg1, sAst, a0, a1);
            if (doL0) gate_epilogue(0, pre0, a0);
            float2 pre1[2][2];
#pragma unroll
            for (int nf = 0; nf < 2; nf++) { pre1[nf][0] = pb[nf]; pre1[nf][1] = pb[nf]; }
            gate_epilogue(1, pre1, a1);
        }
        produce();

        if (lyr == 1 || doL0) kan_step();
        gsync(++nb * NBLK);
    }

    // ---- final FC: out = h1 @ fc_w^T + fc_b ----
    {
        int idx = bid * NTHR + tid;
        int o = idx >> 7, b = idx & 127;
        float s = fc_b[o];
        const __nv_bfloat16* hp = &g_hcat[b * 1024 + 512];
        const float* wp = &fc_w[(size_t)o * Hh];
#pragma unroll 8
        for (int k = 0; k < Hh; k++) s += __bfloat162float(__ldcg(&hp[k])) * wp[k];
        out[b * Oo + o] = s;
    }
}

// ---------------- launch ----------------
extern "C" void kernel_launch(void* const* d_in, const int* in_sizes, int n_in,
                              void* d_out, int out_size)
{
    const float* x     = (const float*)d_in[0];
    const float* wih   = (const float*)d_in[1];
    const float* whh   = (const float*)d_in[2];
    const float* bih   = (const float*)d_in[3];
    const float* bhh   = (const float*)d_in[4];
    const float* kbase = (const float*)d_in[5];
    const float* kspl  = (const float*)d_in[6];
    const float* kscl  = (const float*)d_in[7];
    const float* grid  = (const float*)d_in[8];
    const float* fc_w  = (const float*)d_in[9];
    const float* fc_b  = (const float*)d_in[10];
    float* out = (float*)d_out;

    cudaFuncSetAttribute(persist_kernel, cudaFuncAttributeMaxDynamicSharedMemorySize, SMEM_TOTAL);

    int dev = 0, smCount = 0;
    cudaGetDevice(&dev);
    cudaDeviceGetAttribute(&smCount, cudaDevAttrMultiProcessorCount, dev);
    int nprod = smCount - NBLK;
    bool overlap = (nprod >= 16);
    if (!overlap) nprod = 0;

    init_kernel<<<512, NTHR>>>(wih, bih, bhh, grid, overlap ? 0 : 1);
    if (!overlap) {
        dim3 gg(G4H / 64, Tt);
        xw0_mma<<<gg, NTHR>>>(x, wih, bih, bhh);
    }
    persist_kernel<<<NBLK + nprod, NTHR, SMEM_TOTAL>>>(
        x, wih, whh, kbase, kspl, kscl, fc_w, fc_b, out);
}

// round 15
// speedup vs baseline: 1.0624x; 1.0061x over previous
#include <cuda_runtime.h>
#include <cuda_bf16.h>
#include <math.h>

// Problem constants
#define Bz    128
#define Tt    1024
#define Dd    512
#define Hh    512
#define Oo    256
#define G4H   2048
#define FEAT  4608
#define NBLK  128
#define NTHR  256
#define PITCH 48        // tf32 xw0 fallback smem pitch (floats)

// persist smem layout (bytes)
#define WP_G0 520
#define WP_G1 1032
#define WP_K  584
#define SM_WG0 0
#define SM_WG1 33280
#define SM_WK  99328
#define SM_AST 175104
#define SM_STRIDE 18560       // 3 staging buffers (gates 17408B, KAN 18432B)
#define SMEM_TOTAL 232448
// producer smem layout (aliased)
#define PX_A  0
#define PX_W  133120
#define PX_MT 232000

// ---------------- device scratch ----------------
__device__ float g_xw0[(size_t)Tt * Bz * G4H];
__device__ __nv_bfloat16 g_wihb[(size_t)G4H * Dd];
__device__ float g_bg0[G4H];
__device__ float g_bg1[G4H];
__device__ __nv_bfloat16 g_hcat[Bz * 1024];
__device__ float g_sig[2][Bz * G4H];
__device__ __nv_bfloat16 g_feat[2][(size_t)Bz * FEAT];
__device__ float g_part[2][8][Bz * Hh];
__device__ float g_kt[12];
__device__ float g_invd[30];
__device__ unsigned g_bar;
__device__ unsigned g_gcnt[16];
__device__ unsigned g_pcnt[8];
__device__ unsigned g_xwflag[Tt];
__device__ unsigned g_mtnext;

// ---------------- grid barrier (128 persist blocks only) ----------------
__device__ __forceinline__ void gsync(unsigned target) {
    __syncthreads();
    if (threadIdx.x == 0) {
        asm volatile("red.release.gpu.global.add.u32 [%0], 1;" :: "l"(&g_bar) : "memory");
        unsigned v;
        do {
            asm volatile("ld.acquire.gpu.global.u32 %0, [%1];" : "=r"(v) : "l"(&g_bar) : "memory");
        } while (v < target);
    }
    __syncthreads();
}

// ---------------- bf16 mma primitives ----------------
__device__ __forceinline__ void ldm_x4(unsigned &r0, unsigned &r1, unsigned &r2, unsigned &r3, unsigned addr) {
    asm volatile("ldmatrix.sync.aligned.m8n8.x4.shared.b16 {%0,%1,%2,%3}, [%4];"
                 : "=r"(r0), "=r"(r1), "=r"(r2), "=r"(r3) : "r"(addr));
}
__device__ __forceinline__ void mma16816(float c[4], unsigned a0, unsigned a1, unsigned a2, unsigned a3,
                                         unsigned b0, unsigned b1) {
    asm volatile("mma.sync.aligned.m16n8k16.row.col.f32.bf16.bf16.f32 "
                 "{%0,%1,%2,%3},{%4,%5,%6,%7},{%8,%9},{%0,%1,%2,%3};"
                 : "+f"(c[0]), "+f"(c[1]), "+f"(c[2]), "+f"(c[3])
                 : "r"(a0), "r"(a1), "r"(a2), "r"(a3), "r"(b0), "r"(b1));
}

// ---------------- merged gates mma: R11 config (4m x 2n), KCH=128, race-fixed tail ----
__device__ __forceinline__ void mma_gates(
    const __nv_bfloat16* __restrict__ Ag, int arow0,
    const __nv_bfloat16* sWg0, const __nv_bfloat16* sWg1,
    __nv_bfloat16* sA, float (&acc0)[2][4], float (&acc1)[2][4])
{
    constexpr int KCH = 128, AP = 136, NCH = 8;
    int tid = threadIdx.x, lane = tid & 31, warp = tid >> 5;
    int wm = (warp & 3) * 16, wn = (warp >> 2) * 16;
    unsigned sW0a = (unsigned)__cvta_generic_to_shared(sWg0);
    unsigned sW1a = (unsigned)__cvta_generic_to_shared(sWg1);
    unsigned sAa  = (unsigned)__cvta_generic_to_shared(sA);

    auto issue = [&](int cc) {
        const __nv_bfloat16* gb = Ag + (size_t)arow0 * 1024 + cc * KCH;
        unsigned sb = sAa + (unsigned)(cc % 3) * SM_STRIDE;
#pragma unroll
        for (int o = 0; o < 4; o++) {
            int idx = o * NTHR + tid;
            int r = idx >> 4, c = (idx & 15) * 8;
            unsigned sa = sb + (unsigned)(r * AP + c) * 2u;
            const void* ga = gb + (size_t)r * 1024 + c;
            asm volatile("cp.async.cg.shared.global [%0], [%1], 16;" :: "r"(sa), "l"(ga) : "memory");
        }
        asm volatile("cp.async.commit_group;" ::: "memory");
    };
    issue(0); issue(1);

    int a_r = (lane & 7) + ((lane >> 3) & 1) * 8;
    int a_k = ((lane >> 4) & 1) * 8;
    int b_r = (lane & 7) + ((lane >> 4) & 1) * 8;
    int b_k = ((lane >> 3) & 1) * 8;
    unsigned b0base = sW0a + (unsigned)((wn + b_r) * WP_G0 + b_k) * 2u;
    unsigned b1base = sW1a + (unsigned)((wn + b_r) * WP_G1 + b_k) * 2u;

    for (int cc = 0; cc < NCH; cc++) {
        asm volatile("cp.async.wait_group 1;" ::: "memory");
        __syncthreads();
        if (cc + 2 < NCH) issue(cc + 2);
        else asm volatile("cp.async.commit_group;" ::: "memory");   // retire real groups
        unsigned ab = sAa + (unsigned)(cc % 3) * SM_STRIDE + (unsigned)((wm + a_r) * AP + a_k) * 2u;
#pragma unroll
        for (int ks = 0; ks < 8; ks++) {
            unsigned a0r, a1r, a2r, a3r;
            ldm_x4(a0r, a1r, a2r, a3r, ab + ks * 32);
            unsigned b0, b1, b2, b3;
            ldm_x4(b0, b1, b2, b3, b1base + (unsigned)(cc * KCH + ks * 16) * 2u);
            mma16816(acc1[0], a0r, a1r, a2r, a3r, b0, b1);
            mma16816(acc1[1], a0r, a1r, a2r, a3r, b2, b3);
            if (cc < 4) {
                unsigned c0, c1, c2, c3;
                ldm_x4(c0, c1, c2, c3, b0base + (unsigned)(cc * KCH + ks * 16) * 2u);
                mma16816(acc0[0], a0r, a1r, a2r, a3r, c0, c1);
                mma16816(acc0[1], a0r, a1r, a2r, a3r, c2, c3);
            }
        }
    }
}

// ---------------- KAN mma: R11 config (4m x 2n, MI=2 NW=2), KCH=64, race-fixed tail ----
template<int MI, int NW, int KCH>
__device__ __forceinline__ void mma_phase(
    const __nv_bfloat16* __restrict__ Ag, int lda, int arow0, int kbeg, int nch,
    const __nv_bfloat16* sW, int wp, __nv_bfloat16* sA, float cacc[MI][NW * 2][4])
{
    constexpr int AP  = KCH + 8;
    constexpr int OPR = KCH / 8;
    constexpr int NOPS = (MI * 64) * KCH / 8 / NTHR;
    int tid = threadIdx.x, lane = tid & 31, warp = tid >> 5;
    int wm = (warp & 3) * (MI * 16), wn = (warp >> 2) * (NW * 16);
    unsigned sWa = (unsigned)__cvta_generic_to_shared(sW);
    unsigned sAa = (unsigned)__cvta_generic_to_shared(sA);

    auto issue = [&](int cc) {
        const __nv_bfloat16* gb = Ag + (size_t)arow0 * lda + kbeg + cc * KCH;
        unsigned sb = sAa + (unsigned)(cc % 3) * SM_STRIDE;
#pragma unroll
        for (int o = 0; o < NOPS; o++) {
            int idx = o * NTHR + tid;
            int r = idx / OPR, c = (idx % OPR) * 8;
            unsigned sa = sb + (unsigned)(r * AP + c) * 2u;
            const void* ga = gb + (size_t)r * lda + c;
            asm volatile("cp.async.cg.shared.global [%0], [%1], 16;" :: "r"(sa), "l"(ga) : "memory");
        }
        asm volatile("cp.async.commit_group;" ::: "memory");
    };
    issue(0);
    if (nch > 1) issue(1);

    int a_r = (lane & 7) + ((lane >> 3) & 1) * 8;
    int a_k = ((lane >> 4) & 1) * 8;
    int b_r = (lane & 7) + ((lane >> 4) & 1) * 8;
    int b_k = ((lane >> 3) & 1) * 8;
    unsigned bbase[NW];
#pragma unroll
    for (int nw = 0; nw < NW; nw++)
        bbase[nw] = sWa + (unsigned)((wn + nw * 16 + b_r) * wp + b_k) * 2u;

    for (int cc = 0; cc < nch; cc++) {
        asm volatile("cp.async.wait_group 1;" ::: "memory");
        __syncthreads();
        if (cc + 2 < nch) issue(cc + 2);
        else asm volatile("cp.async.commit_group;" ::: "memory");

        unsigned sb = sAa + (unsigned)(cc % 3) * SM_STRIDE;
        unsigned ab[MI];
#pragma unroll
        for (int mi = 0; mi < MI; mi++)
            ab[mi] = sb + (unsigned)((wm + mi * 16 + a_r) * AP + a_k) * 2u;
#pragma unroll
        for (int ks = 0; ks < KCH / 16; ks++) {
            unsigned a0[MI], a1[MI], a2[MI], a3[MI];
#pragma unroll
            for (int mi = 0; mi < MI; mi++)
                ldm_x4(a0[mi], a1[mi], a2[mi], a3[mi], ab[mi] + ks * 32);
#pragma unroll
            for (int nw = 0; nw < NW; nw++) {
                unsigned b0, b1, b2, b3;
                ldm_x4(b0, b1, b2, b3, bbase[nw] + (unsigned)(cc * KCH + ks * 16) * 2u);
#pragma unroll
                for (int mi = 0; mi < MI; mi++) {
                    mma16816(cacc[mi][nw * 2 + 0], a0[mi], a1[mi], a2[mi], a3[mi], b0, b1);
                    mma16816(cacc[mi][nw * 2 + 1], a0[mi], a1[mi], a2[mi], a3[mi], b2, b3);
                }
            }
        }
    }
}

// ---------------- init ----------------
__global__ void init_kernel(const float* __restrict__ wih,
                            const float* __restrict__ bih, const float* __restrict__ bhh,
                            const float* __restrict__ grid, int preset_flags)
{
    size_t stride = (size_t)gridDim.x * blockDim.x;
    size_t t0 = (size_t)blockIdx.x * blockDim.x + threadIdx.x;
    for (size_t i = t0; i < (size_t)G4H * Dd; i += stride)
        g_wihb[i] = __float2bfloat16(wih[i]);
    for (size_t i = t0; i < G4H; i += stride) {
        g_bg0[i] = bih[i] + bhh[i];
        g_bg1[i] = bih[G4H + i] + bhh[G4H + i];
    }
    for (size_t i = t0; i < (size_t)Bz * 1024; i += stride) g_hcat[i] = __float2bfloat16(0.f);
    for (size_t i = t0; i < 12; i += stride) g_kt[i] = grid[i];
    for (size_t i = t0; i < 30; i += stride) {
        int j = (int)i; int k, jj;
        if (j < 11)      { k = 1; jj = j; }
        else if (j < 21) { k = 2; jj = j - 11; }
        else             { k = 3; jj = j - 21; }
        g_invd[i] = 1.0f / (grid[jj + k] - grid[jj]);
    }
    for (size_t i = t0; i < Tt; i += stride) g_xwflag[i] = (unsigned)preset_flags;
    if (t0 < 16) g_gcnt[t0] = 0u;
    if (t0 < 8) g_pcnt[t0] = 0u;
    if (t0 == 0) { g_bar = 0u; g_mtnext = 0u; }
}

// ---------------- tf32 xw0 fallback (used only if few SMs) ----------------
__device__ __forceinline__ unsigned f2tf(float x) {
    unsigned u; asm("cvt.rna.tf32.f32 %0, %1;" : "=r"(u) : "f"(x)); return u;
}
__device__ __forceinline__ void mma8(float c[4], unsigned a0, unsigned a1, unsigned a2, unsigned a3,
                                     unsigned b0, unsigned b1) {
    asm volatile("mma.sync.aligned.m16n8k8.row.col.f32.tf32.tf32.f32 "
                 "{%0,%1,%2,%3},{%4,%5,%6,%7},{%8,%9},{%0,%1,%2,%3};"
                 : "+f"(c[0]), "+f"(c[1]), "+f"(c[2]), "+f"(c[3])
                 : "r"(a0), "r"(a1), "r"(a2), "r"(a3), "r"(b0), "r"(b1));
}
__global__ void __launch_bounds__(NTHR) xw0_mma(const float* __restrict__ x,
                                                const float* __restrict__ wih,
                                                const float* __restrict__ bih,
                                                const float* __restrict__ bhh)
{
    __shared__ __align__(16) float sA[128 * PITCH];
    __shared__ __align__(16) float sB[64 * PITCH];
    int nt = blockIdx.x, mt = blockIdx.y;
    int tid = threadIdx.x, lane = tid & 31, warp = tid >> 5;
    int wm = (warp & 3) * 32, wn = (warp >> 2) * 32;
    int qr = lane >> 2, qc = lane & 3;
    float cacc[2][4][4] = {};
    const float* A = x + (size_t)mt * Dd;
    const float* W = wih + (size_t)nt * 64 * Dd;
    float4 ra[4], rb[2];
    {
#pragma unroll
        for (int j = 0; j < 4; j++) { int idx = j * 256 + tid;
            ra[j] = *(const float4*)(A + (size_t)(idx >> 3) * ((size_t)Tt * Dd) + ((idx & 7) << 2)); }
#pragma unroll
        for (int j = 0; j < 2; j++) { int idx = j * 256 + tid;
            rb[j] = *(const float4*)(W + (size_t)(idx >> 3) * Dd + ((idx & 7) << 2)); }
    }
    for (int cc = 0; cc < Dd / 32; cc++) {
        __syncthreads();
#pragma unroll
        for (int j = 0; j < 4; j++) {
            int idx = j * 256 + tid; int row = idx >> 3; int c0 = (idx & 7) << 2;
            int base = row * PITCH + ((c0 >> 4) << 4) + ((c0 & 15) >> 2);
            sA[base + 0]  = __uint_as_float(f2tf(ra[j].x));
            sA[base + 4]  = __uint_as_float(f2tf(ra[j].y));
            sA[base + 8]  = __uint_as_float(f2tf(ra[j].z));
            sA[base + 12] = __uint_as_float(f2tf(ra[j].w));
        }
#pragma unroll
        for (int j = 0; j < 2; j++) {
            int idx = j * 256 + tid; int row = idx >> 3; int c0 = (idx & 7) << 2;
            int base = row * PITCH + ((c0 >> 4) << 4) + ((c0 & 15) >> 2);
            sB[base + 0]  = __uint_as_float(f2tf(rb[j].x));
            sB[base + 4]  = __uint_as_float(f2tf(rb[j].y));
            sB[base + 8]  = __uint_as_float(f2tf(rb[j].z));
            sB[base + 12] = __uint_as_float(f2tf(rb[j].w));
        }
        __syncthreads();
        if (cc + 1 < Dd / 32) {
            int kb = (cc + 1) * 32;
#pragma unroll
            for (int j = 0; j < 4; j++) { int idx = j * 256 + tid;
                ra[j] = *(const float4*)(A + (size_t)(idx >> 3) * ((size_t)Tt * Dd) + kb + ((idx & 7) << 2)); }
#pragma unroll
            for (int j = 0; j < 2; j++) { int idx = j * 256 + tid;
                rb[j] = *(const float4*)(W + (size_t)(idx >> 3) * Dd + kb + ((idx & 7) << 2)); }
        }
#pragma unroll
        for (int h = 0; h < 2; h++) {
            unsigned bf[4][4];
#pragma unroll
            for (int f = 0; f < 4; f++) {
                float4 v = *(const float4*)(sB + (wn + f * 8 + qr) * PITCH + h * 16 + qc * 4);
                bf[f][0] = __float_as_uint(v.x); bf[f][1] = __float_as_uint(v.y);
                bf[f][2] = __float_as_uint(v.z); bf[f][3] = __float_as_uint(v.w);
            }
#pragma unroll
            for (int mi = 0; mi < 2; mi++) {
                float4 lo = *(const float4*)(sA + (wm + mi * 16 + qr) * PITCH + h * 16 + qc * 4);
                float4 hi = *(const float4*)(sA + (wm + mi * 16 + 8 + qr) * PITCH + h * 16 + qc * 4);
#pragma unroll
                for (int f = 0; f < 4; f++) {
                    mma8(cacc[mi][f], __float_as_uint(lo.x), __float_as_uint(hi.x),
                         __float_as_uint(lo.y), __float_as_uint(hi.y), bf[f][0], bf[f][1]);
                    mma8(cacc[mi][f], __float_as_uint(lo.z), __float_as_uint(hi.z),
                         __float_as_uint(lo.w), __float_as_uint(hi.w), bf[f][2], bf[f][3]);
                }
            }
        }
    }
    size_t rowbase = (size_t)mt * 128;
#pragma unroll
    for (int mi = 0; mi < 2; mi++)
#pragma unroll
        for (int f = 0; f < 4; f++) {
            int r0 = wm + mi * 16 + qr;
            int cb = nt * 64 + wn + f * 8 + qc * 2;
            float b0 = __ldg(&bih[cb]) + __ldg(&bhh[cb]);
            float b1 = __ldg(&bih[cb + 1]) + __ldg(&bhh[cb + 1]);
            *(float2*)(g_xw0 + (rowbase + r0) * G4H + cb) =
                make_float2(cacc[mi][f][0] + b0, cacc[mi][f][1] + b1);
            *(float2*)(g_xw0 + (rowbase + r0 + 8) * G4H + cb) =
                make_float2(cacc[mi][f][2] + b0, cacc[mi][f][3] + b1);
        }
}

// ---------------- mega kernel: 128 persist blocks + producer blocks ----------------
__global__ void __launch_bounds__(NTHR, 1) persist_kernel(
    const float* __restrict__ x,
    const float* __restrict__ wih, const float* __restrict__ whh,
    const float* __restrict__ kbase, const float* __restrict__ kspl,
    const float* __restrict__ kscl, const float* __restrict__ fc_w,
    const float* __restrict__ fc_b, float* __restrict__ out)
{
    extern __shared__ __align__(16) char smem_raw[];
    int bid = blockIdx.x, tid = threadIdx.x;
    int lane = tid & 31, warp = tid >> 5;
    int qr = lane >> 2, qc = lane & 3;

    // =================== xw0 producer blocks (bid >= 128) ===================
    if (bid >= NBLK) {
        __nv_bfloat16* sA = (__nv_bfloat16*)(smem_raw + PX_A);
        unsigned sAa = (unsigned)__cvta_generic_to_shared(smem_raw + PX_A);
        unsigned sWa = (unsigned)__cvta_generic_to_shared(smem_raw + PX_W);
        unsigned* s_mt = (unsigned*)(smem_raw + PX_MT);
        int a_r = (lane & 7) + ((lane >> 3) & 1) * 8;
        int a_k = ((lane >> 4) & 1) * 8;
        int b_r = (lane & 7) + ((lane >> 4) & 1) * 8;
        int b_k = ((lane >> 3) & 1) * 8;
        int wm = (warp & 3) * 32, wn = (warp >> 2) * 16;

        auto stageW = [&](int sub, int buf) {
            const __nv_bfloat16* gb = g_wihb + (size_t)sub * 32 * 512;
            unsigned dstb = sWa + (unsigned)buf * 33280u;
#pragma unroll
            for (int o = 0; o < 8; o++) {
                int idx = o * NTHR + tid;
                int r = idx >> 6, c = (idx & 63) * 8;
                asm volatile("cp.async.cg.shared.global [%0], [%1], 16;"
                             :: "r"(dstb + (unsigned)(r * 520 + c) * 2u),
                                "l"(gb + r * 512 + c) : "memory");
            }
            asm volatile("cp.async.commit_group;" ::: "memory");
        };

        for (;;) {
            __syncthreads();
            if (tid == 0) *s_mt = atomicAdd(&g_mtnext, 1u);
            __syncthreads();
            unsigned mt = *s_mt;
            if (mt >= Tt) break;
            for (int i = tid; i < 128 * 128; i += NTHR) {
                int r = i >> 7, c4 = (i & 127) << 2;
                float4 v = *(const float4*)(x + ((size_t)r * Tt + mt) * Dd + c4);
                __nv_bfloat162 p0 = __float22bfloat162_rn(make_float2(v.x, v.y));
                __nv_bfloat162 p1 = __float22bfloat162_rn(make_float2(v.z, v.w));
                *(__nv_bfloat162*)&sA[r * 520 + c4] = p0;
                *(__nv_bfloat162*)&sA[r * 520 + c4 + 2] = p1;
            }
            __syncthreads();
            stageW(0, 0);
            for (int sub = 0; sub < 64; sub++) {
                if (sub + 1 < 64) stageW(sub + 1, (sub + 1) & 1);
                else asm volatile("cp.async.commit_group;" ::: "memory");
                asm volatile("cp.async.wait_group 1;" ::: "memory");
                __syncthreads();
                unsigned bb = sWa + (unsigned)((sub & 1) * 33280) +
                              (unsigned)((wn + b_r) * 520 + b_k) * 2u;
                float cacc[2][2][4] = {};
#pragma unroll
                for (int ks = 0; ks < 32; ks++) {
                    unsigned b0, b1, b2, b3;
                    ldm_x4(b0, b1, b2, b3, bb + ks * 32);
#pragma unroll
                    for (int mi = 0; mi < 2; mi++) {
                        unsigned a0, a1, a2, a3;
                        ldm_x4(a0, a1, a2, a3,
                               sAa + (unsigned)((wm + mi * 16 + a_r) * 520 + ks * 16 + a_k) * 2u);
                        mma16816(cacc[mi][0], a0, a1, a2, a3, b0, b1);
                        mma16816(cacc[mi][1], a0, a1, a2, a3, b2, b3);
                    }
                }
                int n0 = sub * 32;
#pragma unroll
                for (int mi = 0; mi < 2; mi++)
#pragma unroll
                    for (int nf = 0; nf < 2; nf++) {
                        int row = wm + mi * 16 + qr;
                        int col = n0 + wn + nf * 8 + qc * 2;
                        float2 bv = *(const float2*)&g_bg0[col];
                        *(float2*)&g_xw0[((size_t)mt * Bz + row) * G4H + col] =
                            make_float2(cacc[mi][nf][0] + bv.x, cacc[mi][nf][1] + bv.y);
                        *(float2*)&g_xw0[((size_t)mt * Bz + row + 8) * G4H + col] =
                            make_float2(cacc[mi][nf][2] + bv.x, cacc[mi][nf][3] + bv.y);
                    }
                __syncthreads();
            }
            if (tid == 0)
                asm volatile("st.release.gpu.global.u32 [%0], %1;"
                             :: "l"(&g_xwflag[mt]), "r"(1u) : "memory");
        }
        return;
    }

    // =================== persist blocks (bid < 128) ===================
    __nv_bfloat16* sWg0 = (__nv_bfloat16*)(smem_raw + SM_WG0);
    __nv_bfloat16* sWg1 = (__nv_bfloat16*)(smem_raw + SM_WG1);
    __nv_bfloat16* sWk  = (__nv_bfloat16*)(smem_raw + SM_WK);
    __nv_bfloat16* sAst = (__nv_bfloat16*)(smem_raw + SM_AST);

    int g_nt = bid >> 1, g_mh = bid & 1;
    int lyr  = bid >> 6;
    int kb2  = bid & 63;
    int k_nt = kb2 >> 3, k_ks = kb2 & 7;

    for (int i = tid; i < 32 * 512; i += NTHR) {
        int r = i >> 9, c = i & 511;
        int ng = (r >> 3) * 512 + g_nt * 8 + (r & 7);
        sWg0[r * WP_G0 + c] = __float2bfloat16(whh[(size_t)ng * 512 + c]);
    }
    for (int i = tid; i < 32 * 1024; i += NTHR) {
        int r = i >> 10, c = i & 1023;
        int ng = (r >> 3) * 512 + g_nt * 8 + (r & 7);
        float v = (c < 512) ? wih[(size_t)G4H * Dd + (size_t)ng * 512 + c]
                            : whh[(size_t)G4H * Hh + (size_t)ng * 512 + (c - 512)];
        sWg1[r * WP_G1 + c] = __float2bfloat16(v);
    }
    for (int i = tid; i < 64 * 576; i += NTHR) {
        int r = i / 576, kk0 = i % 576;
        int row = lyr * 512 + k_nt * 64 + r;
        float v;
        if (kk0 < 64) {
            int ii2 = k_ks * 64 + kk0;
            v = kbase[(size_t)row * 512 + ii2];
        } else {
            int q = kk0 - 64;
            int ii2 = k_ks * 64 + (q >> 3);
            v = kspl[((size_t)row * 512 + ii2) * 8 + (q & 7)] * kscl[(size_t)row * 512 + ii2];
        }
        sWk[r * WP_K + kk0] = __float2bfloat16(v);
    }
    __syncthreads();

    // kt/invd in registers (R11 placement)
    float kt[12], invd[30];
#pragma unroll
    for (int q = 0; q < 12; q++) kt[q] = g_kt[q];
#pragma unroll
    for (int q = 0; q < 30; q++) invd[q] = g_invd[q];

    int wng = (warp >> 2) * 16;
    int eb0 = g_mh * 64 + (warp & 3) * 16 + qr;
    int encls[2]; bool isg[2];
#pragma unroll
    for (int nf = 0; nf < 2; nf++) {
        int cls = (wng + nf * 8) >> 3;
        encls[nf] = cls * 512 + g_nt * 8 + qc * 2;
        isg[nf] = (cls == 2);
    }
    float2 pb[2];
#pragma unroll
    for (int nf = 0; nf < 2; nf++) pb[nf] = *(const float2*)&g_bg1[encls[nf]];

    int upd_row0 = k_ks * 16 + (tid >> 5);
    int upd_col  = k_nt * 64 + ((tid & 31) << 1);
    float2 creg2[2] = {make_float2(0.f, 0.f), make_float2(0.f, 0.f)};
    int gidx = lyr * 8 + k_nt;
    int my_pcnt = g_nt >> 3;

    auto gate_epilogue = [&](int l, const float2 (&pre)[2][2], const float (&cc4)[2][4]) {
#pragma unroll
        for (int nf = 0; nf < 2; nf++)
#pragma unroll
            for (int r = 0; r < 2; r++) {
                int b = eb0 + r * 8;
                float v0 = cc4[nf][r * 2 + 0] + pre[nf][r].x;
                float v1 = cc4[nf][r * 2 + 1] + pre[nf][r].y;
                if (!isg[nf]) {
                    *(float2*)&g_sig[l][b * G4H + encls[nf]] = make_float2(
                        1.f / (1.f + __expf(-v0)), 1.f / (1.f + __expf(-v1)));
                } else {
#pragma unroll
                    for (int e = 0; e < 2; e++) {
                        float v = e ? v1 : v0;
                        int ii = encls[nf] + e - 1024;
                        int ch = ii >> 6, w = ii & 63;
                        size_t fbase = (size_t)b * FEAT + ch * 576;
                        g_feat[l][fbase + w] = __float2bfloat16(v / (1.f + __expf(-v)));
                        float bas[11];
#pragma unroll
                        for (int q = 0; q < 11; q++)
                            bas[q] = (v >= kt[q] && v < kt[q + 1]) ? 1.f : 0.f;
#pragma unroll
                        for (int k = 1; k <= 3; k++) {
                            int off = (k == 1) ? 0 : ((k == 2) ? 11 : 21);
#pragma unroll
                            for (int q = 0; q + k < 11; q++) {
                                float lf = (v - kt[q]) * invd[off + q];
                                float rf = (kt[q + k + 1] - v) * invd[off + q + 1];
                                bas[q] = lf * bas[q] + rf * bas[q + 1];
                            }
                        }
                        __nv_bfloat162 p0 = __float22bfloat162_rn(make_float2(bas[0], bas[1]));
                        __nv_bfloat162 p1 = __float22bfloat162_rn(make_float2(bas[2], bas[3]));
                        __nv_bfloat162 p2 = __float22bfloat162_rn(make_float2(bas[4], bas[5]));
                        __nv_bfloat162 p3 = __float22bfloat162_rn(make_float2(bas[6], bas[7]));
                        uint4 u;
                        u.x = *(unsigned*)&p0; u.y = *(unsigned*)&p1;
                        u.z = *(unsigned*)&p2; u.w = *(unsigned*)&p3;
                        *(uint4*)&g_feat[l][fbase + 64 + w * 8] = u;
                    }
                }
            }
    };

    unsigned gs = 0, ainst = 0;

    auto produce = [&]() {
        __syncthreads();
        if (tid == 0)
            asm volatile("red.release.gpu.global.add.u32 [%0], 1;"
                         :: "l"(&g_pcnt[my_pcnt]) : "memory");
        ainst++;
    };

    auto kan_step = [&](void) {
        if (tid == 0) {
            unsigned tgt = 16u * ainst, v;
            do {
                asm volatile("ld.acquire.gpu.global.u32 %0, [%1];"
                             : "=r"(v) : "l"(&g_pcnt[k_ks]) : "memory");
            } while (v < tgt);
            do {
                asm volatile("ld.acquire.gpu.global.u32 %0, [%1];"
                             : "=r"(v) : "l"(&g_pcnt[k_nt]) : "memory");
            } while (v < tgt);
        }
        __syncthreads();

        float cacc[2][4][4] = {};
        mma_phase<2, 2, 64>(g_feat[lyr], FEAT, 0, k_ks * 576, 9, sWk, WP_K, sAst, cacc);
        int wm = (warp & 3) * 32, wn = (warp >> 2) * 32;
#pragma unroll
        for (int mi = 0; mi < 2; mi++)
#pragma unroll
            for (int f = 0; f < 4; f++) {
                int r0 = wm + mi * 16 + qr;
                int cb = k_nt * 64 + wn + (f >> 1) * 16 + (f & 1) * 8 + qc * 2;
                *(float2*)&g_part[lyr][k_ks][r0 * Hh + cb] =
                    make_float2(cacc[mi][f][0], cacc[mi][f][1]);
                *(float2*)&g_part[lyr][k_ks][(r0 + 8) * Hh + cb] =
                    make_float2(cacc[mi][f][2], cacc[mi][f][3]);
            }

        // sigmoid operands: load here (R11 position) — latency overlaps the group-sync spin
        float2 ig[2], fg[2], og[2];
#pragma unroll
        for (int r = 0; r < 2; r++) {
            int b = upd_row0 + r * 8, o = upd_col;
            ig[r] = __ldcg((const float2*)&g_sig[lyr][b * G4H + o]);
            fg[r] = __ldcg((const float2*)&g_sig[lyr][b * G4H + 512 + o]);
            og[r] = __ldcg((const float2*)&g_sig[lyr][b * G4H + 1536 + o]);
        }

        ++gs;
        __syncthreads();
        if (tid == 0) {
            asm volatile("red.release.gpu.global.add.u32 [%0], 1;"
                         :: "l"(&g_gcnt[gidx]) : "memory");
            unsigned v, tgt = gs * 8;
            do {
                asm volatile("ld.acquire.gpu.global.u32 %0, [%1];"
                             : "=r"(v) : "l"(&g_gcnt[gidx]) : "memory");
            } while (v < tgt);
        }
        __syncthreads();

#pragma unroll
        for (int r = 0; r < 2; r++) {
            int b = upd_row0 + r * 8, o = upd_col;
            float2 v = make_float2(0.f, 0.f);
#pragma unroll
            for (int s = 0; s < 8; s++) {
                float2 p = __ldcg((const float2*)&g_part[lyr][s][b * Hh + o]);
                v.x += p.x; v.y += p.y;
            }
            float c0 = fg[r].x * creg2[r].x + ig[r].x * v.x;
            float c1 = fg[r].y * creg2[r].y + ig[r].y * v.y;
            creg2[r] = make_float2(c0, c1);
            __nv_bfloat162 h2 = __float22bfloat162_rn(
                make_float2(og[r].x * tanhf(c0), og[r].y * tanhf(c1)));
            *(unsigned*)&g_hcat[b * 1024 + lyr * 512 + o] = *(unsigned*)&h2;
        }
    };

    auto ld_pre0 = [&](int t, float2 (&pre)[2][2]) {
        unsigned fv;
        do {
            asm volatile("ld.acquire.gpu.global.u32 %0, [%1];"
                         : "=r"(fv) : "l"(&g_xwflag[t]) : "memory");
        } while (!fv);
#pragma unroll
        for (int nf = 0; nf < 2; nf++)
#pragma unroll
            for (int r = 0; r < 2; r++)
                pre[nf][r] = __ldcs((const float2*)&g_xw0[
                    ((size_t)t * Bz + eb0 + r * 8) * G4H + encls[nf]]);
    };

    unsigned nb = 0;

    // ---- prologue: L0 step 0 (h = 0 -> gates = xw0[0], no mma) ----
    {
        float2 pre[2][2];
        ld_pre0(0, pre);
        float zero4[2][4] = {};
        gate_epilogue(0, pre, zero4);
    }
    produce();
    if (lyr == 0) kan_step();
    gsync(++nb * NBLK);

    // ---- main loop ----
    for (int i = 0; i < Tt; i++) {
        bool doL0 = (i < Tt - 1);
        {
            float2 pre0[2][2];
            if (doL0) ld_pre0(i + 1, pre0);
            float a0[2][4] = {}, a1[2][4] = {};
            mma_gates(g_hcat, g_mh * 64, sWg0, sWg1, sAst, a0, a1);
            if (doL0) gate_epilogue(0, pre0, a0);
            float2 pre1[2][2];
#pragma unroll
            for (int nf = 0; nf < 2; nf++) { pre1[nf][0] = pb[nf]; pre1[nf][1] = pb[nf]; }
            gate_epilogue(1, pre1, a1);
        }
        produce();

        if (lyr == 1 || doL0) kan_step();
        gsync(++nb * NBLK);
    }

    // ---- final FC: out = h1 @ fc_w^T + fc_b ----
    {
        int idx = bid * NTHR + tid;
        int o = idx >> 7, b = idx & 127;
        float s = fc_b[o];
        const __nv_bfloat16* hp = &g_hcat[b * 1024 + 512];
        const float* wp = &fc_w[(size_t)o * Hh];
#pragma unroll 8
        for (int k = 0; k < Hh; k++) s += __bfloat162float(__ldcg(&hp[k])) * wp[k];
        out[b * Oo + o] = s;
    }
}

// ---------------- launch ----------------
extern "C" void kernel_launch(void* const* d_in, const int* in_sizes, int n_in,
                              void* d_out, int out_size)
{
    const float* x     = (const float*)d_in[0];
    const float* wih   = (const float*)d_in[1];
    const float* whh   = (const float*)d_in[2];
    const float* bih   = (const float*)d_in[3];
    const float* bhh   = (const float*)d_in[4];
    const float* kbase = (const float*)d_in[5];
    const float* kspl  = (const float*)d_in[6];
    const float* kscl  = (const float*)d_in[7];
    const float* grid  = (const float*)d_in[8];
    const float* fc_w  = (const float*)d_in[9];
    const float* fc_b  = (const float*)d_in[10];
    float* out = (float*)d_out;

    cudaFuncSetAttribute(persist_kernel, cudaFuncAttributeMaxDynamicSharedMemorySize, SMEM_TOTAL);

    int dev = 0, smCount = 0;
    cudaGetDevice(&dev);
    cudaDeviceGetAttribute(&smCount, cudaDevAttrMultiProcessorCount, dev);
    int nprod = smCount - NBLK;
    bool overlap = (nprod >= 16);
    if (!overlap) nprod = 0;

    init_kernel<<<512, NTHR>>>(wih, bih, bhh, grid, overlap ? 0 : 1);
    if (!overlap) {
        dim3 gg(G4H / 64, Tt);
        xw0_mma<<<gg, NTHR>>>(x, wih, bih, bhh);
    }
    persist_kernel<<<NBLK + nprod, NTHR, SMEM_TOTAL>>>(
        x, wih, whh, kbase, kspl, kscl, fc_w, fc_b, out);
}

// round 16
// speedup vs baseline: 1.0723x; 1.0093x over previous
#include <cuda_runtime.h>
#include <cuda_bf16.h>
#include <math.h>

// Problem constants
#define Bz    128
#define Tt    1024
#define Dd    512
#define Hh    512
#define Oo    256
#define G4H   2048
#define FEAT  4608
#define NBLK  128
#define NTHR  256
#define PITCH 48        // tf32 xw0 fallback smem pitch (floats)

// persist smem layout (bytes)
#define WP_G0 520
#define WP_G1 1032
#define WP_K  584
#define SM_WG0 0
#define SM_WG1 33280
#define SM_WK  99328
#define SM_AST 175104
#define SM_STRIDE 18560       // 3 staging buffers (gates 17408B, KAN 18432B)
#define SMEM_TOTAL 232448
// producer smem layout (aliased)
#define PX_A  0
#define PX_W  133120
#define PX_MT 232000

// ---------------- device scratch ----------------
__device__ float g_xw0[(size_t)Tt * Bz * G4H];
__device__ __nv_bfloat16 g_wihb[(size_t)G4H * Dd];
__device__ float g_bg0[G4H];
__device__ float g_bg1[G4H];
__device__ __nv_bfloat16 g_hcat[Bz * 1024];
__device__ float g_sig[2][Bz * G4H];
__device__ __nv_bfloat16 g_feat[2][(size_t)Bz * FEAT];
__device__ float g_part[2][8][Bz * Hh];
__device__ float g_kt[12];
__device__ float g_invd[30];
__device__ unsigned g_bar;
__device__ unsigned g_gcnt[16];
__device__ unsigned g_pcnt[8];
__device__ unsigned g_xwflag[Tt];
__device__ unsigned g_mtnext;

// ---------------- grid barrier (128 persist blocks only) ----------------
__device__ __forceinline__ void gsync(unsigned target) {
    __syncthreads();
    if (threadIdx.x == 0) {
        asm volatile("red.release.gpu.global.add.u32 [%0], 1;" :: "l"(&g_bar) : "memory");
        unsigned v;
        do {
            asm volatile("ld.acquire.gpu.global.u32 %0, [%1];" : "=r"(v) : "l"(&g_bar) : "memory");
        } while (v < target);
    }
    __syncthreads();
}

// ---------------- bf16 mma primitives ----------------
__device__ __forceinline__ void ldm_x4(unsigned &r0, unsigned &r1, unsigned &r2, unsigned &r3, unsigned addr) {
    asm volatile("ldmatrix.sync.aligned.m8n8.x4.shared.b16 {%0,%1,%2,%3}, [%4];"
                 : "=r"(r0), "=r"(r1), "=r"(r2), "=r"(r3) : "r"(addr));
}
__device__ __forceinline__ void mma16816(float c[4], unsigned a0, unsigned a1, unsigned a2, unsigned a3,
                                         unsigned b0, unsigned b1) {
    asm volatile("mma.sync.aligned.m16n8k16.row.col.f32.bf16.bf16.f32 "
                 "{%0,%1,%2,%3},{%4,%5,%6,%7},{%8,%9},{%0,%1,%2,%3};"
                 : "+f"(c[0]), "+f"(c[1]), "+f"(c[2]), "+f"(c[3])
                 : "r"(a0), "r"(a1), "r"(a2), "r"(a3), "r"(b0), "r"(b1));
}
// pipeline wait: ≤1 pending normally, full drain on last chunk (race-free tail)
__device__ __forceinline__ void pipe_wait(bool last) {
    if (last) asm volatile("cp.async.wait_group 0;" ::: "memory");
    else      asm volatile("cp.async.wait_group 1;" ::: "memory");
}

// ---------------- merged gates mma: 4m x 2n warps, KCH=128, wait0 tail ----------
__device__ __forceinline__ void mma_gates(
    const __nv_bfloat16* __restrict__ Ag, int arow0,
    const __nv_bfloat16* sWg0, const __nv_bfloat16* sWg1,
    __nv_bfloat16* sA, float (&acc0)[2][4], float (&acc1)[2][4])
{
    constexpr int KCH = 128, AP = 136, NCH = 8;
    int tid = threadIdx.x, lane = tid & 31, warp = tid >> 5;
    int wm = (warp & 3) * 16, wn = (warp >> 2) * 16;
    unsigned sW0a = (unsigned)__cvta_generic_to_shared(sWg0);
    unsigned sW1a = (unsigned)__cvta_generic_to_shared(sWg1);
    unsigned sAa  = (unsigned)__cvta_generic_to_shared(sA);

    auto issue = [&](int cc) {
        const __nv_bfloat16* gb = Ag + (size_t)arow0 * 1024 + cc * KCH;
        unsigned sb = sAa + (unsigned)(cc % 3) * SM_STRIDE;
#pragma unroll
        for (int o = 0; o < 4; o++) {
            int idx = o * NTHR + tid;
            int r = idx >> 4, c = (idx & 15) * 8;
            unsigned sa = sb + (unsigned)(r * AP + c) * 2u;
            const void* ga = gb + (size_t)r * 1024 + c;
            asm volatile("cp.async.cg.shared.global [%0], [%1], 16;" :: "r"(sa), "l"(ga) : "memory");
        }
        asm volatile("cp.async.commit_group;" ::: "memory");
    };
    issue(0); issue(1);

    int a_r = (lane & 7) + ((lane >> 3) & 1) * 8;
    int a_k = ((lane >> 4) & 1) * 8;
    int b_r = (lane & 7) + ((lane >> 4) & 1) * 8;
    int b_k = ((lane >> 3) & 1) * 8;
    unsigned b0base = sW0a + (unsigned)((wn + b_r) * WP_G0 + b_k) * 2u;
    unsigned b1base = sW1a + (unsigned)((wn + b_r) * WP_G1 + b_k) * 2u;

#pragma unroll
    for (int cc = 0; cc < NCH; cc++) {
        pipe_wait(cc == NCH - 1);
        __syncthreads();
        if (cc + 2 < NCH) issue(cc + 2);
        unsigned ab = sAa + (unsigned)(cc % 3) * SM_STRIDE + (unsigned)((wm + a_r) * AP + a_k) * 2u;
#pragma unroll
        for (int ks = 0; ks < 8; ks++) {
            unsigned a0r, a1r, a2r, a3r;
            ldm_x4(a0r, a1r, a2r, a3r, ab + ks * 32);
            unsigned b0, b1, b2, b3;
            ldm_x4(b0, b1, b2, b3, b1base + (unsigned)(cc * KCH + ks * 16) * 2u);
            mma16816(acc1[0], a0r, a1r, a2r, a3r, b0, b1);
            mma16816(acc1[1], a0r, a1r, a2r, a3r, b2, b3);
            if (cc < 4) {
                unsigned c0, c1, c2, c3;
                ldm_x4(c0, c1, c2, c3, b0base + (unsigned)(cc * KCH + ks * 16) * 2u);
                mma16816(acc0[0], a0r, a1r, a2r, a3r, c0, c1);
                mma16816(acc0[1], a0r, a1r, a2r, a3r, c2, c3);
            }
        }
    }
}

// ---------------- KAN mma: 4m x 2n warps (MI=2 NW=2), KCH=64, wait0 tail ----
template<int MI, int NW, int KCH>
__device__ __forceinline__ void mma_phase(
    const __nv_bfloat16* __restrict__ Ag, int lda, int arow0, int kbeg, int nch,
    const __nv_bfloat16* sW, int wp, __nv_bfloat16* sA, float cacc[MI][NW * 2][4])
{
    constexpr int AP  = KCH + 8;
    constexpr int OPR = KCH / 8;
    constexpr int NOPS = (MI * 64) * KCH / 8 / NTHR;
    int tid = threadIdx.x, lane = tid & 31, warp = tid >> 5;
    int wm = (warp & 3) * (MI * 16), wn = (warp >> 2) * (NW * 16);
    unsigned sWa = (unsigned)__cvta_generic_to_shared(sW);
    unsigned sAa = (unsigned)__cvta_generic_to_shared(sA);

    auto issue = [&](int cc) {
        const __nv_bfloat16* gb = Ag + (size_t)arow0 * lda + kbeg + cc * KCH;
        unsigned sb = sAa + (unsigned)(cc % 3) * SM_STRIDE;
#pragma unroll
        for (int o = 0; o < NOPS; o++) {
            int idx = o * NTHR + tid;
            int r = idx / OPR, c = (idx % OPR) * 8;
            unsigned sa = sb + (unsigned)(r * AP + c) * 2u;
            const void* ga = gb + (size_t)r * lda + c;
            asm volatile("cp.async.cg.shared.global [%0], [%1], 16;" :: "r"(sa), "l"(ga) : "memory");
        }
        asm volatile("cp.async.commit_group;" ::: "memory");
    };
    issue(0);
    if (nch > 1) issue(1);

    int a_r = (lane & 7) + ((lane >> 3) & 1) * 8;
    int a_k = ((lane >> 4) & 1) * 8;
    int b_r = (lane & 7) + ((lane >> 4) & 1) * 8;
    int b_k = ((lane >> 3) & 1) * 8;
    unsigned bbase[NW];
#pragma unroll
    for (int nw = 0; nw < NW; nw++)
        bbase[nw] = sWa + (unsigned)((wn + nw * 16 + b_r) * wp + b_k) * 2u;

    for (int cc = 0; cc < nch; cc++) {
        pipe_wait(cc == nch - 1);
        __syncthreads();
        if (cc + 2 < nch) issue(cc + 2);

        unsigned sb = sAa + (unsigned)(cc % 3) * SM_STRIDE;
        unsigned ab[MI];
#pragma unroll
        for (int mi = 0; mi < MI; mi++)
            ab[mi] = sb + (unsigned)((wm + mi * 16 + a_r) * AP + a_k) * 2u;
#pragma unroll
        for (int ks = 0; ks < KCH / 16; ks++) {
            unsigned a0[MI], a1[MI], a2[MI], a3[MI];
#pragma unroll
            for (int mi = 0; mi < MI; mi++)
                ldm_x4(a0[mi], a1[mi], a2[mi], a3[mi], ab[mi] + ks * 32);
#pragma unroll
            for (int nw = 0; nw < NW; nw++) {
                unsigned b0, b1, b2, b3;
                ldm_x4(b0, b1, b2, b3, bbase[nw] + (unsigned)(cc * KCH + ks * 16) * 2u);
#pragma unroll
                for (int mi = 0; mi < MI; mi++) {
                    mma16816(cacc[mi][nw * 2 + 0], a0[mi], a1[mi], a2[mi], a3[mi], b0, b1);
                    mma16816(cacc[mi][nw * 2 + 1], a0[mi], a1[mi], a2[mi], a3[mi], b2, b3);
                }
            }
        }
    }
}

// ---------------- init ----------------
__global__ void init_kernel(const float* __restrict__ wih,
                            const float* __restrict__ bih, const float* __restrict__ bhh,
                            const float* __restrict__ grid, int preset_flags)
{
    size_t stride = (size_t)gridDim.x * blockDim.x;
    size_t t0 = (size_t)blockIdx.x * blockDim.x + threadIdx.x;
    for (size_t i = t0; i < (size_t)G4H * Dd; i += stride)
        g_wihb[i] = __float2bfloat16(wih[i]);
    for (size_t i = t0; i < G4H; i += stride) {
        g_bg0[i] = bih[i] + bhh[i];
        g_bg1[i] = bih[G4H + i] + bhh[G4H + i];
    }
    for (size_t i = t0; i < (size_t)Bz * 1024; i += stride) g_hcat[i] = __float2bfloat16(0.f);
    for (size_t i = t0; i < 12; i += stride) g_kt[i] = grid[i];
    for (size_t i = t0; i < 30; i += stride) {
        int j = (int)i; int k, jj;
        if (j < 11)      { k = 1; jj = j; }
        else if (j < 21) { k = 2; jj = j - 11; }
        else             { k = 3; jj = j - 21; }
        g_invd[i] = 1.0f / (grid[jj + k] - grid[jj]);
    }
    for (size_t i = t0; i < Tt; i += stride) g_xwflag[i] = (unsigned)preset_flags;
    if (t0 < 16) g_gcnt[t0] = 0u;
    if (t0 < 8) g_pcnt[t0] = 0u;
    if (t0 == 0) { g_bar = 0u; g_mtnext = 0u; }
}

// ---------------- tf32 xw0 fallback (used only if few SMs) ----------------
__device__ __forceinline__ unsigned f2tf(float x) {
    unsigned u; asm("cvt.rna.tf32.f32 %0, %1;" : "=r"(u) : "f"(x)); return u;
}
__device__ __forceinline__ void mma8(float c[4], unsigned a0, unsigned a1, unsigned a2, unsigned a3,
                                     unsigned b0, unsigned b1) {
    asm volatile("mma.sync.aligned.m16n8k8.row.col.f32.tf32.tf32.f32 "
                 "{%0,%1,%2,%3},{%4,%5,%6,%7},{%8,%9},{%0,%1,%2,%3};"
                 : "+f"(c[0]), "+f"(c[1]), "+f"(c[2]), "+f"(c[3])
                 : "r"(a0), "r"(a1), "r"(a2), "r"(a3), "r"(b0), "r"(b1));
}
__global__ void __launch_bounds__(NTHR) xw0_mma(const float* __restrict__ x,
                                                const float* __restrict__ wih,
                                                const float* __restrict__ bih,
                                                const float* __restrict__ bhh)
{
    __shared__ __align__(16) float sA[128 * PITCH];
    __shared__ __align__(16) float sB[64 * PITCH];
    int nt = blockIdx.x, mt = blockIdx.y;
    int tid = threadIdx.x, lane = tid & 31, warp = tid >> 5;
    int wm = (warp & 3) * 32, wn = (warp >> 2) * 32;
    int qr = lane >> 2, qc = lane & 3;
    float cacc[2][4][4] = {};
    const float* A = x + (size_t)mt * Dd;
    const float* W = wih + (size_t)nt * 64 * Dd;
    float4 ra[4], rb[2];
    {
#pragma unroll
        for (int j = 0; j < 4; j++) { int idx = j * 256 + tid;
            ra[j] = *(const float4*)(A + (size_t)(idx >> 3) * ((size_t)Tt * Dd) + ((idx & 7) << 2)); }
#pragma unroll
        for (int j = 0; j < 2; j++) { int idx = j * 256 + tid;
            rb[j] = *(const float4*)(W + (size_t)(idx >> 3) * Dd + ((idx & 7) << 2)); }
    }
    for (int cc = 0; cc < Dd / 32; cc++) {
        __syncthreads();
#pragma unroll
        for (int j = 0; j < 4; j++) {
            int idx = j * 256 + tid; int row = idx >> 3; int c0 = (idx & 7) << 2;
            int base = row * PITCH + ((c0 >> 4) << 4) + ((c0 & 15) >> 2);
            sA[base + 0]  = __uint_as_float(f2tf(ra[j].x));
            sA[base + 4]  = __uint_as_float(f2tf(ra[j].y));
            sA[base + 8]  = __uint_as_float(f2tf(ra[j].z));
            sA[base + 12] = __uint_as_float(f2tf(ra[j].w));
        }
#pragma unroll
        for (int j = 0; j < 2; j++) {
            int idx = j * 256 + tid; int row = idx >> 3; int c0 = (idx & 7) << 2;
            int base = row * PITCH + ((c0 >> 4) << 4) + ((c0 & 15) >> 2);
            sB[base + 0]  = __uint_as_float(f2tf(rb[j].x));
            sB[base + 4]  = __uint_as_float(f2tf(rb[j].y));
            sB[base + 8]  = __uint_as_float(f2tf(rb[j].z));
            sB[base + 12] = __uint_as_float(f2tf(rb[j].w));
        }
        __syncthreads();
        if (cc + 1 < Dd / 32) {
            int kb = (cc + 1) * 32;
#pragma unroll
            for (int j = 0; j < 4; j++) { int idx = j * 256 + tid;
                ra[j] = *(const float4*)(A + (size_t)(idx >> 3) * ((size_t)Tt * Dd) + kb + ((idx & 7) << 2)); }
#pragma unroll
            for (int j = 0; j < 2; j++) { int idx = j * 256 + tid;
                rb[j] = *(const float4*)(W + (size_t)(idx >> 3) * Dd + kb + ((idx & 7) << 2)); }
        }
#pragma unroll
        for (int h = 0; h < 2; h++) {
            unsigned bf[4][4];
#pragma unroll
            for (int f = 0; f < 4; f++) {
                float4 v = *(const float4*)(sB + (wn + f * 8 + qr) * PITCH + h * 16 + qc * 4);
                bf[f][0] = __float_as_uint(v.x); bf[f][1] = __float_as_uint(v.y);
                bf[f][2] = __float_as_uint(v.z); bf[f][3] = __float_as_uint(v.w);
            }
#pragma unroll
            for (int mi = 0; mi < 2; mi++) {
                float4 lo = *(const float4*)(sA + (wm + mi * 16 + qr) * PITCH + h * 16 + qc * 4);
                float4 hi = *(const float4*)(sA + (wm + mi * 16 + 8 + qr) * PITCH + h * 16 + qc * 4);
#pragma unroll
                for (int f = 0; f < 4; f++) {
                    mma8(cacc[mi][f], __float_as_uint(lo.x), __float_as_uint(hi.x),
                         __float_as_uint(lo.y), __float_as_uint(hi.y), bf[f][0], bf[f][1]);
                    mma8(cacc[mi][f], __float_as_uint(lo.z), __float_as_uint(hi.z),
                         __float_as_uint(lo.w), __float_as_uint(hi.w), bf[f][2], bf[f][3]);
                }
            }
        }
    }
    size_t rowbase = (size_t)mt * 128;
#pragma unroll
    for (int mi = 0; mi < 2; mi++)
#pragma unroll
        for (int f = 0; f < 4; f++) {
            int r0 = wm + mi * 16 + qr;
            int cb = nt * 64 + wn + f * 8 + qc * 2;
            float b0 = __ldg(&bih[cb]) + __ldg(&bhh[cb]);
            float b1 = __ldg(&bih[cb + 1]) + __ldg(&bhh[cb + 1]);
            *(float2*)(g_xw0 + (rowbase + r0) * G4H + cb) =
                make_float2(cacc[mi][f][0] + b0, cacc[mi][f][1] + b1);
            *(float2*)(g_xw0 + (rowbase + r0 + 8) * G4H + cb) =
                make_float2(cacc[mi][f][2] + b0, cacc[mi][f][3] + b1);
        }
}

// ---------------- mega kernel: 128 persist blocks + producer blocks ----------------
__global__ void __launch_bounds__(NTHR, 1) persist_kernel(
    const float* __restrict__ x,
    const float* __restrict__ wih, const float* __restrict__ whh,
    const float* __restrict__ kbase, const float* __restrict__ kspl,
    const float* __restrict__ kscl, const float* __restrict__ fc_w,
    const float* __restrict__ fc_b, float* __restrict__ out)
{
    extern __shared__ __align__(16) char smem_raw[];
    int bid = blockIdx.x, tid = threadIdx.x;
    int lane = tid & 31, warp = tid >> 5;
    int qr = lane >> 2, qc = lane & 3;

    // =================== xw0 producer blocks (bid >= 128) ===================
    if (bid >= NBLK) {
        __nv_bfloat16* sA = (__nv_bfloat16*)(smem_raw + PX_A);
        unsigned sAa = (unsigned)__cvta_generic_to_shared(smem_raw + PX_A);
        unsigned sWa = (unsigned)__cvta_generic_to_shared(smem_raw + PX_W);
        unsigned* s_mt = (unsigned*)(smem_raw + PX_MT);
        int a_r = (lane & 7) + ((lane >> 3) & 1) * 8;
        int a_k = ((lane >> 4) & 1) * 8;
        int b_r = (lane & 7) + ((lane >> 4) & 1) * 8;
        int b_k = ((lane >> 3) & 1) * 8;
        int wm = (warp & 3) * 32, wn = (warp >> 2) * 16;

        auto stageW = [&](int sub, int buf) {
            const __nv_bfloat16* gb = g_wihb + (size_t)sub * 32 * 512;
            unsigned dstb = sWa + (unsigned)buf * 33280u;
#pragma unroll
            for (int o = 0; o < 8; o++) {
                int idx = o * NTHR + tid;
                int r = idx >> 6, c = (idx & 63) * 8;
                asm volatile("cp.async.cg.shared.global [%0], [%1], 16;"
                             :: "r"(dstb + (unsigned)(r * 520 + c) * 2u),
                                "l"(gb + r * 512 + c) : "memory");
            }
            asm volatile("cp.async.commit_group;" ::: "memory");
        };

        for (;;) {
            __syncthreads();
            if (tid == 0) *s_mt = atomicAdd(&g_mtnext, 1u);
            __syncthreads();
            unsigned mt = *s_mt;
            if (mt >= Tt) break;
            for (int i = tid; i < 128 * 128; i += NTHR) {
                int r = i >> 7, c4 = (i & 127) << 2;
                float4 v = *(const float4*)(x + ((size_t)r * Tt + mt) * Dd + c4);
                __nv_bfloat162 p0 = __float22bfloat162_rn(make_float2(v.x, v.y));
                __nv_bfloat162 p1 = __float22bfloat162_rn(make_float2(v.z, v.w));
                *(__nv_bfloat162*)&sA[r * 520 + c4] = p0;
                *(__nv_bfloat162*)&sA[r * 520 + c4 + 2] = p1;
            }
            __syncthreads();
            stageW(0, 0);
            for (int sub = 0; sub < 64; sub++) {
                if (sub + 1 < 64) stageW(sub + 1, (sub + 1) & 1);
                if (sub + 1 < 64) asm volatile("cp.async.wait_group 1;" ::: "memory");
                else              asm volatile("cp.async.wait_group 0;" ::: "memory");
                __syncthreads();
                unsigned bb = sWa + (unsigned)((sub & 1) * 33280) +
                              (unsigned)((wn + b_r) * 520 + b_k) * 2u;
                float cacc[2][2][4] = {};
#pragma unroll
                for (int ks = 0; ks < 32; ks++) {
                    unsigned b0, b1, b2, b3;
                    ldm_x4(b0, b1, b2, b3, bb + ks * 32);
#pragma unroll
                    for (int mi = 0; mi < 2; mi++) {
                        unsigned a0, a1, a2, a3;
                        ldm_x4(a0, a1, a2, a3,
                               sAa + (unsigned)((wm + mi * 16 + a_r) * 520 + ks * 16 + a_k) * 2u);
                        mma16816(cacc[mi][0], a0, a1, a2, a3, b0, b1);
                        mma16816(cacc[mi][1], a0, a1, a2, a3, b2, b3);
                    }
                }
                int n0 = sub * 32;
#pragma unroll
                for (int mi = 0; mi < 2; mi++)
#pragma unroll
                    for (int nf = 0; nf < 2; nf++) {
                        int row = wm + mi * 16 + qr;
                        int col = n0 + wn + nf * 8 + qc * 2;
                        float2 bv = *(const float2*)&g_bg0[col];
                        *(float2*)&g_xw0[((size_t)mt * Bz + row) * G4H + col] =
                            make_float2(cacc[mi][nf][0] + bv.x, cacc[mi][nf][1] + bv.y);
                        *(float2*)&g_xw0[((size_t)mt * Bz + row + 8) * G4H + col] =
                            make_float2(cacc[mi][nf][2] + bv.x, cacc[mi][nf][3] + bv.y);
                    }
                __syncthreads();
            }
            if (tid == 0)
                asm volatile("st.release.gpu.global.u32 [%0], %1;"
                             :: "l"(&g_xwflag[mt]), "r"(1u) : "memory");
        }
        return;
    }

    // =================== persist blocks (bid < 128) ===================
    __nv_bfloat16* sWg0 = (__nv_bfloat16*)(smem_raw + SM_WG0);
    __nv_bfloat16* sWg1 = (__nv_bfloat16*)(smem_raw + SM_WG1);
    __nv_bfloat16* sWk  = (__nv_bfloat16*)(smem_raw + SM_WK);
    __nv_bfloat16* sAst = (__nv_bfloat16*)(smem_raw + SM_AST);

    int g_nt = bid >> 1, g_mh = bid & 1;
    int lyr  = bid >> 6;
    int kb2  = bid & 63;
    int k_nt = kb2 >> 3, k_ks = kb2 & 7;

    for (int i = tid; i < 32 * 512; i += NTHR) {
        int r = i >> 9, c = i & 511;
        int ng = (r >> 3) * 512 + g_nt * 8 + (r & 7);
        sWg0[r * WP_G0 + c] = __float2bfloat16(whh[(size_t)ng * 512 + c]);
    }
    for (int i = tid; i < 32 * 1024; i += NTHR) {
        int r = i >> 10, c = i & 1023;
        int ng = (r >> 3) * 512 + g_nt * 8 + (r & 7);
        float v = (c < 512) ? wih[(size_t)G4H * Dd + (size_t)ng * 512 + c]
                            : whh[(size_t)G4H * Hh + (size_t)ng * 512 + (c - 512)];
        sWg1[r * WP_G1 + c] = __float2bfloat16(v);
    }
    for (int i = tid; i < 64 * 576; i += NTHR) {
        int r = i / 576, kk0 = i % 576;
        int row = lyr * 512 + k_nt * 64 + r;
        float v;
        if (kk0 < 64) {
            int ii2 = k_ks * 64 + kk0;
            v = kbase[(size_t)row * 512 + ii2];
        } else {
            int q = kk0 - 64;
            int ii2 = k_ks * 64 + (q >> 3);
            v = kspl[((size_t)row * 512 + ii2) * 8 + (q & 7)] * kscl[(size_t)row * 512 + ii2];
        }
        sWk[r * WP_K + kk0] = __float2bfloat16(v);
    }
    __syncthreads();

    float kt[12], invd[30];
#pragma unroll
    for (int q = 0; q < 12; q++) kt[q] = g_kt[q];
#pragma unroll
    for (int q = 0; q < 30; q++) invd[q] = g_invd[q];

    int wng = (warp >> 2) * 16;
    int eb0 = g_mh * 64 + (warp & 3) * 16 + qr;
    int encls[2]; bool isg[2];
#pragma unroll
    for (int nf = 0; nf < 2; nf++) {
        int cls = (wng + nf * 8) >> 3;
        encls[nf] = cls * 512 + g_nt * 8 + qc * 2;
        isg[nf] = (cls == 2);
    }
    float2 pb[2];
#pragma unroll
    for (int nf = 0; nf < 2; nf++) pb[nf] = *(const float2*)&g_bg1[encls[nf]];

    int upd_row0 = k_ks * 16 + (tid >> 5);
    int upd_col  = k_nt * 64 + ((tid & 31) << 1);
    float2 creg2[2] = {make_float2(0.f, 0.f), make_float2(0.f, 0.f)};
    int gidx = lyr * 8 + k_nt;
    int my_pcnt = g_nt >> 3;

    auto gate_epilogue = [&](int l, const float2 (&pre)[2][2], const float (&cc4)[2][4]) {
#pragma unroll
        for (int nf = 0; nf < 2; nf++)
#pragma unroll
            for (int r = 0; r < 2; r++) {
                int b = eb0 + r * 8;
                float v0 = cc4[nf][r * 2 + 0] + pre[nf][r].x;
                float v1 = cc4[nf][r * 2 + 1] + pre[nf][r].y;
                if (!isg[nf]) {
                    *(float2*)&g_sig[l][b * G4H + encls[nf]] = make_float2(
                        1.f / (1.f + __expf(-v0)), 1.f / (1.f + __expf(-v1)));
                } else {
#pragma unroll
                    for (int e = 0; e < 2; e++) {
                        float v = e ? v1 : v0;
                        int ii = encls[nf] + e - 1024;
                        int ch = ii >> 6, w = ii & 63;
                        size_t fbase = (size_t)b * FEAT + ch * 576;
                        g_feat[l][fbase + w] = __float2bfloat16(v / (1.f + __expf(-v)));
                        float bas[11];
#pragma unroll
                        for (int q = 0; q < 11; q++)
                            bas[q] = (v >= kt[q] && v < kt[q + 1]) ? 1.f : 0.f;
#pragma unroll
                        for (int k = 1; k <= 3; k++) {
                            int off = (k == 1) ? 0 : ((k == 2) ? 11 : 21);
#pragma unroll
                            for (int q = 0; q + k < 11; q++) {
                                float lf = (v - kt[q]) * invd[off + q];
                                float rf = (kt[q + k + 1] - v) * invd[off + q + 1];
                                bas[q] = lf * bas[q] + rf * bas[q + 1];
                            }
                        }
                        __nv_bfloat162 p0 = __float22bfloat162_rn(make_float2(bas[0], bas[1]));
                        __nv_bfloat162 p1 = __float22bfloat162_rn(make_float2(bas[2], bas[3]));
                        __nv_bfloat162 p2 = __float22bfloat162_rn(make_float2(bas[4], bas[5]));
                        __nv_bfloat162 p3 = __float22bfloat162_rn(make_float2(bas[6], bas[7]));
                        uint4 u;
                        u.x = *(unsigned*)&p0; u.y = *(unsigned*)&p1;
                        u.z = *(unsigned*)&p2; u.w = *(unsigned*)&p3;
                        *(uint4*)&g_feat[l][fbase + 64 + w * 8] = u;
                    }
                }
            }
    };

    unsigned gs = 0, ainst = 0;

    auto produce = [&]() {
        __syncthreads();
        if (tid == 0)
            asm volatile("red.release.gpu.global.add.u32 [%0], 1;"
                         :: "l"(&g_pcnt[my_pcnt]) : "memory");
        ainst++;
    };

    auto kan_step = [&](void) {
        if (tid == 0) {
            unsigned tgt = 16u * ainst, v;
            do {
                asm volatile("ld.acquire.gpu.global.u32 %0, [%1];"
                             : "=r"(v) : "l"(&g_pcnt[k_ks]) : "memory");
            } while (v < tgt);
            do {
                asm volatile("ld.acquire.gpu.global.u32 %0, [%1];"
                             : "=r"(v) : "l"(&g_pcnt[k_nt]) : "memory");
            } while (v < tgt);
        }
        __syncthreads();

        float cacc[2][4][4] = {};
        mma_phase<2, 2, 64>(g_feat[lyr], FEAT, 0, k_ks * 576, 9, sWk, WP_K, sAst, cacc);
        int wm = (warp & 3) * 32, wn = (warp >> 2) * 32;
#pragma unroll
        for (int mi = 0; mi < 2; mi++)
#pragma unroll
            for (int f = 0; f < 4; f++) {
                int r0 = wm + mi * 16 + qr;
                int cb = k_nt * 64 + wn + (f >> 1) * 16 + (f & 1) * 8 + qc * 2;
                *(float2*)&g_part[lyr][k_ks][r0 * Hh + cb] =
                    make_float2(cacc[mi][f][0], cacc[mi][f][1]);
                *(float2*)&g_part[lyr][k_ks][(r0 + 8) * Hh + cb] =
                    make_float2(cacc[mi][f][2], cacc[mi][f][3]);
            }

        // sigmoid operands: latency overlaps the group-sync spin
        float2 ig[2], fg[2], og[2];
#pragma unroll
        for (int r = 0; r < 2; r++) {
            int b = upd_row0 + r * 8, o = upd_col;
            ig[r] = __ldcg((const float2*)&g_sig[lyr][b * G4H + o]);
            fg[r] = __ldcg((const float2*)&g_sig[lyr][b * G4H + 512 + o]);
            og[r] = __ldcg((const float2*)&g_sig[lyr][b * G4H + 1536 + o]);
        }

        ++gs;
        __syncthreads();
        if (tid == 0) {
            asm volatile("red.release.gpu.global.add.u32 [%0], 1;"
                         :: "l"(&g_gcnt[gidx]) : "memory");
            unsigned v, tgt = gs * 8;
            do {
                asm volatile("ld.acquire.gpu.global.u32 %0, [%1];"
                             : "=r"(v) : "l"(&g_gcnt[gidx]) : "memory");
            } while (v < tgt);
        }
        __syncthreads();

#pragma unroll
        for (int r = 0; r < 2; r++) {
            int b = upd_row0 + r * 8, o = upd_col;
            float2 v = make_float2(0.f, 0.f);
#pragma unroll
            for (int s = 0; s < 8; s++) {
                float2 p = __ldcg((const float2*)&g_part[lyr][s][b * Hh + o]);
                v.x += p.x; v.y += p.y;
            }
            float c0 = fg[r].x * creg2[r].x + ig[r].x * v.x;
            float c1 = fg[r].y * creg2[r].y + ig[r].y * v.y;
            creg2[r] = make_float2(c0, c1);
            __nv_bfloat162 h2 = __float22bfloat162_rn(
                make_float2(og[r].x * tanhf(c0), og[r].y * tanhf(c1)));
            *(unsigned*)&g_hcat[b * 1024 + lyr * 512 + o] = *(unsigned*)&h2;
        }
    };

    auto ld_pre0 = [&](int t, float2 (&pre)[2][2]) {
        unsigned fv;
        do {
            asm volatile("ld.acquire.gpu.global.u32 %0, [%1];"
                         : "=r"(fv) : "l"(&g_xwflag[t]) : "memory");
        } while (!fv);
#pragma unroll
        for (int nf = 0; nf < 2; nf++)
#pragma unroll
            for (int r = 0; r < 2; r++)
                pre[nf][r] = __ldcs((const float2*)&g_xw0[
                    ((size_t)t * Bz + eb0 + r * 8) * G4H + encls[nf]]);
    };

    unsigned nb = 0;

    // ---- prologue: L0 step 0 (h = 0 -> gates = xw0[0], no mma) ----
    {
        float2 pre[2][2];
        ld_pre0(0, pre);
        float zero4[2][4] = {};
        gate_epilogue(0, pre, zero4);
    }
    produce();
    if (lyr == 0) kan_step();
    gsync(++nb * NBLK);

    // ---- main loop ----
    for (int i = 0; i < Tt; i++) {
        bool doL0 = (i < Tt - 1);
        {
            float2 pre0[2][2];
            if (doL0) ld_pre0(i + 1, pre0);
            float a0[2][4] = {}, a1[2][4] = {};
            mma_gates(g_hcat, g_mh * 64, sWg0, sWg1, sAst, a0, a1);
            if (doL0) gate_epilogue(0, pre0, a0);
            float2 pre1[2][2];
#pragma unroll
            for (int nf = 0; nf < 2; nf++) { pre1[nf][0] = pb[nf]; pre1[nf][1] = pb[nf]; }
            gate_epilogue(1, pre1, a1);
        }
        produce();

        if (lyr == 1 || doL0) kan_step();
        gsync(++nb * NBLK);
    }

    // ---- final FC: out = h1 @ fc_w^T + fc_b ----
    {
        int idx = bid * NTHR + tid;
        int o = idx >> 7, b = idx & 127;
        float s = fc_b[o];
        const __nv_bfloat16* hp = &g_hcat[b * 1024 + 512];
        const float* wp = &fc_w[(size_t)o * Hh];
#pragma unroll 8
        for (int k = 0; k < Hh; k++) s += __bfloat162float(__ldcg(&hp[k])) * wp[k];
        out[b * Oo + o] = s;
    }
}

// ---------------- launch ----------------
extern "C" void kernel_launch(void* const* d_in, const int* in_sizes, int n_in,
                              void* d_out, int out_size)
{
    const float* x     = (const float*)d_in[0];
    const float* wih   = (const float*)d_in[1];
    const float* whh   = (const float*)d_in[2];
    const float* bih   = (const float*)d_in[3];
    const float* bhh   = (const float*)d_in[4];
    const float* kbase = (const float*)d_in[5];
    const float* kspl  = (const float*)d_in[6];
    const float* kscl  = (const float*)d_in[7];
    const float* grid  = (const float*)d_in[8];
    const float* fc_w  = (const float*)d_in[9];
    const float* fc_b  = (const float*)d_in[10];
    float* out = (float*)d_out;

    cudaFuncSetAttribute(persist_kernel, cudaFuncAttributeMaxDynamicSharedMemorySize, SMEM_TOTAL);

    int dev = 0, smCount = 0;
    cudaGetDevice(&dev);
    cudaDeviceGetAttribute(&smCount, cudaDevAttrMultiProcessorCount, dev);
    int nprod = smCount - NBLK;
    bool overlap = (nprod >= 16);
    if (!overlap) nprod = 0;

    init_kernel<<<512, NTHR>>>(wih, bih, bhh, grid, overlap ? 0 : 1);
    if (!overlap) {
        dim3 gg(G4H / 64, Tt);
        xw0_mma<<<gg, NTHR>>>(x, wih, bih, bhh);
    }
    persist_kernel<<<NBLK + nprod, NTHR, SMEM_TOTAL>>>(
        x, wih, whh, kbase, kspl, kscl, fc_w, fc_b, out);
}

// round 17
// speedup vs baseline: 1.0742x; 1.0017x over previous
#include <cuda_runtime.h>
#include <cuda_bf16.h>
#include <math.h>

// Problem constants
#define Bz    128
#define Tt    1024
#define Dd    512
#define Hh    512
#define Oo    256
#define G4H   2048
#define FEAT  4608
#define NBLK  128
#define NTHR  256
#define PITCH 48        // tf32 xw0 fallback smem pitch (floats)

// persist smem layout (bytes)
#define WP_G0 520
#define WP_G1 1032
#define WP_K  584
#define SM_WG0 0
#define SM_WG1 33280
#define SM_WK  99328
#define SM_AST 175104
#define SM_STRIDE 18560       // 3 staging buffers (gates 17408B, KAN 18432B)
#define SMEM_TOTAL 232448
// producer smem layout (aliased)
#define PX_A  0
#define PX_W  133120
#define PX_MT 232000

// ---------------- device scratch ----------------
__device__ float g_xw0[(size_t)Tt * Bz * G4H];
__device__ __nv_bfloat16 g_wihb[(size_t)G4H * Dd];
__device__ float g_bg0[G4H];
__device__ float g_bg1[G4H];
__device__ __nv_bfloat16 g_hcat[Bz * 1024];
__device__ float g_sig[2][Bz * G4H];
__device__ __nv_bfloat16 g_feat[2][(size_t)Bz * FEAT];
__device__ float g_part[2][8][Bz * Hh];
__device__ float g_kt[12];
__device__ float g_invd[30];
__device__ unsigned g_bar;
__device__ unsigned g_gcnt[16];
__device__ unsigned g_pcnt[8];
__device__ unsigned g_xwflag[Tt];
__device__ unsigned g_mtnext;

// ---------------- grid barrier (128 persist blocks only) ----------------
__device__ __forceinline__ void gsync(unsigned target) {
    __syncthreads();
    if (threadIdx.x == 0) {
        asm volatile("red.release.gpu.global.add.u32 [%0], 1;" :: "l"(&g_bar) : "memory");
        unsigned v;
        do {
            asm volatile("ld.acquire.gpu.global.u32 %0, [%1];" : "=r"(v) : "l"(&g_bar) : "memory");
        } while (v < target);
    }
    __syncthreads();
}

// ---------------- bf16 mma primitives ----------------
__device__ __forceinline__ void ldm_x4(unsigned &r0, unsigned &r1, unsigned &r2, unsigned &r3, unsigned addr) {
    asm volatile("ldmatrix.sync.aligned.m8n8.x4.shared.b16 {%0,%1,%2,%3}, [%4];"
                 : "=r"(r0), "=r"(r1), "=r"(r2), "=r"(r3) : "r"(addr));
}
__device__ __forceinline__ void mma16816(float c[4], unsigned a0, unsigned a1, unsigned a2, unsigned a3,
                                         unsigned b0, unsigned b1) {
    asm volatile("mma.sync.aligned.m16n8k16.row.col.f32.bf16.bf16.f32 "
                 "{%0,%1,%2,%3},{%4,%5,%6,%7},{%8,%9},{%0,%1,%2,%3};"
                 : "+f"(c[0]), "+f"(c[1]), "+f"(c[2]), "+f"(c[3])
                 : "r"(a0), "r"(a1), "r"(a2), "r"(a3), "r"(b0), "r"(b1));
}
// pipeline wait: ≤1 pending normally, full drain on last chunk (race-free tail)
__device__ __forceinline__ void pipe_wait(bool last) {
    if (last) asm volatile("cp.async.wait_group 0;" ::: "memory");
    else      asm volatile("cp.async.wait_group 1;" ::: "memory");
}

// ---------------- merged gates mma: 4m x 2n warps, KCH=128, wait0 tail ----------
__device__ __forceinline__ void mma_gates(
    const __nv_bfloat16* __restrict__ Ag, int arow0,
    const __nv_bfloat16* sWg0, const __nv_bfloat16* sWg1,
    __nv_bfloat16* sA, float (&acc0)[2][4], float (&acc1)[2][4])
{
    constexpr int KCH = 128, AP = 136, NCH = 8;
    int tid = threadIdx.x, lane = tid & 31, warp = tid >> 5;
    int wm = (warp & 3) * 16, wn = (warp >> 2) * 16;
    unsigned sW0a = (unsigned)__cvta_generic_to_shared(sWg0);
    unsigned sW1a = (unsigned)__cvta_generic_to_shared(sWg1);
    unsigned sAa  = (unsigned)__cvta_generic_to_shared(sA);

    auto issue = [&](int cc) {
        const __nv_bfloat16* gb = Ag + (size_t)arow0 * 1024 + cc * KCH;
        unsigned sb = sAa + (unsigned)(cc % 3) * SM_STRIDE;
#pragma unroll
        for (int o = 0; o < 4; o++) {
            int idx = o * NTHR + tid;
            int r = idx >> 4, c = (idx & 15) * 8;
            unsigned sa = sb + (unsigned)(r * AP + c) * 2u;
            const void* ga = gb + (size_t)r * 1024 + c;
            asm volatile("cp.async.cg.shared.global [%0], [%1], 16;" :: "r"(sa), "l"(ga) : "memory");
        }
        asm volatile("cp.async.commit_group;" ::: "memory");
    };
    issue(0); issue(1);

    int a_r = (lane & 7) + ((lane >> 3) & 1) * 8;
    int a_k = ((lane >> 4) & 1) * 8;
    int b_r = (lane & 7) + ((lane >> 4) & 1) * 8;
    int b_k = ((lane >> 3) & 1) * 8;
    unsigned b0base = sW0a + (unsigned)((wn + b_r) * WP_G0 + b_k) * 2u;
    unsigned b1base = sW1a + (unsigned)((wn + b_r) * WP_G1 + b_k) * 2u;

#pragma unroll
    for (int cc = 0; cc < NCH; cc++) {
        pipe_wait(cc == NCH - 1);
        __syncthreads();
        if (cc + 2 < NCH) issue(cc + 2);
        unsigned ab = sAa + (unsigned)(cc % 3) * SM_STRIDE + (unsigned)((wm + a_r) * AP + a_k) * 2u;
#pragma unroll
        for (int ks = 0; ks < 8; ks++) {
            unsigned a0r, a1r, a2r, a3r;
            ldm_x4(a0r, a1r, a2r, a3r, ab + ks * 32);
            unsigned b0, b1, b2, b3;
            ldm_x4(b0, b1, b2, b3, b1base + (unsigned)(cc * KCH + ks * 16) * 2u);
            mma16816(acc1[0], a0r, a1r, a2r, a3r, b0, b1);
            mma16816(acc1[1], a0r, a1r, a2r, a3r, b2, b3);
            if (cc < 4) {
                unsigned c0, c1, c2, c3;
                ldm_x4(c0, c1, c2, c3, b0base + (unsigned)(cc * KCH + ks * 16) * 2u);
                mma16816(acc0[0], a0r, a1r, a2r, a3r, c0, c1);
                mma16816(acc0[1], a0r, a1r, a2r, a3r, c2, c3);
            }
        }
    }
}

// ---------------- KAN mma: 4m x 2n warps (MI=2 NW=2), KCH=64, wait0 tail ----
template<int MI, int NW, int KCH>
__device__ __forceinline__ void mma_phase(
    const __nv_bfloat16* __restrict__ Ag, int lda, int arow0, int kbeg, int nch,
    const __nv_bfloat16* sW, int wp, __nv_bfloat16* sA, float cacc[MI][NW * 2][4])
{
    constexpr int AP  = KCH + 8;
    constexpr int OPR = KCH / 8;
    constexpr int NOPS = (MI * 64) * KCH / 8 / NTHR;
    int tid = threadIdx.x, lane = tid & 31, warp = tid >> 5;
    int wm = (warp & 3) * (MI * 16), wn = (warp >> 2) * (NW * 16);
    unsigned sWa = (unsigned)__cvta_generic_to_shared(sW);
    unsigned sAa = (unsigned)__cvta_generic_to_shared(sA);

    auto issue = [&](int cc) {
        const __nv_bfloat16* gb = Ag + (size_t)arow0 * lda + kbeg + cc * KCH;
        unsigned sb = sAa + (unsigned)(cc % 3) * SM_STRIDE;
#pragma unroll
        for (int o = 0; o < NOPS; o++) {
            int idx = o * NTHR + tid;
            int r = idx / OPR, c = (idx % OPR) * 8;
            unsigned sa = sb + (unsigned)(r * AP + c) * 2u;
            const void* ga = gb + (size_t)r * lda + c;
            asm volatile("cp.async.cg.shared.global [%0], [%1], 16;" :: "r"(sa), "l"(ga) : "memory");
        }
        asm volatile("cp.async.commit_group;" ::: "memory");
    };
    issue(0);
    if (nch > 1) issue(1);

    int a_r = (lane & 7) + ((lane >> 3) & 1) * 8;
    int a_k = ((lane >> 4) & 1) * 8;
    int b_r = (lane & 7) + ((lane >> 4) & 1) * 8;
    int b_k = ((lane >> 3) & 1) * 8;
    unsigned bbase[NW];
#pragma unroll
    for (int nw = 0; nw < NW; nw++)
        bbase[nw] = sWa + (unsigned)((wn + nw * 16 + b_r) * wp + b_k) * 2u;

    for (int cc = 0; cc < nch; cc++) {
        pipe_wait(cc == nch - 1);
        __syncthreads();
        if (cc + 2 < nch) issue(cc + 2);

        unsigned sb = sAa + (unsigned)(cc % 3) * SM_STRIDE;
        unsigned ab[MI];
#pragma unroll
        for (int mi = 0; mi < MI; mi++)
            ab[mi] = sb + (unsigned)((wm + mi * 16 + a_r) * AP + a_k) * 2u;
#pragma unroll
        for (int ks = 0; ks < KCH / 16; ks++) {
            unsigned a0[MI], a1[MI], a2[MI], a3[MI];
#pragma unroll
            for (int mi = 0; mi < MI; mi++)
                ldm_x4(a0[mi], a1[mi], a2[mi], a3[mi], ab[mi] + ks * 32);
#pragma unroll
            for (int nw = 0; nw < NW; nw++) {
                unsigned b0, b1, b2, b3;
                ldm_x4(b0, b1, b2, b3, bbase[nw] + (unsigned)(cc * KCH + ks * 16) * 2u);
#pragma unroll
                for (int mi = 0; mi < MI; mi++) {
                    mma16816(cacc[mi][nw * 2 + 0], a0[mi], a1[mi], a2[mi], a3[mi], b0, b1);
                    mma16816(cacc[mi][nw * 2 + 1], a0[mi], a1[mi], a2[mi], a3[mi], b2, b3);
                }
            }
        }
    }
}

// ---------------- init ----------------
__global__ void init_kernel(const float* __restrict__ wih,
                            const float* __restrict__ bih, const float* __restrict__ bhh,
                            const float* __restrict__ grid, int preset_flags)
{
    size_t stride = (size_t)gridDim.x * blockDim.x;
    size_t t0 = (size_t)blockIdx.x * blockDim.x + threadIdx.x;
    for (size_t i = t0; i < (size_t)G4H * Dd; i += stride)
        g_wihb[i] = __float2bfloat16(wih[i]);
    for (size_t i = t0; i < G4H; i += stride) {
        g_bg0[i] = bih[i] + bhh[i];
        g_bg1[i] = bih[G4H + i] + bhh[G4H + i];
    }
    for (size_t i = t0; i < (size_t)Bz * 1024; i += stride) g_hcat[i] = __float2bfloat16(0.f);
    for (size_t i = t0; i < 12; i += stride) g_kt[i] = grid[i];
    for (size_t i = t0; i < 30; i += stride) {
        int j = (int)i; int k, jj;
        if (j < 11)      { k = 1; jj = j; }
        else if (j < 21) { k = 2; jj = j - 11; }
        else             { k = 3; jj = j - 21; }
        g_invd[i] = 1.0f / (grid[jj + k] - grid[jj]);
    }
    for (size_t i = t0; i < Tt; i += stride) g_xwflag[i] = (unsigned)preset_flags;
    if (t0 < 16) g_gcnt[t0] = 0u;
    if (t0 < 8) g_pcnt[t0] = 0u;
    if (t0 == 0) { g_bar = 0u; g_mtnext = 0u; }
}

// ---------------- tf32 xw0 fallback (used only if few SMs) ----------------
__device__ __forceinline__ unsigned f2tf(float x) {
    unsigned u; asm("cvt.rna.tf32.f32 %0, %1;" : "=r"(u) : "f"(x)); return u;
}
__device__ __forceinline__ void mma8(float c[4], unsigned a0, unsigned a1, unsigned a2, unsigned a3,
                                     unsigned b0, unsigned b1) {
    asm volatile("mma.sync.aligned.m16n8k8.row.col.f32.tf32.tf32.f32 "
                 "{%0,%1,%2,%3},{%4,%5,%6,%7},{%8,%9},{%0,%1,%2,%3};"
                 : "+f"(c[0]), "+f"(c[1]), "+f"(c[2]), "+f"(c[3])
                 : "r"(a0), "r"(a1), "r"(a2), "r"(a3), "r"(b0), "r"(b1));
}
__global__ void __launch_bounds__(NTHR) xw0_mma(const float* __restrict__ x,
                                                const float* __restrict__ wih,
                                                const float* __restrict__ bih,
                                                const float* __restrict__ bhh)
{
    __shared__ __align__(16) float sA[128 * PITCH];
    __shared__ __align__(16) float sB[64 * PITCH];
    int nt = blockIdx.x, mt = blockIdx.y;
    int tid = threadIdx.x, lane = tid & 31, warp = tid >> 5;
    int wm = (warp & 3) * 32, wn = (warp >> 2) * 32;
    int qr = lane >> 2, qc = lane & 3;
    float cacc[2][4][4] = {};
    const float* A = x + (size_t)mt * Dd;
    const float* W = wih + (size_t)nt * 64 * Dd;
    float4 ra[4], rb[2];
    {
#pragma unroll
        for (int j = 0; j < 4; j++) { int idx = j * 256 + tid;
            ra[j] = *(const float4*)(A + (size_t)(idx >> 3) * ((size_t)Tt * Dd) + ((idx & 7) << 2)); }
#pragma unroll
        for (int j = 0; j < 2; j++) { int idx = j * 256 + tid;
            rb[j] = *(const float4*)(W + (size_t)(idx >> 3) * Dd + ((idx & 7) << 2)); }
    }
    for (int cc = 0; cc < Dd / 32; cc++) {
        __syncthreads();
#pragma unroll
        for (int j = 0; j < 4; j++) {
            int idx = j * 256 + tid; int row = idx >> 3; int c0 = (idx & 7) << 2;
            int base = row * PITCH + ((c0 >> 4) << 4) + ((c0 & 15) >> 2);
            sA[base + 0]  = __uint_as_float(f2tf(ra[j].x));
            sA[base + 4]  = __uint_as_float(f2tf(ra[j].y));
            sA[base + 8]  = __uint_as_float(f2tf(ra[j].z));
            sA[base + 12] = __uint_as_float(f2tf(ra[j].w));
        }
#pragma unroll
        for (int j = 0; j < 2; j++) {
            int idx = j * 256 + tid; int row = idx >> 3; int c0 = (idx & 7) << 2;
            int base = row * PITCH + ((c0 >> 4) << 4) + ((c0 & 15) >> 2);
            sB[base + 0]  = __uint_as_float(f2tf(rb[j].x));
            sB[base + 4]  = __uint_as_float(f2tf(rb[j].y));
            sB[base + 8]  = __uint_as_float(f2tf(rb[j].z));
            sB[base + 12] = __uint_as_float(f2tf(rb[j].w));
        }
        __syncthreads();
        if (cc + 1 < Dd / 32) {
            int kb = (cc + 1) * 32;
#pragma unroll
            for (int j = 0; j < 4; j++) { int idx = j * 256 + tid;
                ra[j] = *(const float4*)(A + (size_t)(idx >> 3) * ((size_t)Tt * Dd) + kb + ((idx & 7) << 2)); }
#pragma unroll
            for (int j = 0; j < 2; j++) { int idx = j * 256 + tid;
                rb[j] = *(const float4*)(W + (size_t)(idx >> 3) * Dd + kb + ((idx & 7) << 2)); }
        }
#pragma unroll
        for (int h = 0; h < 2; h++) {
            unsigned bf[4][4];
#pragma unroll
            for (int f = 0; f < 4; f++) {
                float4 v = *(const float4*)(sB + (wn + f * 8 + qr) * PITCH + h * 16 + qc * 4);
                bf[f][0] = __float_as_uint(v.x); bf[f][1] = __float_as_uint(v.y);
                bf[f][2] = __float_as_uint(v.z); bf[f][3] = __float_as_uint(v.w);
            }
#pragma unroll
            for (int mi = 0; mi < 2; mi++) {
                float4 lo = *(const float4*)(sA + (wm + mi * 16 + qr) * PITCH + h * 16 + qc * 4);
                float4 hi = *(const float4*)(sA + (wm + mi * 16 + 8 + qr) * PITCH + h * 16 + qc * 4);
#pragma unroll
                for (int f = 0; f < 4; f++) {
                    mma8(cacc[mi][f], __float_as_uint(lo.x), __float_as_uint(hi.x),
                         __float_as_uint(lo.y), __float_as_uint(hi.y), bf[f][0], bf[f][1]);
                    mma8(cacc[mi][f], __float_as_uint(lo.z), __float_as_uint(hi.z),
                         __float_as_uint(lo.w), __float_as_uint(hi.w), bf[f][2], bf[f][3]);
                }
            }
        }
    }
    size_t rowbase = (size_t)mt * 128;
#pragma unroll
    for (int mi = 0; mi < 2; mi++)
#pragma unroll
        for (int f = 0; f < 4; f++) {
            int r0 = wm + mi * 16 + qr;
            int cb = nt * 64 + wn + f * 8 + qc * 2;
            float b0 = __ldg(&bih[cb]) + __ldg(&bhh[cb]);
            float b1 = __ldg(&bih[cb + 1]) + __ldg(&bhh[cb + 1]);
            *(float2*)(g_xw0 + (rowbase + r0) * G4H + cb) =
                make_float2(cacc[mi][f][0] + b0, cacc[mi][f][1] + b1);
            *(float2*)(g_xw0 + (rowbase + r0 + 8) * G4H + cb) =
                make_float2(cacc[mi][f][2] + b0, cacc[mi][f][3] + b1);
        }
}

// ---------------- mega kernel: 128 persist blocks + producer blocks ----------------
__global__ void __launch_bounds__(NTHR, 1) persist_kernel(
    const float* __restrict__ x,
    const float* __restrict__ wih, const float* __restrict__ whh,
    const float* __restrict__ kbase, const float* __restrict__ kspl,
    const float* __restrict__ kscl, const float* __restrict__ fc_w,
    const float* __restrict__ fc_b, float* __restrict__ out)
{
    extern __shared__ __align__(16) char smem_raw[];
    int bid = blockIdx.x, tid = threadIdx.x;
    int lane = tid & 31, warp = tid >> 5;
    int qr = lane >> 2, qc = lane & 3;

    // =================== xw0 producer blocks (bid >= 128) ===================
    if (bid >= NBLK) {
        __nv_bfloat16* sA = (__nv_bfloat16*)(smem_raw + PX_A);
        unsigned sAa = (unsigned)__cvta_generic_to_shared(smem_raw + PX_A);
        unsigned sWa = (unsigned)__cvta_generic_to_shared(smem_raw + PX_W);
        unsigned* s_mt = (unsigned*)(smem_raw + PX_MT);
        int a_r = (lane & 7) + ((lane >> 3) & 1) * 8;
        int a_k = ((lane >> 4) & 1) * 8;
        int b_r = (lane & 7) + ((lane >> 4) & 1) * 8;
        int b_k = ((lane >> 3) & 1) * 8;
        int wm = (warp & 3) * 32, wn = (warp >> 2) * 16;

        auto stageW = [&](int sub, int buf) {
            const __nv_bfloat16* gb = g_wihb + (size_t)sub * 32 * 512;
            unsigned dstb = sWa + (unsigned)buf * 33280u;
#pragma unroll
            for (int o = 0; o < 8; o++) {
                int idx = o * NTHR + tid;
                int r = idx >> 6, c = (idx & 63) * 8;
                asm volatile("cp.async.cg.shared.global [%0], [%1], 16;"
                             :: "r"(dstb + (unsigned)(r * 520 + c) * 2u),
                                "l"(gb + r * 512 + c) : "memory");
            }
            asm volatile("cp.async.commit_group;" ::: "memory");
        };

        for (;;) {
            __syncthreads();
            if (tid == 0) *s_mt = atomicAdd(&g_mtnext, 1u);
            __syncthreads();
            unsigned mt = *s_mt;
            if (mt >= Tt) break;
            for (int i = tid; i < 128 * 128; i += NTHR) {
                int r = i >> 7, c4 = (i & 127) << 2;
                float4 v = *(const float4*)(x + ((size_t)r * Tt + mt) * Dd + c4);
                __nv_bfloat162 p0 = __float22bfloat162_rn(make_float2(v.x, v.y));
                __nv_bfloat162 p1 = __float22bfloat162_rn(make_float2(v.z, v.w));
                *(__nv_bfloat162*)&sA[r * 520 + c4] = p0;
                *(__nv_bfloat162*)&sA[r * 520 + c4 + 2] = p1;
            }
            __syncthreads();
            stageW(0, 0);
            for (int sub = 0; sub < 64; sub++) {
                if (sub + 1 < 64) stageW(sub + 1, (sub + 1) & 1);
                if (sub + 1 < 64) asm volatile("cp.async.wait_group 1;" ::: "memory");
                else              asm volatile("cp.async.wait_group 0;" ::: "memory");
                __syncthreads();
                unsigned bb = sWa + (unsigned)((sub & 1) * 33280) +
                              (unsigned)((wn + b_r) * 520 + b_k) * 2u;
                float cacc[2][2][4] = {};
#pragma unroll
                for (int ks = 0; ks < 32; ks++) {
                    unsigned b0, b1, b2, b3;
                    ldm_x4(b0, b1, b2, b3, bb + ks * 32);
#pragma unroll
                    for (int mi = 0; mi < 2; mi++) {
                        unsigned a0, a1, a2, a3;
                        ldm_x4(a0, a1, a2, a3,
                               sAa + (unsigned)((wm + mi * 16 + a_r) * 520 + ks * 16 + a_k) * 2u);
                        mma16816(cacc[mi][0], a0, a1, a2, a3, b0, b1);
                        mma16816(cacc[mi][1], a0, a1, a2, a3, b2, b3);
                    }
                }
                int n0 = sub * 32;
#pragma unroll
                for (int mi = 0; mi < 2; mi++)
#pragma unroll
                    for (int nf = 0; nf < 2; nf++) {
                        int row = wm + mi * 16 + qr;
                        int col = n0 + wn + nf * 8 + qc * 2;
                        float2 bv = *(const float2*)&g_bg0[col];
                        *(float2*)&g_xw0[((size_t)mt * Bz + row) * G4H + col] =
                            make_float2(cacc[mi][nf][0] + bv.x, cacc[mi][nf][1] + bv.y);
                        *(float2*)&g_xw0[((size_t)mt * Bz + row + 8) * G4H + col] =
                            make_float2(cacc[mi][nf][2] + bv.x, cacc[mi][nf][3] + bv.y);
                    }
                __syncthreads();
            }
            if (tid == 0)
                asm volatile("st.release.gpu.global.u32 [%0], %1;"
                             :: "l"(&g_xwflag[mt]), "r"(1u) : "memory");
        }
        return;
    }

    // =================== persist blocks (bid < 128) ===================
    __nv_bfloat16* sWg0 = (__nv_bfloat16*)(smem_raw + SM_WG0);
    __nv_bfloat16* sWg1 = (__nv_bfloat16*)(smem_raw + SM_WG1);
    __nv_bfloat16* sWk  = (__nv_bfloat16*)(smem_raw + SM_WK);
    __nv_bfloat16* sAst = (__nv_bfloat16*)(smem_raw + SM_AST);

    int g_nt = bid >> 1, g_mh = bid & 1;
    int lyr  = bid >> 6;
    int kb2  = bid & 63;
    int k_nt = kb2 >> 3, k_ks = kb2 & 7;

    for (int i = tid; i < 32 * 512; i += NTHR) {
        int r = i >> 9, c = i & 511;
        int ng = (r >> 3) * 512 + g_nt * 8 + (r & 7);
        sWg0[r * WP_G0 + c] = __float2bfloat16(whh[(size_t)ng * 512 + c]);
    }
    for (int i = tid; i < 32 * 1024; i += NTHR) {
        int r = i >> 10, c = i & 1023;
        int ng = (r >> 3) * 512 + g_nt * 8 + (r & 7);
        float v = (c < 512) ? wih[(size_t)G4H * Dd + (size_t)ng * 512 + c]
                            : whh[(size_t)G4H * Hh + (size_t)ng * 512 + (c - 512)];
        sWg1[r * WP_G1 + c] = __float2bfloat16(v);
    }
    for (int i = tid; i < 64 * 576; i += NTHR) {
        int r = i / 576, kk0 = i % 576;
        int row = lyr * 512 + k_nt * 64 + r;
        float v;
        if (kk0 < 64) {
            int ii2 = k_ks * 64 + kk0;
            v = kbase[(size_t)row * 512 + ii2];
        } else {
            int q = kk0 - 64;
            int ii2 = k_ks * 64 + (q >> 3);
            v = kspl[((size_t)row * 512 + ii2) * 8 + (q & 7)] * kscl[(size_t)row * 512 + ii2];
        }
        sWk[r * WP_K + kk0] = __float2bfloat16(v);
    }
    __syncthreads();

    float kt[12], invd[30];
#pragma unroll
    for (int q = 0; q < 12; q++) kt[q] = g_kt[q];
#pragma unroll
    for (int q = 0; q < 30; q++) invd[q] = g_invd[q];

    int wng = (warp >> 2) * 16;
    int eb0 = g_mh * 64 + (warp & 3) * 16 + qr;
    int encls[2]; bool isg[2];
#pragma unroll
    for (int nf = 0; nf < 2; nf++) {
        int cls = (wng + nf * 8) >> 3;
        encls[nf] = cls * 512 + g_nt * 8 + qc * 2;
        isg[nf] = (cls == 2);
    }
    float2 pb[2];
#pragma unroll
    for (int nf = 0; nf < 2; nf++) pb[nf] = *(const float2*)&g_bg1[encls[nf]];

    int upd_row0 = k_ks * 16 + (tid >> 5);
    int upd_col  = k_nt * 64 + ((tid & 31) << 1);
    float2 creg2[2] = {make_float2(0.f, 0.f), make_float2(0.f, 0.f)};
    int gidx = lyr * 8 + k_nt;
    int my_pcnt = g_nt >> 3;

    auto gate_epilogue = [&](int l, const float2 (&pre)[2][2], const float (&cc4)[2][4]) {
#pragma unroll
        for (int nf = 0; nf < 2; nf++)
#pragma unroll
            for (int r = 0; r < 2; r++) {
                int b = eb0 + r * 8;
                float v0 = cc4[nf][r * 2 + 0] + pre[nf][r].x;
                float v1 = cc4[nf][r * 2 + 1] + pre[nf][r].y;
                if (!isg[nf]) {
                    *(float2*)&g_sig[l][b * G4H + encls[nf]] = make_float2(
                        1.f / (1.f + __expf(-v0)), 1.f / (1.f + __expf(-v1)));
                } else {
#pragma unroll
                    for (int e = 0; e < 2; e++) {
                        float v = e ? v1 : v0;
                        int ii = encls[nf] + e - 1024;
                        int ch = ii >> 6, w = ii & 63;
                        size_t fbase = (size_t)b * FEAT + ch * 576;
                        g_feat[l][fbase + w] = __float2bfloat16(v / (1.f + __expf(-v)));
                        float bas[11];
#pragma unroll
                        for (int q = 0; q < 11; q++)
                            bas[q] = (v >= kt[q] && v < kt[q + 1]) ? 1.f : 0.f;
#pragma unroll
                        for (int k = 1; k <= 3; k++) {
                            int off = (k == 1) ? 0 : ((k == 2) ? 11 : 21);
#pragma unroll
                            for (int q = 0; q + k < 11; q++) {
                                float lf = (v - kt[q]) * invd[off + q];
                                float rf = (kt[q + k + 1] - v) * invd[off + q + 1];
                                bas[q] = lf * bas[q] + rf * bas[q + 1];
                            }
                        }
                        __nv_bfloat162 p0 = __float22bfloat162_rn(make_float2(bas[0], bas[1]));
                        __nv_bfloat162 p1 = __float22bfloat162_rn(make_float2(bas[2], bas[3]));
                        __nv_bfloat162 p2 = __float22bfloat162_rn(make_float2(bas[4], bas[5]));
                        __nv_bfloat162 p3 = __float22bfloat162_rn(make_float2(bas[6], bas[7]));
                        uint4 u;
                        u.x = *(unsigned*)&p0; u.y = *(unsigned*)&p1;
                        u.z = *(unsigned*)&p2; u.w = *(unsigned*)&p3;
                        *(uint4*)&g_feat[l][fbase + 64 + w * 8] = u;
                    }
                }
            }
    };

    unsigned gs = 0, ainst = 0;

    auto produce = [&]() {
        __syncthreads();
        if (tid == 0)
            asm volatile("red.release.gpu.global.add.u32 [%0], 1;"
                         :: "l"(&g_pcnt[my_pcnt]) : "memory");
        ainst++;
    };

    auto kan_step = [&](void) {
        if (tid == 0) {
            unsigned tgt = 16u * ainst, v;
            do {
                asm volatile("ld.acquire.gpu.global.u32 %0, [%1];"
                             : "=r"(v) : "l"(&g_pcnt[k_ks]) : "memory");
            } while (v < tgt);
            do {
                asm volatile("ld.acquire.gpu.global.u32 %0, [%1];"
                             : "=r"(v) : "l"(&g_pcnt[k_nt]) : "memory");
            } while (v < tgt);
        }
        __syncthreads();

        float cacc[2][4][4] = {};
        mma_phase<2, 2, 64>(g_feat[lyr], FEAT, 0, k_ks * 576, 9, sWk, WP_K, sAst, cacc);
        int wm = (warp & 3) * 32, wn = (warp >> 2) * 32;
#pragma unroll
        for (int mi = 0; mi < 2; mi++)
#pragma unroll
            for (int f = 0; f < 4; f++) {
                int r0 = wm + mi * 16 + qr;
                int cb = k_nt * 64 + wn + (f >> 1) * 16 + (f & 1) * 8 + qc * 2;
                *(float2*)&g_part[lyr][k_ks][r0 * Hh + cb] =
                    make_float2(cacc[mi][f][0], cacc[mi][f][1]);
                *(float2*)&g_part[lyr][k_ks][(r0 + 8) * Hh + cb] =
                    make_float2(cacc[mi][f][2], cacc[mi][f][3]);
            }

        // sigmoid operands: latency overlaps the group-sync spin
        float2 ig[2], fg[2], og[2];
#pragma unroll
        for (int r = 0; r < 2; r++) {
            int b = upd_row0 + r * 8, o = upd_col;
            ig[r] = __ldcg((const float2*)&g_sig[lyr][b * G4H + o]);
            fg[r] = __ldcg((const float2*)&g_sig[lyr][b * G4H + 512 + o]);
            og[r] = __ldcg((const float2*)&g_sig[lyr][b * G4H + 1536 + o]);
        }

        ++gs;
        __syncthreads();
        if (tid == 0) {
            asm volatile("red.release.gpu.global.add.u32 [%0], 1;"
                         :: "l"(&g_gcnt[gidx]) : "memory");
            unsigned v, tgt = gs * 8;
            do {
                asm volatile("ld.acquire.gpu.global.u32 %0, [%1];"
                             : "=r"(v) : "l"(&g_gcnt[gidx]) : "memory");
            } while (v < tgt);
        }
        __syncthreads();

#pragma unroll
        for (int r = 0; r < 2; r++) {
            int b = upd_row0 + r * 8, o = upd_col;
            float2 v = make_float2(0.f, 0.f);
#pragma unroll
            for (int s = 0; s < 8; s++) {
                float2 p = __ldcg((const float2*)&g_part[lyr][s][b * Hh + o]);
                v.x += p.x; v.y += p.y;
            }
            float c0 = fg[r].x * creg2[r].x + ig[r].x * v.x;
            float c1 = fg[r].y * creg2[r].y + ig[r].y * v.y;
            creg2[r] = make_float2(c0, c1);
            __nv_bfloat162 h2 = __float22bfloat162_rn(
                make_float2(og[r].x * tanhf(c0), og[r].y * tanhf(c1)));
            *(unsigned*)&g_hcat[b * 1024 + lyr * 512 + o] = *(unsigned*)&h2;
        }
    };

    auto ld_pre0 = [&](int t, float2 (&pre)[2][2]) {
        unsigned fv;
        do {
            asm volatile("ld.acquire.gpu.global.u32 %0, [%1];"
                         : "=r"(fv) : "l"(&g_xwflag[t]) : "memory");
        } while (!fv);
#pragma unroll
        for (int nf = 0; nf < 2; nf++)
#pragma unroll
            for (int r = 0; r < 2; r++)
                pre[nf][r] = __ldcs((const float2*)&g_xw0[
                    ((size_t)t * Bz + eb0 + r * 8) * G4H + encls[nf]]);
    };

    unsigned nb = 0;

    // ---- prologue: L0 step 0 (h = 0 -> gates = xw0[0], no mma) ----
    {
        float2 pre[2][2];
        ld_pre0(0, pre);
        float zero4[2][4] = {};
        gate_epilogue(0, pre, zero4);
    }
    produce();
    if (lyr == 0) kan_step();
    gsync(++nb * NBLK);

    // ---- main loop ----
    for (int i = 0; i < Tt; i++) {
        bool doL0 = (i < Tt - 1);
        {
            float2 pre0[2][2];
            if (doL0) ld_pre0(i + 1, pre0);
            float a0[2][4] = {}, a1[2][4] = {};
            mma_gates(g_hcat, g_mh * 64, sWg0, sWg1, sAst, a0, a1);
            if (doL0) gate_epilogue(0, pre0, a0);
            float2 pre1[2][2];
#pragma unroll
            for (int nf = 0; nf < 2; nf++) { pre1[nf][0] = pb[nf]; pre1[nf][1] = pb[nf]; }
            gate_epilogue(1, pre1, a1);
        }
        produce();

        if (lyr == 1 || doL0) kan_step();
        gsync(++nb * NBLK);
    }

    // ---- final FC: out = h1 @ fc_w^T + fc_b ----
    {
        int idx = bid * NTHR + tid;
        int o = idx >> 7, b = idx & 127;
        float s = fc_b[o];
        const __nv_bfloat16* hp = &g_hcat[b * 1024 + 512];
        const float* wp = &fc_w[(size_t)o * Hh];
#pragma unroll 8
        for (int k = 0; k < Hh; k++) s += __bfloat162float(__ldcg(&hp[k])) * wp[k];
        out[b * Oo + o] = s;
    }
}

// ---------------- launch ----------------
extern "C" void kernel_launch(void* const* d_in, const int* in_sizes, int n_in,
                              void* d_out, int out_size)
{
    const float* x     = (const float*)d_in[0];
    const float* wih   = (const float*)d_in[1];
    const float* whh   = (const float*)d_in[2];
    const float* bih   = (const float*)d_in[3];
    const float* bhh   = (const float*)d_in[4];
    const float* kbase = (const float*)d_in[5];
    const float* kspl  = (const float*)d_in[6];
    const float* kscl  = (const float*)d_in[7];
    const float* grid  = (const float*)d_in[8];
    const float* fc_w  = (const float*)d_in[9];
    const float* fc_b  = (const float*)d_in[10];
    float* out = (float*)d_out;

    cudaFuncSetAttribute(persist_kernel, cudaFuncAttributeMaxDynamicSharedMemorySize, SMEM_TOTAL);

    int dev = 0, smCount = 0;
    cudaGetDevice(&dev);
    cudaDeviceGetAttribute(&smCount, cudaDevAttrMultiProcessorCount, dev);
    int nprod = smCount - NBLK;
    bool overlap = (nprod >= 16);
    if (!overlap) nprod = 0;

    init_kernel<<<512, NTHR>>>(wih, bih, bhh, grid, overlap ? 0 : 1);
    if (!overlap) {
        dim3 gg(G4H / 64, Tt);
        xw0_mma<<<gg, NTHR>>>(x, wih, bih, bhh);
    }
    persist_kernel<<<NBLK + nprod, NTHR, SMEM_TOTAL>>>(
        x, wih, whh, kbase, kspl, kscl, fc_w, fc_b, out);
}